// round 1
// baseline (speedup 1.0000x reference)
#include <cuda_runtime.h>
#include <cstdint>

#define D_MODEL 256
#define N_NODES 20
#define N_HEADS 8
#define BMAX    8192
#define MMAX    (BMAX * N_NODES)   // 163840 rows

// ---------------- scratch (device globals: allocation-free) ----------------
__device__ float g_w3[768 * 768];          // repacked conv weights [j=t*256+i][o (q|k|v)]
__device__ float g_wot[256 * 256];         // wo transposed [i][o]
__device__ float g_conv[(size_t)MMAX * 768]; // conv outputs (pre-LN)
__device__ float g_qkv [(size_t)MMAX * 768]; // q|k|v after LN+residual
__device__ float g_attn[(size_t)MMAX * 256]; // attention output (pre-proj)

// ---------------- packed f32x2 helpers (sm_103a) ----------------
__device__ __forceinline__ unsigned long long pk2(float x, float y) {
    unsigned long long r;
    asm("mov.b64 %0, {%1, %2};" : "=l"(r) : "f"(x), "f"(y));
    return r;
}
__device__ __forceinline__ void fma2(unsigned long long& d,
                                     unsigned long long a,
                                     unsigned long long b) {
    asm("fma.rn.f32x2 %0, %1, %2, %0;" : "+l"(d) : "l"(a), "l"(b));
}
__device__ __forceinline__ void upk2(unsigned long long v, float& x, float& y) {
    asm("mov.b64 {%0, %1}, %2;" : "=f"(x), "=f"(y) : "l"(v));
}

// ---------------- kernel 0: weight repack ----------------
// g_w3[j*768+o]: j = t*256+i, o in [0,768): 0..255 wq, 256..511 wk, 512..767 wv
// w layout (O,I,K) row-major: w[o][i][t] = w[(o*256+i)*3+t]
__global__ void prep_kernel(const float* __restrict__ wq,
                            const float* __restrict__ wk,
                            const float* __restrict__ wv,
                            const float* __restrict__ wo) {
    int idx = blockIdx.x * blockDim.x + threadIdx.x;
    if (idx < 768 * 768) {
        int j = idx / 768, o = idx % 768;
        int t = j >> 8, d = j & 255;
        const float* w = (o < 256) ? wq : (o < 512) ? wk : wv;
        int oc = o & 255;
        g_w3[idx] = w[(oc * 256 + d) * 3 + t];
    }
    if (idx < 256 * 256) {
        int j = idx >> 8, o = idx & 255;
        g_wot[idx] = wo[o * 256 + j];
    }
}

// ---------------- kernel 1: conv as GEMM ----------------
// C[M,768] = A[M,768] @ g_w3[768,768], A gathered from x with N-halo.
// Tiles: BM=128, BN=128, BK=16; 256 threads; 8x8 per thread via f32x2 pairs.
__global__ __launch_bounds__(256, 2)
void conv_gemm_kernel(const float* __restrict__ x, int M) {
    const int BK = 16;
    __shared__ __align__(16) float As[16][128];   // [k][m] (transposed)
    __shared__ __align__(16) float Bs[16][128];   // [k][o]

    int tid = threadIdx.x;
    int tx = tid & 15, ty = tid >> 4;
    int row0 = blockIdx.y * 128;
    int col0 = blockIdx.x * 128;

    // per-thread load mapping (2 passes of float4 each for A and B)
    int mA[2], kcA[2], bA[2], nA[2], oB[2], kB[2];
    bool mOk[2];
#pragma unroll
    for (int p = 0; p < 2; p++) {
        int f = tid + p * 256;
        mA[p] = f >> 2; kcA[p] = (f & 3) * 4;
        int mg = row0 + mA[p];
        mOk[p] = (mg < M);
        int mgc = mOk[p] ? mg : 0;
        bA[p] = mgc / N_NODES; nA[p] = mgc % N_NODES;
        oB[p] = (f & 31) * 4; kB[p] = f >> 5;
    }

    unsigned long long acc[8][4];
#pragma unroll
    for (int i = 0; i < 8; i++)
#pragma unroll
        for (int j = 0; j < 4; j++) acc[i][j] = 0ULL;

    float4 aR[2], bR[2];

    auto loadG = [&](int kt) {
        int ktg = kt * BK;
        int t = ktg >> 8;        // tap index (constant within a 16-wide k-tile)
        int dbase = ktg & 255;
#pragma unroll
        for (int p = 0; p < 2; p++) {
            int srcN = nA[p] + t - 1;
            if (mOk[p] && srcN >= 0 && srcN < N_NODES) {
                aR[p] = *reinterpret_cast<const float4*>(
                    &x[(size_t)(bA[p] * N_NODES + srcN) * 256 + dbase + kcA[p]]);
            } else {
                aR[p] = make_float4(0.f, 0.f, 0.f, 0.f);
            }
            bR[p] = *reinterpret_cast<const float4*>(
                &g_w3[(size_t)(ktg + kB[p]) * 768 + col0 + oB[p]]);
        }
    };
    auto storeS = [&]() {
#pragma unroll
        for (int p = 0; p < 2; p++) {
            As[kcA[p] + 0][mA[p]] = aR[p].x;
            As[kcA[p] + 1][mA[p]] = aR[p].y;
            As[kcA[p] + 2][mA[p]] = aR[p].z;
            As[kcA[p] + 3][mA[p]] = aR[p].w;
            *reinterpret_cast<float4*>(&Bs[kB[p]][oB[p]]) = bR[p];
        }
    };
    auto compute = [&]() {
#pragma unroll
        for (int kk = 0; kk < BK; kk++) {
            float4 a0 = *reinterpret_cast<const float4*>(&As[kk][ty * 4]);
            float4 a1 = *reinterpret_cast<const float4*>(&As[kk][ty * 4 + 64]);
            ulonglong2 b0 = *reinterpret_cast<const ulonglong2*>(&Bs[kk][tx * 4]);
            ulonglong2 b1 = *reinterpret_cast<const ulonglong2*>(&Bs[kk][tx * 4 + 64]);
            float av[8] = {a0.x, a0.y, a0.z, a0.w, a1.x, a1.y, a1.z, a1.w};
            unsigned long long bp[4] = {b0.x, b0.y, b1.x, b1.y};
#pragma unroll
            for (int i = 0; i < 8; i++) {
                unsigned long long aa = pk2(av[i], av[i]);
#pragma unroll
                for (int j = 0; j < 4; j++) fma2(acc[i][j], aa, bp[j]);
            }
        }
    };

    const int KT = 48;  // 768 / 16
    loadG(0); storeS(); __syncthreads();
#pragma unroll 1
    for (int kt = 0; kt < KT; kt++) {
        if (kt + 1 < KT) loadG(kt + 1);
        compute();
        __syncthreads();
        if (kt + 1 < KT) { storeS(); __syncthreads(); }
    }

#pragma unroll
    for (int i = 0; i < 8; i++) {
        int r = row0 + ty * 4 + ((i < 4) ? i : 60 + i);
        if (r >= M) continue;
#pragma unroll
        for (int j = 0; j < 4; j++) {
            int c = col0 + tx * 4 + ((j < 2) ? 2 * j : 60 + 2 * j);
            float lo, hi; upk2(acc[i][j], lo, hi);
            *reinterpret_cast<float2*>(&g_conv[(size_t)r * 768 + c]) =
                make_float2(lo, hi);
        }
    }
}

// ---------------- kernel 2: LayerNorm + residual ----------------
__global__ __launch_bounds__(256)
void ln_kernel(const float* __restrict__ x,
               const float* __restrict__ gq, const float* __restrict__ bq,
               const float* __restrict__ gk, const float* __restrict__ bk,
               const float* __restrict__ gv, const float* __restrict__ bv) {
    int m = blockIdx.x;
    int tid = threadIdx.x;
    int lane = tid & 31, wid = tid >> 5;
    __shared__ float rs[8], rs2[8];
    float xv = x[(size_t)m * 256 + tid];
#pragma unroll
    for (int c = 0; c < 3; c++) {
        float v = g_conv[(size_t)m * 768 + c * 256 + tid];
        float s = v, s2 = v * v;
#pragma unroll
        for (int off = 16; off; off >>= 1) {
            s  += __shfl_xor_sync(0xffffffffu, s,  off);
            s2 += __shfl_xor_sync(0xffffffffu, s2, off);
        }
        if (lane == 0) { rs[wid] = s; rs2[wid] = s2; }
        __syncthreads();
        if (tid == 0) {
            float a = 0.f, a2 = 0.f;
            for (int i = 0; i < 8; i++) { a += rs[i]; a2 += rs2[i]; }
            rs[0] = a; rs2[0] = a2;
        }
        __syncthreads();
        float mean = rs[0] * (1.0f / 256.0f);
        float var  = rs2[0] * (1.0f / 256.0f) - mean * mean;
        float g  = (c == 0) ? gq[tid] : (c == 1) ? gk[tid] : gv[tid];
        float bb = (c == 0) ? bq[tid] : (c == 1) ? bk[tid] : bv[tid];
        float o = xv + (v - mean) * rsqrtf(var + 1e-5f) * g + bb;
        g_qkv[(size_t)m * 768 + c * 256 + tid] = o;
        __syncthreads();
    }
}

// ---------------- kernel 3: attention (warp per (b, head)) ----------------
__global__ __launch_bounds__(128)
void attn_kernel(const float* __restrict__ rel,
                 const float* __restrict__ gbias,
                 const float* __restrict__ alphap) {
    __shared__ float q_s[4][20][33];
    __shared__ float k_s[4][20][33];
    __shared__ float v_s[4][20][33];
    __shared__ float p_s[4][20][20];
    int lane = threadIdx.x & 31;
    int wid  = threadIdx.x >> 5;
    int h = blockIdx.y * 4 + wid;
    int b = blockIdx.x;
    float alpha = alphap[0];

    for (int idx = lane; idx < 20 * 32; idx += 32) {
        int n = idx >> 5, d = idx & 31;
        size_t base = (size_t)(b * 20 + n) * 768 + h * 32 + d;
        q_s[wid][n][d] = g_qkv[base];
        k_s[wid][n][d] = g_qkv[base + 256];
        v_s[wid][n][d] = g_qkv[base + 512];
    }
    __syncwarp();

    for (int idx = lane; idx < 400; idx += 32) {
        int n = idx / 20, m2 = idx % 20;
        float acc = 0.f;
#pragma unroll
        for (int i = 0; i < 32; i++) acc += q_s[wid][n][i] * k_s[wid][m2][i];
        acc *= 0.17677669529663689f;              // 1/sqrt(32)
        acc += rel[(n - m2 + 19) * 8 + h];
        acc += gbias[(h * 20 + n) * 20 + m2] * alpha;
        p_s[wid][n][m2] = acc;
    }
    __syncwarp();

    if (lane < 20) {
        int n = lane;
        float mx = -1e30f;
        for (int m2 = 0; m2 < 20; m2++) mx = fmaxf(mx, p_s[wid][n][m2]);
        float s = 0.f;
        for (int m2 = 0; m2 < 20; m2++) {
            float e = __expf(p_s[wid][n][m2] - mx);
            p_s[wid][n][m2] = e; s += e;
        }
        float inv = 1.f / s;
        for (int m2 = 0; m2 < 20; m2++) p_s[wid][n][m2] *= inv;
    }
    __syncwarp();

    int d = lane;
    for (int n = 0; n < 20; n++) {
        float acc = 0.f;
#pragma unroll
        for (int m2 = 0; m2 < 20; m2++) acc += p_s[wid][n][m2] * v_s[wid][m2][d];
        g_attn[(size_t)(b * 20 + n) * 256 + h * 32 + d] = acc;
    }
}

// ---------------- kernel 4: output projection GEMM + bias ----------------
__global__ __launch_bounds__(256, 2)
void proj_gemm_kernel(const float* __restrict__ bo, float* __restrict__ out, int M) {
    const int BK = 16;
    __shared__ __align__(16) float As[16][128];
    __shared__ __align__(16) float Bs[16][128];

    int tid = threadIdx.x;
    int tx = tid & 15, ty = tid >> 4;
    int row0 = blockIdx.y * 128;
    int col0 = blockIdx.x * 128;

    int mA[2], kcA[2], oB[2], kB[2];
    bool mOk[2];
#pragma unroll
    for (int p = 0; p < 2; p++) {
        int f = tid + p * 256;
        mA[p] = f >> 2; kcA[p] = (f & 3) * 4;
        mOk[p] = (row0 + mA[p] < M);
        oB[p] = (f & 31) * 4; kB[p] = f >> 5;
    }

    unsigned long long acc[8][4];
#pragma unroll
    for (int i = 0; i < 8; i++)
#pragma unroll
        for (int j = 0; j < 4; j++) acc[i][j] = 0ULL;

    float4 aR[2], bR[2];
    auto loadG = [&](int kt) {
        int ktg = kt * BK;
#pragma unroll
        for (int p = 0; p < 2; p++) {
            if (mOk[p]) {
                aR[p] = *reinterpret_cast<const float4*>(
                    &g_attn[(size_t)(row0 + mA[p]) * 256 + ktg + kcA[p]]);
            } else {
                aR[p] = make_float4(0.f, 0.f, 0.f, 0.f);
            }
            bR[p] = *reinterpret_cast<const float4*>(
                &g_wot[(size_t)(ktg + kB[p]) * 256 + col0 + oB[p]]);
        }
    };
    auto storeS = [&]() {
#pragma unroll
        for (int p = 0; p < 2; p++) {
            As[kcA[p] + 0][mA[p]] = aR[p].x;
            As[kcA[p] + 1][mA[p]] = aR[p].y;
            As[kcA[p] + 2][mA[p]] = aR[p].z;
            As[kcA[p] + 3][mA[p]] = aR[p].w;
            *reinterpret_cast<float4*>(&Bs[kB[p]][oB[p]]) = bR[p];
        }
    };
    auto compute = [&]() {
#pragma unroll
        for (int kk = 0; kk < BK; kk++) {
            float4 a0 = *reinterpret_cast<const float4*>(&As[kk][ty * 4]);
            float4 a1 = *reinterpret_cast<const float4*>(&As[kk][ty * 4 + 64]);
            ulonglong2 b0 = *reinterpret_cast<const ulonglong2*>(&Bs[kk][tx * 4]);
            ulonglong2 b1 = *reinterpret_cast<const ulonglong2*>(&Bs[kk][tx * 4 + 64]);
            float av[8] = {a0.x, a0.y, a0.z, a0.w, a1.x, a1.y, a1.z, a1.w};
            unsigned long long bp[4] = {b0.x, b0.y, b1.x, b1.y};
#pragma unroll
            for (int i = 0; i < 8; i++) {
                unsigned long long aa = pk2(av[i], av[i]);
#pragma unroll
                for (int j = 0; j < 4; j++) fma2(acc[i][j], aa, bp[j]);
            }
        }
    };

    const int KT = 16;  // 256 / 16
    loadG(0); storeS(); __syncthreads();
#pragma unroll 1
    for (int kt = 0; kt < KT; kt++) {
        if (kt + 1 < KT) loadG(kt + 1);
        compute();
        __syncthreads();
        if (kt + 1 < KT) { storeS(); __syncthreads(); }
    }

#pragma unroll
    for (int i = 0; i < 8; i++) {
        int r = row0 + ty * 4 + ((i < 4) ? i : 60 + i);
        if (r >= M) continue;
#pragma unroll
        for (int j = 0; j < 4; j++) {
            int c = col0 + tx * 4 + ((j < 2) ? 2 * j : 60 + 2 * j);
            float lo, hi; upk2(acc[i][j], lo, hi);
            *reinterpret_cast<float2*>(&out[(size_t)r * 256 + c]) =
                make_float2(lo + bo[c], hi + bo[c + 1]);
        }
    }
}

// ---------------- launch ----------------
extern "C" void kernel_launch(void* const* d_in, const int* in_sizes, int n_in,
                              void* d_out, int out_size) {
    const float* x     = (const float*)d_in[0];
    const float* wq    = (const float*)d_in[1];
    const float* wk    = (const float*)d_in[2];
    const float* wv    = (const float*)d_in[3];
    const float* gq    = (const float*)d_in[4];
    const float* bq    = (const float*)d_in[5];
    const float* gk    = (const float*)d_in[6];
    const float* bk    = (const float*)d_in[7];
    const float* gv    = (const float*)d_in[8];
    const float* bv    = (const float*)d_in[9];
    const float* rel   = (const float*)d_in[10];
    const float* gbias = (const float*)d_in[11];
    const float* alpha = (const float*)d_in[12];
    const float* wo    = (const float*)d_in[13];
    const float* bo    = (const float*)d_in[14];
    float* out = (float*)d_out;

    int B = in_sizes[0] / (N_NODES * D_MODEL);
    int M = B * N_NODES;

    prep_kernel<<<(768 * 768 + 255) / 256, 256>>>(wq, wk, wv, wo);

    dim3 g1(6, (M + 127) / 128);
    conv_gemm_kernel<<<g1, 256>>>(x, M);

    ln_kernel<<<M, 256>>>(x, gq, bq, gk, bk, gv, bv);

    dim3 g3(B, 2);
    attn_kernel<<<g3, 128>>>(rel, gbias, alpha);

    dim3 g4(2, (M + 127) / 128);
    proj_gemm_kernel<<<g4, 256>>>(bo, out, M);
}

// round 3
// speedup vs baseline: 1.6243x; 1.6243x over previous
#include <cuda_runtime.h>
#include <cuda_bf16.h>
#include <cstdint>

#define D_MODEL 256
#define N_NODES 20
#define N_HEADS 8
#define BMAX    8192
#define MMAX    (BMAX * N_NODES)   // 163840 rows

// ---------------- scratch (device globals: allocation-free) ----------------
__device__ __nv_bfloat16 g_xhi[(size_t)MMAX * 256];
__device__ __nv_bfloat16 g_xlo[(size_t)MMAX * 256];
__device__ __nv_bfloat16 g_bhi[768 * 768];     // conv weights [o][j=t*256+i]
__device__ __nv_bfloat16 g_blo[768 * 768];
__device__ __nv_bfloat16 g_wohi[256 * 256];    // wo [o][i]
__device__ __nv_bfloat16 g_wolo[256 * 256];
__device__ float g_conv[(size_t)MMAX * 768];   // conv outputs (pre-LN)
__device__ float g_qkv [(size_t)MMAX * 768];   // q|k|v after LN+residual
__device__ __nv_bfloat16 g_ahi[(size_t)MMAX * 256];  // attn out hi
__device__ __nv_bfloat16 g_alo[(size_t)MMAX * 256];  // attn out lo

// ---------------- warp-MMA helpers (baseline PTX: sm_80+) ----------------
__device__ __forceinline__ uint32_t smem_u32(const void* p) {
    uint32_t a;
    asm("{ .reg .u64 t; cvta.to.shared.u64 t, %1; cvt.u32.u64 %0, t; }"
        : "=r"(a) : "l"(p));
    return a;
}
__device__ __forceinline__ void ldsm4(uint32_t& r0, uint32_t& r1,
                                      uint32_t& r2, uint32_t& r3, uint32_t addr) {
    asm volatile("ldmatrix.sync.aligned.m8n8.x4.shared.b16 {%0,%1,%2,%3}, [%4];"
                 : "=r"(r0), "=r"(r1), "=r"(r2), "=r"(r3) : "r"(addr));
}
__device__ __forceinline__ void mma_bf16(float& d0, float& d1, float& d2, float& d3,
                                         uint32_t a0, uint32_t a1, uint32_t a2, uint32_t a3,
                                         uint32_t b0, uint32_t b1) {
    asm volatile(
        "mma.sync.aligned.m16n8k16.row.col.f32.bf16.bf16.f32 "
        "{%0,%1,%2,%3}, {%4,%5,%6,%7}, {%8,%9}, {%0,%1,%2,%3};"
        : "+f"(d0), "+f"(d1), "+f"(d2), "+f"(d3)
        : "r"(a0), "r"(a1), "r"(a2), "r"(a3), "r"(b0), "r"(b1));
}
// swizzled smem offset: row r (64B rows of 32 bf16), 16B chunk kq in [0,4)
__device__ __forceinline__ uint32_t swz(uint32_t r, uint32_t kq) {
    return r * 64 + ((kq ^ ((r >> 1) & 3)) * 16);
}

// ---------------- prep kernels ----------------
__global__ void prep_w(const float* __restrict__ wq, const float* __restrict__ wk,
                       const float* __restrict__ wv, const float* __restrict__ wo) {
    int idx = blockIdx.x * blockDim.x + threadIdx.x;
    if (idx < 768 * 768) {
        int o = idx / 768, j = idx % 768;
        int t = j >> 8, i = j & 255;
        const float* w = (o < 256) ? wq : (o < 512) ? wk : wv;
        int oc = o & 255;
        float v = w[(oc * 256 + i) * 3 + t];
        __nv_bfloat16 h = __float2bfloat16(v);
        g_bhi[idx] = h;
        g_blo[idx] = __float2bfloat16(v - __bfloat162float(h));
    }
    if (idx < 256 * 256) {
        float v = wo[idx];
        __nv_bfloat16 h = __float2bfloat16(v);
        g_wohi[idx] = h;
        g_wolo[idx] = __float2bfloat16(v - __bfloat162float(h));
    }
}
__global__ void prep_x(const float* __restrict__ x, int total) {
    int i = blockIdx.x * blockDim.x + threadIdx.x;
    if (i < total) {
        float v = x[i];
        __nv_bfloat16 h = __float2bfloat16(v);
        g_xhi[i] = h;
        g_xlo[i] = __float2bfloat16(v - __bfloat162float(h));
    }
}

// ---------------- split-bf16 HMMA GEMM ----------------
// CONV: C[M,768] = A[M,768] @ W3[768,768]^T  (A gathered from x with node halo)
// PROJ: C[M,256] = attn[M,256] @ wo[256,256]^T (+bias)
// Tile BM=128 BN=128 BK=32; 8 warps (4x2); warp tile 32x64.
template<bool CONV>
__global__ __launch_bounds__(256)
void hmma_gemm(const float* __restrict__ bo, float* __restrict__ outp,
               int Kdim, int M) {
    __shared__ __align__(16) char smem[32768];   // Ahi 8K | Alo 8K | Bhi 8K | Blo 8K
    const uint32_t sA = smem_u32(smem);
    const uint32_t sB = sA + 16384;

    int tid = threadIdx.x, lane = tid & 31, wid = tid >> 5;
    int row0 = blockIdx.y * 128;
    int col0 = blockIdx.x * 128;
    int wm = (wid >> 1) * 32;          // warp m offset in tile
    int wn = (wid & 1) * 64;           // warp n offset in tile

    const __nv_bfloat16* Bhi = CONV ? g_bhi : g_wohi;
    const __nv_bfloat16* Blo = CONV ? g_blo : g_wolo;
    const int bstride = CONV ? 768 : 256;

    float acc[2][8][4];
#pragma unroll
    for (int i = 0; i < 2; i++)
#pragma unroll
        for (int j = 0; j < 8; j++)
#pragma unroll
            for (int q = 0; q < 4; q++) acc[i][j][q] = 0.f;

    int4 aH[2], aL[2], bH[2], bL[2];

    auto loadG = [&](int kt) {
        int k0 = kt * 32;
#pragma unroll
        for (int p = 0; p < 2; p++) {
            int f = p * 256 + tid;
            int r = f >> 2, kq = f & 3;
            if (CONV) {
                int t = k0 >> 8;                     // tap (constant per k-chunk)
                int dcol = (k0 & 255) + kq * 8;
                int m = row0 + r;
                int n = m % N_NODES;
                int ns = n + t - 1;
                if ((unsigned)ns < (unsigned)N_NODES) {
                    size_t src = (size_t)(m + t - 1) * 256 + dcol;
                    aH[p] = *reinterpret_cast<const int4*>(g_xhi + src);
                    aL[p] = *reinterpret_cast<const int4*>(g_xlo + src);
                } else {
                    aH[p] = make_int4(0, 0, 0, 0);
                    aL[p] = make_int4(0, 0, 0, 0);
                }
            } else {
                size_t src = (size_t)(row0 + r) * 256 + k0 + kq * 8;
                aH[p] = *reinterpret_cast<const int4*>(g_ahi + src);
                aL[p] = *reinterpret_cast<const int4*>(g_alo + src);
            }
            size_t bsrc = (size_t)(col0 + r) * bstride + k0 + kq * 8;
            bH[p] = *reinterpret_cast<const int4*>(Bhi + bsrc);
            bL[p] = *reinterpret_cast<const int4*>(Blo + bsrc);
        }
    };
    auto storeS = [&]() {
#pragma unroll
        for (int p = 0; p < 2; p++) {
            int f = p * 256 + tid;
            uint32_t r = f >> 2, kq = f & 3;
            uint32_t o = swz(r, kq);
            *reinterpret_cast<int4*>(smem + o)         = aH[p];
            *reinterpret_cast<int4*>(smem + 8192 + o)  = aL[p];
            *reinterpret_cast<int4*>(smem + 16384 + o) = bH[p];
            *reinterpret_cast<int4*>(smem + 24576 + o) = bL[p];
        }
    };
    auto compute = [&]() {
#pragma unroll
        for (int ks = 0; ks < 2; ks++) {           // two k16 steps within BK=32
            uint32_t fAh[2][4], fAl[2][4], fBh[8][2], fBl[8][2];
#pragma unroll
            for (int mf = 0; mf < 2; mf++) {
                uint32_t r = wm + mf * 16 + (lane & 15);
                uint32_t kq = ks * 2 + (lane >> 4);
                uint32_t ad = sA + swz(r, kq);
                ldsm4(fAh[mf][0], fAh[mf][1], fAh[mf][2], fAh[mf][3], ad);
                ldsm4(fAl[mf][0], fAl[mf][1], fAl[mf][2], fAl[mf][3], ad + 8192);
            }
#pragma unroll
            for (int np = 0; np < 4; np++) {       // pairs of n8 frags
                uint32_t r = wn + np * 16 + (lane & 7) + ((lane >> 4) << 3);
                uint32_t kq = ks * 2 + ((lane >> 3) & 1);
                uint32_t ad = sB + swz(r, kq);
                ldsm4(fBh[2 * np][0], fBh[2 * np][1],
                      fBh[2 * np + 1][0], fBh[2 * np + 1][1], ad);
                ldsm4(fBl[2 * np][0], fBl[2 * np][1],
                      fBl[2 * np + 1][0], fBl[2 * np + 1][1], ad + 8192);
            }
#pragma unroll
            for (int mf = 0; mf < 2; mf++)
#pragma unroll
                for (int nf = 0; nf < 8; nf++) {
                    float* d = acc[mf][nf];
                    mma_bf16(d[0], d[1], d[2], d[3],
                             fAh[mf][0], fAh[mf][1], fAh[mf][2], fAh[mf][3],
                             fBh[nf][0], fBh[nf][1]);
                    mma_bf16(d[0], d[1], d[2], d[3],
                             fAh[mf][0], fAh[mf][1], fAh[mf][2], fAh[mf][3],
                             fBl[nf][0], fBl[nf][1]);
                    mma_bf16(d[0], d[1], d[2], d[3],
                             fAl[mf][0], fAl[mf][1], fAl[mf][2], fAl[mf][3],
                             fBh[nf][0], fBh[nf][1]);
                }
        }
    };

    const int KT = Kdim / 32;
    loadG(0); storeS(); __syncthreads();
#pragma unroll 1
    for (int kt = 0; kt < KT; kt++) {
        if (kt + 1 < KT) loadG(kt + 1);
        compute();
        __syncthreads();
        if (kt + 1 < KT) { storeS(); __syncthreads(); }
    }

    // ---- epilogue ----
#pragma unroll
    for (int mf = 0; mf < 2; mf++) {
        int row = row0 + wm + mf * 16 + (lane >> 2);
#pragma unroll
        for (int nf = 0; nf < 8; nf++) {
            int col = col0 + wn + nf * 8 + 2 * (lane & 3);
            float* d = acc[mf][nf];
            if (CONV) {
                *reinterpret_cast<float2*>(&g_conv[(size_t)row * 768 + col]) =
                    make_float2(d[0], d[1]);
                *reinterpret_cast<float2*>(&g_conv[(size_t)(row + 8) * 768 + col]) =
                    make_float2(d[2], d[3]);
            } else {
                float b0 = bo[col], b1 = bo[col + 1];
                *reinterpret_cast<float2*>(&outp[(size_t)row * 256 + col]) =
                    make_float2(d[0] + b0, d[1] + b1);
                *reinterpret_cast<float2*>(&outp[(size_t)(row + 8) * 256 + col]) =
                    make_float2(d[2] + b0, d[3] + b1);
            }
        }
    }
}

// ---------------- LayerNorm + residual ----------------
__global__ __launch_bounds__(256)
void ln_kernel(const float* __restrict__ x,
               const float* __restrict__ gq, const float* __restrict__ bq,
               const float* __restrict__ gk, const float* __restrict__ bk,
               const float* __restrict__ gv, const float* __restrict__ bv) {
    int m = blockIdx.x;
    int tid = threadIdx.x;
    int lane = tid & 31, wid = tid >> 5;
    __shared__ float rs[8], rs2[8];
    float xv = x[(size_t)m * 256 + tid];
#pragma unroll
    for (int c = 0; c < 3; c++) {
        float v = g_conv[(size_t)m * 768 + c * 256 + tid];
        float s = v, s2 = v * v;
#pragma unroll
        for (int off = 16; off; off >>= 1) {
            s  += __shfl_xor_sync(0xffffffffu, s,  off);
            s2 += __shfl_xor_sync(0xffffffffu, s2, off);
        }
        if (lane == 0) { rs[wid] = s; rs2[wid] = s2; }
        __syncthreads();
        if (tid == 0) {
            float a = 0.f, a2 = 0.f;
            for (int i = 0; i < 8; i++) { a += rs[i]; a2 += rs2[i]; }
            rs[0] = a; rs2[0] = a2;
        }
        __syncthreads();
        float mean = rs[0] * (1.0f / 256.0f);
        float var  = rs2[0] * (1.0f / 256.0f) - mean * mean;
        float g  = (c == 0) ? gq[tid] : (c == 1) ? gk[tid] : gv[tid];
        float bb = (c == 0) ? bq[tid] : (c == 1) ? bk[tid] : bv[tid];
        float o = xv + (v - mean) * rsqrtf(var + 1e-5f) * g + bb;
        g_qkv[(size_t)m * 768 + c * 256 + tid] = o;
        __syncthreads();
    }
}

// ---------------- attention (warp per (b, head)), emits split-bf16 ----------------
__global__ __launch_bounds__(128)
void attn_kernel(const float* __restrict__ rel,
                 const float* __restrict__ gbias,
                 const float* __restrict__ alphap) {
    __shared__ float q_s[4][20][33];
    __shared__ float k_s[4][20][33];
    __shared__ float v_s[4][20][33];
    __shared__ float p_s[4][20][20];
    int lane = threadIdx.x & 31;
    int wid  = threadIdx.x >> 5;
    int h = blockIdx.y * 4 + wid;
    int b = blockIdx.x;
    float alpha = alphap[0];

    for (int idx = lane; idx < 20 * 32; idx += 32) {
        int n = idx >> 5, d = idx & 31;
        size_t base = (size_t)(b * 20 + n) * 768 + h * 32 + d;
        q_s[wid][n][d] = g_qkv[base];
        k_s[wid][n][d] = g_qkv[base + 256];
        v_s[wid][n][d] = g_qkv[base + 512];
    }
    __syncwarp();

    for (int idx = lane; idx < 400; idx += 32) {
        int n = idx / 20, m2 = idx % 20;
        float acc = 0.f;
#pragma unroll
        for (int i = 0; i < 32; i++) acc += q_s[wid][n][i] * k_s[wid][m2][i];
        acc *= 0.17677669529663689f;              // 1/sqrt(32)
        acc += rel[(n - m2 + 19) * 8 + h];
        acc += gbias[(h * 20 + n) * 20 + m2] * alpha;
        p_s[wid][n][m2] = acc;
    }
    __syncwarp();

    if (lane < 20) {
        int n = lane;
        float mx = -1e30f;
        for (int m2 = 0; m2 < 20; m2++) mx = fmaxf(mx, p_s[wid][n][m2]);
        float s = 0.f;
        for (int m2 = 0; m2 < 20; m2++) {
            float e = __expf(p_s[wid][n][m2] - mx);
            p_s[wid][n][m2] = e; s += e;
        }
        float inv = 1.f / s;
        for (int m2 = 0; m2 < 20; m2++) p_s[wid][n][m2] *= inv;
    }
    __syncwarp();

    int d = lane;
    for (int n = 0; n < 20; n++) {
        float acc = 0.f;
#pragma unroll
        for (int m2 = 0; m2 < 20; m2++) acc += p_s[wid][n][m2] * v_s[wid][m2][d];
        size_t idx = (size_t)(b * 20 + n) * 256 + h * 32 + d;
        __nv_bfloat16 hh = __float2bfloat16(acc);
        g_ahi[idx] = hh;
        g_alo[idx] = __float2bfloat16(acc - __bfloat162float(hh));
    }
}

// ---------------- launch ----------------
extern "C" void kernel_launch(void* const* d_in, const int* in_sizes, int n_in,
                              void* d_out, int out_size) {
    const float* x     = (const float*)d_in[0];
    const float* wq    = (const float*)d_in[1];
    const float* wk    = (const float*)d_in[2];
    const float* wv    = (const float*)d_in[3];
    const float* gq    = (const float*)d_in[4];
    const float* bq    = (const float*)d_in[5];
    const float* gk    = (const float*)d_in[6];
    const float* bk    = (const float*)d_in[7];
    const float* gv    = (const float*)d_in[8];
    const float* bv    = (const float*)d_in[9];
    const float* rel   = (const float*)d_in[10];
    const float* gbias = (const float*)d_in[11];
    const float* alpha = (const float*)d_in[12];
    const float* wo    = (const float*)d_in[13];
    const float* bo    = (const float*)d_in[14];
    float* out = (float*)d_out;

    int B = in_sizes[0] / (N_NODES * D_MODEL);
    int M = B * N_NODES;

    prep_w<<<(768 * 768 + 255) / 256, 256>>>(wq, wk, wv, wo);
    prep_x<<<(M * 256 + 255) / 256, 256>>>(x, M * 256);

    hmma_gemm<true><<<dim3(6, M / 128), 256>>>(nullptr, nullptr, 768, M);

    ln_kernel<<<M, 256>>>(x, gq, bq, gk, bk, gv, bv);

    attn_kernel<<<dim3(B, 2), 128>>>(rel, gbias, alpha);

    hmma_gemm<false><<<dim3(2, M / 128), 256>>>(bo, out, 256, M);
}

// round 4
// speedup vs baseline: 2.1383x; 1.3165x over previous
#include <cuda_runtime.h>
#include <cuda_bf16.h>
#include <cstdint>

#define D_MODEL 256
#define N_NODES 20
#define N_HEADS 8
#define BMAX    8192
#define MMAX    (BMAX * N_NODES)   // 163840 rows

// ---------------- scratch (device globals: allocation-free) ----------------
__device__ __nv_bfloat16 g_xhi[(size_t)MMAX * 256];
__device__ __nv_bfloat16 g_xlo[(size_t)MMAX * 256];
__device__ __nv_bfloat16 g_bhi[768 * 768];     // conv weights [o][j=t*256+i]
__device__ __nv_bfloat16 g_blo[768 * 768];
__device__ __nv_bfloat16 g_wohi[256 * 256];    // wo [o][i]
__device__ __nv_bfloat16 g_wolo[256 * 256];
__device__ float g_qkv [(size_t)MMAX * 768];   // q|k|v after LN+residual
__device__ __nv_bfloat16 g_ahi[(size_t)MMAX * 256];  // attn out hi
__device__ __nv_bfloat16 g_alo[(size_t)MMAX * 256];  // attn out lo

// ---------------- warp-MMA helpers (baseline PTX: sm_80+) ----------------
__device__ __forceinline__ uint32_t smem_u32(const void* p) {
    uint32_t a;
    asm("{ .reg .u64 t; cvta.to.shared.u64 t, %1; cvt.u32.u64 %0, t; }"
        : "=r"(a) : "l"(p));
    return a;
}
__device__ __forceinline__ void ldsm4(uint32_t& r0, uint32_t& r1,
                                      uint32_t& r2, uint32_t& r3, uint32_t addr) {
    asm volatile("ldmatrix.sync.aligned.m8n8.x4.shared.b16 {%0,%1,%2,%3}, [%4];"
                 : "=r"(r0), "=r"(r1), "=r"(r2), "=r"(r3) : "r"(addr));
}
__device__ __forceinline__ void mma_bf16(float* d,
                                         const uint32_t* a,
                                         uint32_t b0, uint32_t b1) {
    asm volatile(
        "mma.sync.aligned.m16n8k16.row.col.f32.bf16.bf16.f32 "
        "{%0,%1,%2,%3}, {%4,%5,%6,%7}, {%8,%9}, {%0,%1,%2,%3};"
        : "+f"(d[0]), "+f"(d[1]), "+f"(d[2]), "+f"(d[3])
        : "r"(a[0]), "r"(a[1]), "r"(a[2]), "r"(a[3]), "r"(b0), "r"(b1));
}
__device__ __forceinline__ uint32_t swz(uint32_t r, uint32_t kq) {
    return r * 64 + ((kq ^ ((r >> 1) & 3)) * 16);
}
__device__ __forceinline__ void cp16(uint32_t dst, const void* src, int srcsz) {
    asm volatile("cp.async.cg.shared.global [%0], [%1], 16, %2;"
                 :: "r"(dst), "l"(__cvta_generic_to_global(src)), "r"(srcsz)
                 : "memory");
}
__device__ __forceinline__ void cp_commit() {
    asm volatile("cp.async.commit_group;" ::: "memory");
}
template<int N>
__device__ __forceinline__ void cp_wait() {
    asm volatile("cp.async.wait_group %0;" :: "n"(N) : "memory");
}

// ---------------- prep kernels ----------------
__global__ void prep_w(const float* __restrict__ wq, const float* __restrict__ wk,
                       const float* __restrict__ wv, const float* __restrict__ wo) {
    int idx = blockIdx.x * blockDim.x + threadIdx.x;
    if (idx < 768 * 768) {
        int o = idx / 768, j = idx % 768;
        int t = j >> 8, i = j & 255;
        const float* w = (o < 256) ? wq : (o < 512) ? wk : wv;
        int oc = o & 255;
        float v = w[(oc * 256 + i) * 3 + t];
        __nv_bfloat16 h = __float2bfloat16(v);
        g_bhi[idx] = h;
        g_blo[idx] = __float2bfloat16(v - __bfloat162float(h));
    }
    if (idx < 256 * 256) {
        float v = wo[idx];
        __nv_bfloat16 h = __float2bfloat16(v);
        g_wohi[idx] = h;
        g_wolo[idx] = __float2bfloat16(v - __bfloat162float(h));
    }
}
__global__ void prep_x(const float* __restrict__ x, int total) {
    int i = blockIdx.x * blockDim.x + threadIdx.x;
    if (i < total) {
        float v = x[i];
        __nv_bfloat16 h = __float2bfloat16(v);
        g_xhi[i] = h;
        g_xlo[i] = __float2bfloat16(v - __bfloat162float(h));
    }
}

// ---------------- fused conv GEMM + LayerNorm + residual ----------------
// Per block: 128 rows x 256 cols (one q/k/v segment, seg = blockIdx.x).
// Split-bf16 3-pass HMMA; cp.async 2-stage pipeline; epilogue does LN+residual
// and writes g_qkv directly.
// smem: 2 stages x [Ahi 8K|Alo 8K|Bhi 16K|Blo 16K] = 96K, + red 1K + g/b 2K.
#define STAGE_SZ 49152
#define SMEM_CONV (2 * STAGE_SZ + 1024 + 2048)

__global__ __launch_bounds__(256, 1)
void conv_ln_kernel(const float* __restrict__ x,
                    const float* __restrict__ gq, const float* __restrict__ bq,
                    const float* __restrict__ gk, const float* __restrict__ bk,
                    const float* __restrict__ gv, const float* __restrict__ bv) {
    extern __shared__ __align__(16) char smem[];
    const uint32_t sb = smem_u32(smem);
    float* red = reinterpret_cast<float*>(smem + 2 * STAGE_SZ);        // [128][2]
    float* gam = reinterpret_cast<float*>(smem + 2 * STAGE_SZ + 1024); // [256]
    float* bet = reinterpret_cast<float*>(smem + 2 * STAGE_SZ + 2048); // [256]

    int tid = threadIdx.x, lane = tid & 31, wid = tid >> 5;
    int seg = blockIdx.x;              // 0=q 1=k 2=v
    int row0 = blockIdx.y * 128;
    int wm = (wid >> 2) * 64;          // warp m offset (2 warp-rows)
    int wn = (wid & 3) * 64;           // warp n offset (4 warp-cols)

    // stage gamma/beta + zero reduction buffer
    {
        const float* gsel = (seg == 0) ? gq : (seg == 1) ? gk : gv;
        const float* bsel = (seg == 0) ? bq : (seg == 1) ? bk : bv;
        gam[tid] = gsel[tid];
        bet[tid] = bsel[tid];
        red[tid] = 0.f;   // covers 256 = 128 rows x 2
    }

    float acc[4][8][4];
#pragma unroll
    for (int i = 0; i < 4; i++)
#pragma unroll
        for (int j = 0; j < 8; j++)
#pragma unroll
            for (int q = 0; q < 4; q++) acc[i][j][q] = 0.f;

    auto issue = [&](int s, int kt) {
        uint32_t stg = sb + s * STAGE_SZ;
        int k0 = kt * 32;
        int t = kt >> 3;                 // tap (8 chunks of 32 per tap)
        int dbase = (kt & 7) * 32;
        // A: 128 x 32 bf16, hi+lo
#pragma unroll
        for (int it = 0; it < 2; it++) {
            int f = it * 256 + tid;
            int r = f >> 2, kq = f & 3;
            int m = row0 + r;
            int n = m % N_NODES;
            int ns = n + t - 1;
            int ok = ((unsigned)ns < (unsigned)N_NODES);
            size_t src = (size_t)(ok ? (m + t - 1) : m) * 256 + dbase + kq * 8;
            int sz = ok ? 16 : 0;
            uint32_t o = swz((uint32_t)r, (uint32_t)kq);
            cp16(stg + o, g_xhi + src, sz);
            cp16(stg + 8192 + o, g_xlo + src, sz);
        }
        // B: 256 x 32 bf16, hi+lo
#pragma unroll
        for (int it = 0; it < 4; it++) {
            int f = it * 256 + tid;
            int r = f >> 2, kq = f & 3;
            size_t src = (size_t)(seg * 256 + r) * 768 + k0 + kq * 8;
            uint32_t o = swz((uint32_t)r, (uint32_t)kq);
            cp16(stg + 16384 + o, g_bhi + src, 16);
            cp16(stg + 32768 + o, g_blo + src, 16);
        }
        cp_commit();
    };

    auto compute = [&](int s) {
        uint32_t base = sb + s * STAGE_SZ;
#pragma unroll
        for (int ks = 0; ks < 2; ks++) {
            uint32_t fAh[4][4], fAl[4][4];
#pragma unroll
            for (int mf = 0; mf < 4; mf++) {
                uint32_t r = wm + mf * 16 + (lane & 15);
                uint32_t kq = ks * 2 + (lane >> 4);
                uint32_t ad = base + swz(r, kq);
                ldsm4(fAh[mf][0], fAh[mf][1], fAh[mf][2], fAh[mf][3], ad);
                ldsm4(fAl[mf][0], fAl[mf][1], fAl[mf][2], fAl[mf][3], ad + 8192);
            }
#pragma unroll
            for (int np = 0; np < 4; np++) {
                uint32_t r = wn + np * 16 + (lane & 7) + ((lane >> 4) << 3);
                uint32_t kq = ks * 2 + ((lane >> 3) & 1);
                uint32_t ad = base + 16384 + swz(r, kq);
                uint32_t bh0, bh1, bh2, bh3, bl0, bl1, bl2, bl3;
                ldsm4(bh0, bh1, bh2, bh3, ad);
                ldsm4(bl0, bl1, bl2, bl3, ad + 16384);
#pragma unroll
                for (int mf = 0; mf < 4; mf++) {
                    float* d0 = acc[mf][2 * np];
                    float* d1 = acc[mf][2 * np + 1];
                    mma_bf16(d0, fAh[mf], bh0, bh1);
                    mma_bf16(d0, fAh[mf], bl0, bl1);
                    mma_bf16(d0, fAl[mf], bh0, bh1);
                    mma_bf16(d1, fAh[mf], bh2, bh3);
                    mma_bf16(d1, fAh[mf], bl2, bl3);
                    mma_bf16(d1, fAl[mf], bh2, bh3);
                }
            }
        }
    };

    issue(0, 0);
#pragma unroll 1
    for (int kt = 0; kt < 24; kt++) {
        int s = kt & 1;
        if (kt + 1 < 24) { issue(s ^ 1, kt + 1); cp_wait<1>(); }
        else             { cp_wait<0>(); }
        __syncthreads();
        compute(s);
        __syncthreads();
    }

    // ---- LN + residual epilogue ----
    // per-thread partial moments for its 8 rows x 16 cols, quad-reduce, smem-acc
#pragma unroll
    for (int mf = 0; mf < 4; mf++) {
#pragma unroll
        for (int rr = 0; rr < 2; rr++) {
            int rloc = wm + mf * 16 + (lane >> 2) + rr * 8;
            float s = 0.f, s2 = 0.f;
#pragma unroll
            for (int nf = 0; nf < 8; nf++) {
                float c0 = acc[mf][nf][rr * 2];
                float c1 = acc[mf][nf][rr * 2 + 1];
                s += c0 + c1; s2 += c0 * c0 + c1 * c1;
            }
            s  += __shfl_xor_sync(0xffffffffu, s, 1);
            s  += __shfl_xor_sync(0xffffffffu, s, 2);
            s2 += __shfl_xor_sync(0xffffffffu, s2, 1);
            s2 += __shfl_xor_sync(0xffffffffu, s2, 2);
            if ((lane & 3) == 0) {
                atomicAdd(&red[rloc * 2], s);
                atomicAdd(&red[rloc * 2 + 1], s2);
            }
        }
    }
    __syncthreads();

#pragma unroll
    for (int mf = 0; mf < 4; mf++) {
#pragma unroll
        for (int rr = 0; rr < 2; rr++) {
            int rloc = wm + mf * 16 + (lane >> 2) + rr * 8;
            int rg = row0 + rloc;
            float mean = red[rloc * 2] * (1.0f / 256.0f);
            float var  = red[rloc * 2 + 1] * (1.0f / 256.0f) - mean * mean;
            float inv  = rsqrtf(var + 1e-5f);
#pragma unroll
            for (int nf = 0; nf < 8; nf++) {
                int cloc = wn + nf * 8 + 2 * (lane & 3);
                float2 xv = *reinterpret_cast<const float2*>(
                    &x[(size_t)rg * 256 + cloc]);
                float c0 = acc[mf][nf][rr * 2];
                float c1 = acc[mf][nf][rr * 2 + 1];
                float o0 = xv.x + (c0 - mean) * inv * gam[cloc]     + bet[cloc];
                float o1 = xv.y + (c1 - mean) * inv * gam[cloc + 1] + bet[cloc + 1];
                *reinterpret_cast<float2*>(
                    &g_qkv[(size_t)rg * 768 + seg * 256 + cloc]) =
                    make_float2(o0, o1);
            }
        }
    }
}

// ---------------- proj GEMM (split-bf16 HMMA, 128x128 tile) ----------------
__global__ __launch_bounds__(256)
void proj_gemm(const float* __restrict__ bo, float* __restrict__ outp, int M) {
    __shared__ __align__(16) char smem[32768];   // Ahi 8K | Alo 8K | Bhi 8K | Blo 8K
    const uint32_t sA = smem_u32(smem);
    const uint32_t sB = sA + 16384;

    int tid = threadIdx.x, lane = tid & 31, wid = tid >> 5;
    int row0 = blockIdx.y * 128;
    int col0 = blockIdx.x * 128;
    int wm = (wid >> 1) * 32;
    int wn = (wid & 1) * 64;

    float acc[2][8][4];
#pragma unroll
    for (int i = 0; i < 2; i++)
#pragma unroll
        for (int j = 0; j < 8; j++)
#pragma unroll
            for (int q = 0; q < 4; q++) acc[i][j][q] = 0.f;

    auto issue = [&](int kt) {
        int k0 = kt * 32;
#pragma unroll
        for (int p = 0; p < 2; p++) {
            int f = p * 256 + tid;
            uint32_t r = f >> 2, kq = f & 3;
            uint32_t o = swz(r, kq);
            size_t asrc = (size_t)(row0 + r) * 256 + k0 + kq * 8;
            size_t bsrc = (size_t)(col0 + r) * 256 + k0 + kq * 8;
            cp16(sA + o,         g_ahi + asrc, 16);
            cp16(sA + 8192 + o,  g_alo + asrc, 16);
            cp16(sB + o,         g_wohi + bsrc, 16);
            cp16(sB + 8192 + o,  g_wolo + bsrc, 16);
        }
        cp_commit();
    };
    auto compute = [&]() {
#pragma unroll
        for (int ks = 0; ks < 2; ks++) {
            uint32_t fAh[2][4], fAl[2][4];
#pragma unroll
            for (int mf = 0; mf < 2; mf++) {
                uint32_t r = wm + mf * 16 + (lane & 15);
                uint32_t kq = ks * 2 + (lane >> 4);
                uint32_t ad = sA + swz(r, kq);
                ldsm4(fAh[mf][0], fAh[mf][1], fAh[mf][2], fAh[mf][3], ad);
                ldsm4(fAl[mf][0], fAl[mf][1], fAl[mf][2], fAl[mf][3], ad + 8192);
            }
#pragma unroll
            for (int np = 0; np < 4; np++) {
                uint32_t r = wn + np * 16 + (lane & 7) + ((lane >> 4) << 3);
                uint32_t kq = ks * 2 + ((lane >> 3) & 1);
                uint32_t ad = sB + swz(r, kq);
                uint32_t bh0, bh1, bh2, bh3, bl0, bl1, bl2, bl3;
                ldsm4(bh0, bh1, bh2, bh3, ad);
                ldsm4(bl0, bl1, bl2, bl3, ad + 8192);
#pragma unroll
                for (int mf = 0; mf < 2; mf++) {
                    float* d0 = acc[mf][2 * np];
                    float* d1 = acc[mf][2 * np + 1];
                    mma_bf16(d0, fAh[mf], bh0, bh1);
                    mma_bf16(d0, fAh[mf], bl0, bl1);
                    mma_bf16(d0, fAl[mf], bh0, bh1);
                    mma_bf16(d1, fAh[mf], bh2, bh3);
                    mma_bf16(d1, fAh[mf], bl2, bl3);
                    mma_bf16(d1, fAl[mf], bh2, bh3);
                }
            }
        }
    };

    // simple: load, compute, no cross-stage overlap (K=256 only, 8 iters)
#pragma unroll 1
    for (int kt = 0; kt < 8; kt++) {
        issue(kt);
        cp_wait<0>();
        __syncthreads();
        compute();
        __syncthreads();
    }

#pragma unroll
    for (int mf = 0; mf < 2; mf++) {
        int row = row0 + wm + mf * 16 + (lane >> 2);
#pragma unroll
        for (int nf = 0; nf < 8; nf++) {
            int col = col0 + wn + nf * 8 + 2 * (lane & 3);
            float* d = acc[mf][nf];
            float b0 = bo[col], b1 = bo[col + 1];
            *reinterpret_cast<float2*>(&outp[(size_t)row * 256 + col]) =
                make_float2(d[0] + b0, d[1] + b1);
            *reinterpret_cast<float2*>(&outp[(size_t)(row + 8) * 256 + col]) =
                make_float2(d[2] + b0, d[3] + b1);
        }
    }
}

// ---------------- attention (warp per (b, head)), emits split-bf16 ----------------
__global__ __launch_bounds__(128)
void attn_kernel(const float* __restrict__ rel,
                 const float* __restrict__ gbias,
                 const float* __restrict__ alphap) {
    __shared__ float q_s[4][20][36];
    __shared__ float k_s[4][20][36];
    __shared__ float v_s[4][20][36];
    __shared__ float p_s[4][20][20];
    int lane = threadIdx.x & 31;
    int wid  = threadIdx.x >> 5;
    int h = blockIdx.y * 4 + wid;
    int b = blockIdx.x;
    float alpha = alphap[0];

    // vectorized load: 20 rows x 32 cols = 160 float4 per array
    for (int idx = lane; idx < 160; idx += 32) {
        int n = idx >> 3, d4 = (idx & 7) << 2;
        size_t base = (size_t)(b * 20 + n) * 768 + h * 32 + d4;
        *reinterpret_cast<float4*>(&q_s[wid][n][d4]) =
            *reinterpret_cast<const float4*>(&g_qkv[base]);
        *reinterpret_cast<float4*>(&k_s[wid][n][d4]) =
            *reinterpret_cast<const float4*>(&g_qkv[base + 256]);
        *reinterpret_cast<float4*>(&v_s[wid][n][d4]) =
            *reinterpret_cast<const float4*>(&g_qkv[base + 512]);
    }
    __syncwarp();

    for (int idx = lane; idx < 400; idx += 32) {
        int n = idx / 20, m2 = idx % 20;
        float acc = 0.f;
#pragma unroll
        for (int i = 0; i < 32; i++) acc += q_s[wid][n][i] * k_s[wid][m2][i];
        acc *= 0.17677669529663689f;              // 1/sqrt(32)
        acc += rel[(n - m2 + 19) * 8 + h];
        acc += gbias[(h * 20 + n) * 20 + m2] * alpha;
        p_s[wid][n][m2] = acc;
    }
    __syncwarp();

    if (lane < 20) {
        int n = lane;
        float mx = -1e30f;
        for (int m2 = 0; m2 < 20; m2++) mx = fmaxf(mx, p_s[wid][n][m2]);
        float s = 0.f;
        for (int m2 = 0; m2 < 20; m2++) {
            float e = __expf(p_s[wid][n][m2] - mx);
            p_s[wid][n][m2] = e; s += e;
        }
        float inv = 1.f / s;
        for (int m2 = 0; m2 < 20; m2++) p_s[wid][n][m2] *= inv;
    }
    __syncwarp();

    int d = lane;
    for (int n = 0; n < 20; n++) {
        float acc = 0.f;
#pragma unroll
        for (int m2 = 0; m2 < 20; m2++) acc += p_s[wid][n][m2] * v_s[wid][m2][d];
        size_t idx = (size_t)(b * 20 + n) * 256 + h * 32 + d;
        __nv_bfloat16 hh = __float2bfloat16(acc);
        g_ahi[idx] = hh;
        g_alo[idx] = __float2bfloat16(acc - __bfloat162float(hh));
    }
}

// ---------------- launch ----------------
extern "C" void kernel_launch(void* const* d_in, const int* in_sizes, int n_in,
                              void* d_out, int out_size) {
    const float* x     = (const float*)d_in[0];
    const float* wq    = (const float*)d_in[1];
    const float* wk    = (const float*)d_in[2];
    const float* wv    = (const float*)d_in[3];
    const float* gq    = (const float*)d_in[4];
    const float* bq    = (const float*)d_in[5];
    const float* gk    = (const float*)d_in[6];
    const float* bk    = (const float*)d_in[7];
    const float* gv    = (const float*)d_in[8];
    const float* bv    = (const float*)d_in[9];
    const float* rel   = (const float*)d_in[10];
    const float* gbias = (const float*)d_in[11];
    const float* alpha = (const float*)d_in[12];
    const float* wo    = (const float*)d_in[13];
    const float* bo    = (const float*)d_in[14];
    float* out = (float*)d_out;

    int B = in_sizes[0] / (N_NODES * D_MODEL);
    int M = B * N_NODES;

    static int smem_set = 0;
    if (!smem_set) {
        cudaFuncSetAttribute(conv_ln_kernel,
                             cudaFuncAttributeMaxDynamicSharedMemorySize,
                             SMEM_CONV);
        smem_set = 1;
    }

    prep_w<<<(768 * 768 + 255) / 256, 256>>>(wq, wk, wv, wo);
    prep_x<<<(M * 256 + 255) / 256, 256>>>(x, M * 256);

    conv_ln_kernel<<<dim3(3, M / 128), 256, SMEM_CONV>>>(
        x, gq, bq, gk, bk, gv, bv);

    attn_kernel<<<dim3(B, 2), 128>>>(rel, gbias, alpha);

    proj_gemm<<<dim3(2, M / 128), 256>>>(bo, out, M);
}

// round 5
// speedup vs baseline: 2.3339x; 1.0915x over previous
#include <cuda_runtime.h>
#include <cuda_bf16.h>
#include <cstdint>

#define D_MODEL 256
#define N_NODES 20
#define N_HEADS 8
#define BMAX    8192
#define MMAX    (BMAX * N_NODES)   // 163840 rows

// ---------------- scratch (device globals: allocation-free) ----------------
__device__ __nv_bfloat16 g_xhi[(size_t)MMAX * 256];
__device__ __nv_bfloat16 g_xlo[(size_t)MMAX * 256];
__device__ __nv_bfloat16 g_bhi[768 * 768];     // conv weights [o][j=t*256+i]
__device__ __nv_bfloat16 g_blo[768 * 768];
__device__ __nv_bfloat16 g_wohi[256 * 256];    // wo [o][i]
__device__ __nv_bfloat16 g_wolo[256 * 256];
__device__ float g_qkv [(size_t)MMAX * 768];   // q|k|v after LN+residual
__device__ __nv_bfloat16 g_ahi[(size_t)MMAX * 256];  // attn out hi
__device__ __nv_bfloat16 g_alo[(size_t)MMAX * 256];  // attn out lo

// ---------------- warp-MMA helpers (baseline PTX: sm_80+) ----------------
__device__ __forceinline__ uint32_t smem_u32(const void* p) {
    uint32_t a;
    asm("{ .reg .u64 t; cvta.to.shared.u64 t, %1; cvt.u32.u64 %0, t; }"
        : "=r"(a) : "l"(p));
    return a;
}
__device__ __forceinline__ void ldsm4(uint32_t& r0, uint32_t& r1,
                                      uint32_t& r2, uint32_t& r3, uint32_t addr) {
    asm volatile("ldmatrix.sync.aligned.m8n8.x4.shared.b16 {%0,%1,%2,%3}, [%4];"
                 : "=r"(r0), "=r"(r1), "=r"(r2), "=r"(r3) : "r"(addr));
}
__device__ __forceinline__ void mma_bf16(float* d,
                                         const uint32_t* a,
                                         uint32_t b0, uint32_t b1) {
    asm volatile(
        "mma.sync.aligned.m16n8k16.row.col.f32.bf16.bf16.f32 "
        "{%0,%1,%2,%3}, {%4,%5,%6,%7}, {%8,%9}, {%0,%1,%2,%3};"
        : "+f"(d[0]), "+f"(d[1]), "+f"(d[2]), "+f"(d[3])
        : "r"(a[0]), "r"(a[1]), "r"(a[2]), "r"(a[3]), "r"(b0), "r"(b1));
}
__device__ __forceinline__ uint32_t swz(uint32_t r, uint32_t kq) {
    return r * 64 + ((kq ^ ((r >> 1) & 3)) * 16);
}
__device__ __forceinline__ void cp16(uint32_t dst, const void* src, int srcsz) {
    asm volatile("cp.async.cg.shared.global [%0], [%1], 16, %2;"
                 :: "r"(dst), "l"(__cvta_generic_to_global(src)), "r"(srcsz)
                 : "memory");
}
__device__ __forceinline__ void cp_commit() {
    asm volatile("cp.async.commit_group;" ::: "memory");
}
template<int N>
__device__ __forceinline__ void cp_wait() {
    asm volatile("cp.async.wait_group %0;" :: "n"(N) : "memory");
}

// ---------------- prep kernels ----------------
__global__ void prep_w(const float* __restrict__ wq, const float* __restrict__ wk,
                       const float* __restrict__ wv, const float* __restrict__ wo) {
    int idx = blockIdx.x * blockDim.x + threadIdx.x;
    if (idx < 768 * 768) {
        int o = idx / 768, j = idx % 768;
        int t = j >> 8, i = j & 255;
        const float* w = (o < 256) ? wq : (o < 512) ? wk : wv;
        int oc = o & 255;
        float v = w[(oc * 256 + i) * 3 + t];
        __nv_bfloat16 h = __float2bfloat16(v);
        g_bhi[idx] = h;
        g_blo[idx] = __float2bfloat16(v - __bfloat162float(h));
    }
    if (idx < 256 * 256) {
        float v = wo[idx];
        __nv_bfloat16 h = __float2bfloat16(v);
        g_wohi[idx] = h;
        g_wolo[idx] = __float2bfloat16(v - __bfloat162float(h));
    }
}
__global__ void prep_x(const float* __restrict__ x, int total4) {
    int i = blockIdx.x * blockDim.x + threadIdx.x;
    if (i < total4) {
        float4 v = reinterpret_cast<const float4*>(x)[i];
        __nv_bfloat16 h0 = __float2bfloat16(v.x);
        __nv_bfloat16 h1 = __float2bfloat16(v.y);
        __nv_bfloat16 h2 = __float2bfloat16(v.z);
        __nv_bfloat16 h3 = __float2bfloat16(v.w);
        __nv_bfloat162 hi0, hi1, lo0, lo1;
        hi0.x = h0; hi0.y = h1; hi1.x = h2; hi1.y = h3;
        lo0.x = __float2bfloat16(v.x - __bfloat162float(h0));
        lo0.y = __float2bfloat16(v.y - __bfloat162float(h1));
        lo1.x = __float2bfloat16(v.z - __bfloat162float(h2));
        lo1.y = __float2bfloat16(v.w - __bfloat162float(h3));
        reinterpret_cast<__nv_bfloat162*>(g_xhi)[i * 2]     = hi0;
        reinterpret_cast<__nv_bfloat162*>(g_xhi)[i * 2 + 1] = hi1;
        reinterpret_cast<__nv_bfloat162*>(g_xlo)[i * 2]     = lo0;
        reinterpret_cast<__nv_bfloat162*>(g_xlo)[i * 2 + 1] = lo1;
    }
}

// ---------------- fused conv GEMM + LayerNorm + residual ----------------
// Per block: 128 rows x 256 cols (one q/k/v segment, seg = blockIdx.x).
// Split-bf16 3-pass HMMA; cp.async 3-stage pipeline (1 barrier/chunk);
// epilogue does LN+residual and writes g_qkv directly.
#define STAGE_SZ 49152
#define SMEM_CONV (3 * STAGE_SZ + 1024 + 2048)

__global__ __launch_bounds__(256, 1)
void conv_ln_kernel(const float* __restrict__ x,
                    const float* __restrict__ gq, const float* __restrict__ bq,
                    const float* __restrict__ gk, const float* __restrict__ bk,
                    const float* __restrict__ gv, const float* __restrict__ bv) {
    extern __shared__ __align__(16) char smem[];
    const uint32_t sb = smem_u32(smem);
    float* red = reinterpret_cast<float*>(smem + 3 * STAGE_SZ);        // [128][2]
    float* gam = reinterpret_cast<float*>(smem + 3 * STAGE_SZ + 1024); // [256]
    float* bet = reinterpret_cast<float*>(smem + 3 * STAGE_SZ + 2048); // [256]

    int tid = threadIdx.x, lane = tid & 31, wid = tid >> 5;
    int seg = blockIdx.x;              // 0=q 1=k 2=v
    int row0 = blockIdx.y * 128;
    int wm = (wid >> 2) * 64;
    int wn = (wid & 3) * 64;

    {
        const float* gsel = (seg == 0) ? gq : (seg == 1) ? gk : gv;
        const float* bsel = (seg == 0) ? bq : (seg == 1) ? bk : bv;
        gam[tid] = gsel[tid];
        bet[tid] = bsel[tid];
        red[tid] = 0.f;
    }

    float acc[4][8][4];
#pragma unroll
    for (int i = 0; i < 4; i++)
#pragma unroll
        for (int j = 0; j < 8; j++)
#pragma unroll
            for (int q = 0; q < 4; q++) acc[i][j][q] = 0.f;

    auto issue = [&](int s, int kt) {
        uint32_t stg = sb + s * STAGE_SZ;
        int k0 = kt * 32;
        int t = kt >> 3;
        int dbase = (kt & 7) * 32;
#pragma unroll
        for (int it = 0; it < 2; it++) {
            int f = it * 256 + tid;
            int r = f >> 2, kq = f & 3;
            int m = row0 + r;
            int n = m % N_NODES;
            int ns = n + t - 1;
            int ok = ((unsigned)ns < (unsigned)N_NODES);
            size_t src = (size_t)(ok ? (m + t - 1) : m) * 256 + dbase + kq * 8;
            int sz = ok ? 16 : 0;
            uint32_t o = swz((uint32_t)r, (uint32_t)kq);
            cp16(stg + o, g_xhi + src, sz);
            cp16(stg + 8192 + o, g_xlo + src, sz);
        }
#pragma unroll
        for (int it = 0; it < 4; it++) {
            int f = it * 256 + tid;
            int r = f >> 2, kq = f & 3;
            size_t src = (size_t)(seg * 256 + r) * 768 + k0 + kq * 8;
            uint32_t o = swz((uint32_t)r, (uint32_t)kq);
            cp16(stg + 16384 + o, g_bhi + src, 16);
            cp16(stg + 32768 + o, g_blo + src, 16);
        }
        cp_commit();
    };

    auto compute = [&](int s) {
        uint32_t base = sb + s * STAGE_SZ;
#pragma unroll
        for (int ks = 0; ks < 2; ks++) {
            uint32_t fAh[4][4], fAl[4][4];
#pragma unroll
            for (int mf = 0; mf < 4; mf++) {
                uint32_t r = wm + mf * 16 + (lane & 15);
                uint32_t kq = ks * 2 + (lane >> 4);
                uint32_t ad = base + swz(r, kq);
                ldsm4(fAh[mf][0], fAh[mf][1], fAh[mf][2], fAh[mf][3], ad);
                ldsm4(fAl[mf][0], fAl[mf][1], fAl[mf][2], fAl[mf][3], ad + 8192);
            }
#pragma unroll
            for (int np = 0; np < 4; np++) {
                uint32_t r = wn + np * 16 + (lane & 7) + ((lane >> 4) << 3);
                uint32_t kq = ks * 2 + ((lane >> 3) & 1);
                uint32_t ad = base + 16384 + swz(r, kq);
                uint32_t bh0, bh1, bh2, bh3, bl0, bl1, bl2, bl3;
                ldsm4(bh0, bh1, bh2, bh3, ad);
                ldsm4(bl0, bl1, bl2, bl3, ad + 16384);
#pragma unroll
                for (int mf = 0; mf < 4; mf++) {
                    float* d0 = acc[mf][2 * np];
                    float* d1 = acc[mf][2 * np + 1];
                    mma_bf16(d0, fAh[mf], bh0, bh1);
                    mma_bf16(d0, fAh[mf], bl0, bl1);
                    mma_bf16(d0, fAl[mf], bh0, bh1);
                    mma_bf16(d1, fAh[mf], bh2, bh3);
                    mma_bf16(d1, fAh[mf], bl2, bl3);
                    mma_bf16(d1, fAl[mf], bh2, bh3);
                }
            }
        }
    };

    const int KT = 24;
    issue(0, 0);
    issue(1, 1);
#pragma unroll 1
    for (int kt = 0; kt < KT; kt++) {
        if (kt == KT - 1) cp_wait<0>(); else cp_wait<1>();
        __syncthreads();
        if (kt + 2 < KT) issue((kt + 2) % 3, kt + 2);
        compute(kt % 3);
    }

    // ---- LN + residual epilogue ----
#pragma unroll
    for (int mf = 0; mf < 4; mf++) {
#pragma unroll
        for (int rr = 0; rr < 2; rr++) {
            int rloc = wm + mf * 16 + (lane >> 2) + rr * 8;
            float s = 0.f, s2 = 0.f;
#pragma unroll
            for (int nf = 0; nf < 8; nf++) {
                float c0 = acc[mf][nf][rr * 2];
                float c1 = acc[mf][nf][rr * 2 + 1];
                s += c0 + c1; s2 += c0 * c0 + c1 * c1;
            }
            s  += __shfl_xor_sync(0xffffffffu, s, 1);
            s  += __shfl_xor_sync(0xffffffffu, s, 2);
            s2 += __shfl_xor_sync(0xffffffffu, s2, 1);
            s2 += __shfl_xor_sync(0xffffffffu, s2, 2);
            if ((lane & 3) == 0) {
                atomicAdd(&red[rloc * 2], s);
                atomicAdd(&red[rloc * 2 + 1], s2);
            }
        }
    }
    __syncthreads();

#pragma unroll
    for (int mf = 0; mf < 4; mf++) {
#pragma unroll
        for (int rr = 0; rr < 2; rr++) {
            int rloc = wm + mf * 16 + (lane >> 2) + rr * 8;
            int rg = row0 + rloc;
            float mean = red[rloc * 2] * (1.0f / 256.0f);
            float var  = red[rloc * 2 + 1] * (1.0f / 256.0f) - mean * mean;
            float inv  = rsqrtf(var + 1e-5f);
#pragma unroll
            for (int nf = 0; nf < 8; nf++) {
                int cloc = wn + nf * 8 + 2 * (lane & 3);
                float2 xv = *reinterpret_cast<const float2*>(
                    &x[(size_t)rg * 256 + cloc]);
                float c0 = acc[mf][nf][rr * 2];
                float c1 = acc[mf][nf][rr * 2 + 1];
                float o0 = xv.x + (c0 - mean) * inv * gam[cloc]     + bet[cloc];
                float o1 = xv.y + (c1 - mean) * inv * gam[cloc + 1] + bet[cloc + 1];
                *reinterpret_cast<float2*>(
                    &g_qkv[(size_t)rg * 768 + seg * 256 + cloc]) =
                    make_float2(o0, o1);
            }
        }
    }
}

// ---------------- proj GEMM (split-bf16 HMMA, 128x256 tile, 3-stage) ----------------
#define SMEM_PROJ (3 * STAGE_SZ)

__global__ __launch_bounds__(256, 1)
void proj_gemm(const float* __restrict__ bo, float* __restrict__ outp) {
    extern __shared__ __align__(16) char smem[];
    const uint32_t sb = smem_u32(smem);

    int tid = threadIdx.x, lane = tid & 31, wid = tid >> 5;
    int row0 = blockIdx.x * 128;
    int wm = (wid >> 2) * 64;
    int wn = (wid & 3) * 64;

    float acc[4][8][4];
#pragma unroll
    for (int i = 0; i < 4; i++)
#pragma unroll
        for (int j = 0; j < 8; j++)
#pragma unroll
            for (int q = 0; q < 4; q++) acc[i][j][q] = 0.f;

    auto issue = [&](int s, int kt) {
        uint32_t stg = sb + s * STAGE_SZ;
        int k0 = kt * 32;
#pragma unroll
        for (int it = 0; it < 2; it++) {
            int f = it * 256 + tid;
            int r = f >> 2, kq = f & 3;
            size_t src = (size_t)(row0 + r) * 256 + k0 + kq * 8;
            uint32_t o = swz((uint32_t)r, (uint32_t)kq);
            cp16(stg + o, g_ahi + src, 16);
            cp16(stg + 8192 + o, g_alo + src, 16);
        }
#pragma unroll
        for (int it = 0; it < 4; it++) {
            int f = it * 256 + tid;
            int r = f >> 2, kq = f & 3;
            size_t src = (size_t)r * 256 + k0 + kq * 8;
            uint32_t o = swz((uint32_t)r, (uint32_t)kq);
            cp16(stg + 16384 + o, g_wohi + src, 16);
            cp16(stg + 32768 + o, g_wolo + src, 16);
        }
        cp_commit();
    };

    auto compute = [&](int s) {
        uint32_t base = sb + s * STAGE_SZ;
#pragma unroll
        for (int ks = 0; ks < 2; ks++) {
            uint32_t fAh[4][4], fAl[4][4];
#pragma unroll
            for (int mf = 0; mf < 4; mf++) {
                uint32_t r = wm + mf * 16 + (lane & 15);
                uint32_t kq = ks * 2 + (lane >> 4);
                uint32_t ad = base + swz(r, kq);
                ldsm4(fAh[mf][0], fAh[mf][1], fAh[mf][2], fAh[mf][3], ad);
                ldsm4(fAl[mf][0], fAl[mf][1], fAl[mf][2], fAl[mf][3], ad + 8192);
            }
#pragma unroll
            for (int np = 0; np < 4; np++) {
                uint32_t r = wn + np * 16 + (lane & 7) + ((lane >> 4) << 3);
                uint32_t kq = ks * 2 + ((lane >> 3) & 1);
                uint32_t ad = base + 16384 + swz(r, kq);
                uint32_t bh0, bh1, bh2, bh3, bl0, bl1, bl2, bl3;
                ldsm4(bh0, bh1, bh2, bh3, ad);
                ldsm4(bl0, bl1, bl2, bl3, ad + 16384);
#pragma unroll
                for (int mf = 0; mf < 4; mf++) {
                    float* d0 = acc[mf][2 * np];
                    float* d1 = acc[mf][2 * np + 1];
                    mma_bf16(d0, fAh[mf], bh0, bh1);
                    mma_bf16(d0, fAh[mf], bl0, bl1);
                    mma_bf16(d0, fAl[mf], bh0, bh1);
                    mma_bf16(d1, fAh[mf], bh2, bh3);
                    mma_bf16(d1, fAh[mf], bl2, bl3);
                    mma_bf16(d1, fAl[mf], bh2, bh3);
                }
            }
        }
    };

    const int KT = 8;
    issue(0, 0);
    issue(1, 1);
#pragma unroll 1
    for (int kt = 0; kt < KT; kt++) {
        if (kt == KT - 1) cp_wait<0>(); else cp_wait<1>();
        __syncthreads();
        if (kt + 2 < KT) issue((kt + 2) % 3, kt + 2);
        compute(kt % 3);
    }

#pragma unroll
    for (int mf = 0; mf < 4; mf++) {
        int row = row0 + wm + mf * 16 + (lane >> 2);
#pragma unroll
        for (int nf = 0; nf < 8; nf++) {
            int col = wn + nf * 8 + 2 * (lane & 3);
            float* d = acc[mf][nf];
            float b0 = bo[col], b1 = bo[col + 1];
            *reinterpret_cast<float2*>(&outp[(size_t)row * 256 + col]) =
                make_float2(d[0] + b0, d[1] + b1);
            *reinterpret_cast<float2*>(&outp[(size_t)(row + 8) * 256 + col]) =
                make_float2(d[2] + b0, d[3] + b1);
        }
    }
}

// ---------------- attention (warp per (b, head)), register-centric ----------------
__global__ __launch_bounds__(128)
void attn_kernel(const float* __restrict__ rel,
                 const float* __restrict__ gbias,
                 const float* __restrict__ alphap) {
    __shared__ float q_s[4][20][36];
    __shared__ float k_s[4][20][36];
    __shared__ float p_s[4][20][20];
    int lane = threadIdx.x & 31;
    int wid  = threadIdx.x >> 5;
    int h = blockIdx.y * 4 + wid;
    int b = blockIdx.x;
    float alpha = alphap[0];

    // stage q,k into smem (vectorized); v straight into registers (lane = dim)
    for (int idx = lane; idx < 160; idx += 32) {
        int n = idx >> 3, d4 = (idx & 7) << 2;
        size_t base = (size_t)(b * 20 + n) * 768 + h * 32 + d4;
        *reinterpret_cast<float4*>(&q_s[wid][n][d4]) =
            *reinterpret_cast<const float4*>(&g_qkv[base]);
        *reinterpret_cast<float4*>(&k_s[wid][n][d4]) =
            *reinterpret_cast<const float4*>(&g_qkv[base + 256]);
    }
    float vreg[20];
#pragma unroll
    for (int m2 = 0; m2 < 20; m2++)
        vreg[m2] = g_qkv[(size_t)(b * 20 + m2) * 768 + 512 + h * 32 + lane];
    __syncwarp();

    // scores + softmax fully in registers; lane = query row n (20 active)
    if (lane < 20) {
        int n = lane;
        float4 q4[8];
#pragma unroll
        for (int j = 0; j < 8; j++)
            q4[j] = *reinterpret_cast<const float4*>(&q_s[wid][n][4 * j]);
        float sc[20];
        const float* gb = &gbias[(h * 20 + n) * 20];
        float4 gb4[5];
#pragma unroll
        for (int j = 0; j < 5; j++)
            gb4[j] = *reinterpret_cast<const float4*>(&gb[4 * j]);
        float mx = -1e30f;
#pragma unroll
        for (int m2 = 0; m2 < 20; m2++) {
            float a = 0.f;
#pragma unroll
            for (int j = 0; j < 8; j++) {
                float4 k4 = *reinterpret_cast<const float4*>(&k_s[wid][m2][4 * j]);
                a += q4[j].x * k4.x + q4[j].y * k4.y +
                     q4[j].z * k4.z + q4[j].w * k4.w;
            }
            float gbv = (&gb4[0].x)[m2];
            a = a * 0.17677669529663689f + rel[(n - m2 + 19) * 8 + h] + gbv * alpha;
            sc[m2] = a;
            mx = fmaxf(mx, a);
        }
        float ssum = 0.f;
#pragma unroll
        for (int m2 = 0; m2 < 20; m2++) {
            float e = __expf(sc[m2] - mx);
            sc[m2] = e; ssum += e;
        }
        float inv = 1.f / ssum;
#pragma unroll
        for (int j = 0; j < 5; j++) {
            float4 p4 = make_float4(sc[4 * j] * inv, sc[4 * j + 1] * inv,
                                    sc[4 * j + 2] * inv, sc[4 * j + 3] * inv);
            *reinterpret_cast<float4*>(&p_s[wid][n][4 * j]) = p4;
        }
    }
    __syncwarp();

    // AV: lane = dim d; p broadcast from smem, v in registers
#pragma unroll 1
    for (int n = 0; n < 20; n++) {
        float a = 0.f;
#pragma unroll
        for (int j = 0; j < 5; j++) {
            float4 p4 = *reinterpret_cast<const float4*>(&p_s[wid][n][4 * j]);
            a += p4.x * vreg[4 * j] + p4.y * vreg[4 * j + 1] +
                 p4.z * vreg[4 * j + 2] + p4.w * vreg[4 * j + 3];
        }
        size_t idx = (size_t)(b * 20 + n) * 256 + h * 32 + lane;
        __nv_bfloat16 hh = __float2bfloat16(a);
        g_ahi[idx] = hh;
        g_alo[idx] = __float2bfloat16(a - __bfloat162float(hh));
    }
}

// ---------------- launch ----------------
extern "C" void kernel_launch(void* const* d_in, const int* in_sizes, int n_in,
                              void* d_out, int out_size) {
    const float* x     = (const float*)d_in[0];
    const float* wq    = (const float*)d_in[1];
    const float* wk    = (const float*)d_in[2];
    const float* wv    = (const float*)d_in[3];
    const float* gq    = (const float*)d_in[4];
    const float* bq    = (const float*)d_in[5];
    const float* gk    = (const float*)d_in[6];
    const float* bk    = (const float*)d_in[7];
    const float* gv    = (const float*)d_in[8];
    const float* bv    = (const float*)d_in[9];
    const float* rel   = (const float*)d_in[10];
    const float* gbias = (const float*)d_in[11];
    const float* alpha = (const float*)d_in[12];
    const float* wo    = (const float*)d_in[13];
    const float* bo    = (const float*)d_in[14];
    float* out = (float*)d_out;

    int B = in_sizes[0] / (N_NODES * D_MODEL);
    int M = B * N_NODES;

    cudaFuncSetAttribute(conv_ln_kernel,
                         cudaFuncAttributeMaxDynamicSharedMemorySize, SMEM_CONV);
    cudaFuncSetAttribute(proj_gemm,
                         cudaFuncAttributeMaxDynamicSharedMemorySize, SMEM_PROJ);

    prep_w<<<(768 * 768 + 255) / 256, 256>>>(wq, wk, wv, wo);
    prep_x<<<(M * 64 + 255) / 256, 256>>>(x, M * 64);

    conv_ln_kernel<<<dim3(3, M / 128), 256, SMEM_CONV>>>(
        x, gq, bq, gk, bk, gv, bv);

    attn_kernel<<<dim3(B, 2), 128>>>(rel, gbias, alpha);

    proj_gemm<<<M / 128, 256, SMEM_PROJ>>>(bo, out);
}

// round 6
// speedup vs baseline: 2.9436x; 1.2612x over previous
#include <cuda_runtime.h>
#include <cuda_bf16.h>
#include <cuda_fp16.h>
#include <cstdint>

#define D_MODEL 256
#define N_NODES 20
#define N_HEADS 8
#define BMAX    8192
#define MMAX    (BMAX * N_NODES)   // 163840 rows

// ---------------- scratch (device globals: allocation-free) ----------------
__device__ __half g_xh[(size_t)MMAX * 256];     // x as single fp16
__device__ __half g_whi[768 * 768];             // conv weights hi [o][j=t*256+i]
__device__ __half g_wlo[768 * 768];             // conv weights lo
__device__ __nv_bfloat16 g_wohi[256 * 256];     // wo [o][i] (proj stays bf16 3-pass)
__device__ __nv_bfloat16 g_wolo[256 * 256];
__device__ float g_qkv [(size_t)MMAX * 768];    // q|k|v after LN+residual
__device__ __nv_bfloat16 g_ahi[(size_t)MMAX * 256];  // attn out hi
__device__ __nv_bfloat16 g_alo[(size_t)MMAX * 256];  // attn out lo

// ---------------- warp-MMA helpers (baseline PTX: sm_80+) ----------------
__device__ __forceinline__ uint32_t smem_u32(const void* p) {
    uint32_t a;
    asm("{ .reg .u64 t; cvta.to.shared.u64 t, %1; cvt.u32.u64 %0, t; }"
        : "=r"(a) : "l"(p));
    return a;
}
__device__ __forceinline__ void ldsm4(uint32_t& r0, uint32_t& r1,
                                      uint32_t& r2, uint32_t& r3, uint32_t addr) {
    asm volatile("ldmatrix.sync.aligned.m8n8.x4.shared.b16 {%0,%1,%2,%3}, [%4];"
                 : "=r"(r0), "=r"(r1), "=r"(r2), "=r"(r3) : "r"(addr));
}
__device__ __forceinline__ void mma_bf16(float* d,
                                         const uint32_t* a,
                                         uint32_t b0, uint32_t b1) {
    asm volatile(
        "mma.sync.aligned.m16n8k16.row.col.f32.bf16.bf16.f32 "
        "{%0,%1,%2,%3}, {%4,%5,%6,%7}, {%8,%9}, {%0,%1,%2,%3};"
        : "+f"(d[0]), "+f"(d[1]), "+f"(d[2]), "+f"(d[3])
        : "r"(a[0]), "r"(a[1]), "r"(a[2]), "r"(a[3]), "r"(b0), "r"(b1));
}
__device__ __forceinline__ void mma_f16(float* d,
                                        const uint32_t* a,
                                        uint32_t b0, uint32_t b1) {
    asm volatile(
        "mma.sync.aligned.m16n8k16.row.col.f32.f16.f16.f32 "
        "{%0,%1,%2,%3}, {%4,%5,%6,%7}, {%8,%9}, {%0,%1,%2,%3};"
        : "+f"(d[0]), "+f"(d[1]), "+f"(d[2]), "+f"(d[3])
        : "r"(a[0]), "r"(a[1]), "r"(a[2]), "r"(a[3]), "r"(b0), "r"(b1));
}
__device__ __forceinline__ uint32_t swz(uint32_t r, uint32_t kq) {
    return r * 64 + ((kq ^ ((r >> 1) & 3)) * 16);
}
__device__ __forceinline__ void cp16(uint32_t dst, const void* src, int srcsz) {
    asm volatile("cp.async.cg.shared.global [%0], [%1], 16, %2;"
                 :: "r"(dst), "l"(__cvta_generic_to_global(src)), "r"(srcsz)
                 : "memory");
}
__device__ __forceinline__ void cp_commit() {
    asm volatile("cp.async.commit_group;" ::: "memory");
}
template<int N>
__device__ __forceinline__ void cp_wait() {
    asm volatile("cp.async.wait_group %0;" :: "n"(N) : "memory");
}

// ---------------- prep kernels ----------------
__global__ void prep_w(const float* __restrict__ wq, const float* __restrict__ wk,
                       const float* __restrict__ wv, const float* __restrict__ wo) {
    int idx = blockIdx.x * blockDim.x + threadIdx.x;
    if (idx < 768 * 768) {
        int o = idx / 768, j = idx % 768;
        int t = j >> 8, i = j & 255;
        const float* w = (o < 256) ? wq : (o < 512) ? wk : wv;
        int oc = o & 255;
        float v = w[(oc * 256 + i) * 3 + t];
        __half h = __float2half(v);
        g_whi[idx] = h;
        g_wlo[idx] = __float2half(v - __half2float(h));
    }
    if (idx < 256 * 256) {
        float v = wo[idx];
        __nv_bfloat16 h = __float2bfloat16(v);
        g_wohi[idx] = h;
        g_wolo[idx] = __float2bfloat16(v - __bfloat162float(h));
    }
}
__global__ void prep_x(const float* __restrict__ x, int total4) {
    int i = blockIdx.x * blockDim.x + threadIdx.x;
    if (i < total4) {
        float4 v = reinterpret_cast<const float4*>(x)[i];
        __half2 h0, h1;
        h0.x = __float2half(v.x); h0.y = __float2half(v.y);
        h1.x = __float2half(v.z); h1.y = __float2half(v.w);
        reinterpret_cast<__half2*>(g_xh)[i * 2]     = h0;
        reinterpret_cast<__half2*>(g_xh)[i * 2 + 1] = h1;
    }
}

// ---------------- fused conv GEMM + LayerNorm + residual ----------------
// Per block: 128 rows x 256 cols (one q/k/v segment, seg = blockIdx.x).
// fp16 2-pass: A single fp16, B split hi/lo. cp.async 3-stage pipeline.
// Stage: A 8K | Bhi 16K | Blo 16K = 40K
#define STAGE_SZ 40960
#define SMEM_CONV (3 * STAGE_SZ + 1024 + 2048)

__global__ __launch_bounds__(256, 1)
void conv_ln_kernel(const float* __restrict__ x,
                    const float* __restrict__ gq, const float* __restrict__ bq,
                    const float* __restrict__ gk, const float* __restrict__ bk,
                    const float* __restrict__ gv, const float* __restrict__ bv) {
    extern __shared__ __align__(16) char smem[];
    const uint32_t sb = smem_u32(smem);
    float* red = reinterpret_cast<float*>(smem + 3 * STAGE_SZ);        // [128][2]
    float* gam = reinterpret_cast<float*>(smem + 3 * STAGE_SZ + 1024); // [256]
    float* bet = reinterpret_cast<float*>(smem + 3 * STAGE_SZ + 2048); // [256]

    int tid = threadIdx.x, lane = tid & 31, wid = tid >> 5;
    int seg = blockIdx.x;              // 0=q 1=k 2=v
    int row0 = blockIdx.y * 128;
    int wm = (wid >> 2) * 64;
    int wn = (wid & 3) * 64;

    {
        const float* gsel = (seg == 0) ? gq : (seg == 1) ? gk : gv;
        const float* bsel = (seg == 0) ? bq : (seg == 1) ? bk : bv;
        gam[tid] = gsel[tid];
        bet[tid] = bsel[tid];
        red[tid] = 0.f;
    }

    float acc[4][8][4];
#pragma unroll
    for (int i = 0; i < 4; i++)
#pragma unroll
        for (int j = 0; j < 8; j++)
#pragma unroll
            for (int q = 0; q < 4; q++) acc[i][j][q] = 0.f;

    auto issue = [&](int s, int kt) {
        uint32_t stg = sb + s * STAGE_SZ;
        int k0 = kt * 32;
        int t = kt >> 3;
        int dbase = (kt & 7) * 32;
        // A: 128 rows x 32 fp16 = 8KB = 512 cp16 -> 2 per thread
#pragma unroll
        for (int it = 0; it < 2; it++) {
            int f = it * 256 + tid;
            int r = f >> 2, kq = f & 3;
            int m = row0 + r;
            int n = m % N_NODES;
            int ns = n + t - 1;
            int ok = ((unsigned)ns < (unsigned)N_NODES);
            size_t src = (size_t)(ok ? (m + t - 1) : m) * 256 + dbase + kq * 8;
            int sz = ok ? 16 : 0;
            cp16(stg + swz((uint32_t)r, (uint32_t)kq), g_xh + src, sz);
        }
        // B: 256 rows x 32 fp16, hi+lo
#pragma unroll
        for (int it = 0; it < 4; it++) {
            int f = it * 256 + tid;
            int r = f >> 2, kq = f & 3;
            size_t src = (size_t)(seg * 256 + r) * 768 + k0 + kq * 8;
            uint32_t o = swz((uint32_t)r, (uint32_t)kq);
            cp16(stg + 8192 + o, g_whi + src, 16);
            cp16(stg + 24576 + o, g_wlo + src, 16);
        }
        cp_commit();
    };

    auto compute = [&](int s) {
        uint32_t base = sb + s * STAGE_SZ;
#pragma unroll
        for (int ks = 0; ks < 2; ks++) {
            uint32_t fA[4][4];
#pragma unroll
            for (int mf = 0; mf < 4; mf++) {
                uint32_t r = wm + mf * 16 + (lane & 15);
                uint32_t kq = ks * 2 + (lane >> 4);
                uint32_t ad = base + swz(r, kq);
                ldsm4(fA[mf][0], fA[mf][1], fA[mf][2], fA[mf][3], ad);
            }
#pragma unroll
            for (int np = 0; np < 4; np++) {
                uint32_t r = wn + np * 16 + (lane & 7) + ((lane >> 4) << 3);
                uint32_t kq = ks * 2 + ((lane >> 3) & 1);
                uint32_t ad = base + 8192 + swz(r, kq);
                uint32_t bh0, bh1, bh2, bh3, bl0, bl1, bl2, bl3;
                ldsm4(bh0, bh1, bh2, bh3, ad);
                ldsm4(bl0, bl1, bl2, bl3, ad + 16384);
#pragma unroll
                for (int mf = 0; mf < 4; mf++) {
                    float* d0 = acc[mf][2 * np];
                    float* d1 = acc[mf][2 * np + 1];
                    mma_f16(d0, fA[mf], bh0, bh1);
                    mma_f16(d0, fA[mf], bl0, bl1);
                    mma_f16(d1, fA[mf], bh2, bh3);
                    mma_f16(d1, fA[mf], bl2, bl3);
                }
            }
        }
    };

    const int KT = 24;
    issue(0, 0);
    issue(1, 1);
#pragma unroll 1
    for (int kt = 0; kt < KT; kt++) {
        if (kt == KT - 1) cp_wait<0>(); else cp_wait<1>();
        __syncthreads();
        if (kt + 2 < KT) issue((kt + 2) % 3, kt + 2);
        compute(kt % 3);
    }

    // ---- LN + residual epilogue ----
#pragma unroll
    for (int mf = 0; mf < 4; mf++) {
#pragma unroll
        for (int rr = 0; rr < 2; rr++) {
            int rloc = wm + mf * 16 + (lane >> 2) + rr * 8;
            float s = 0.f, s2 = 0.f;
#pragma unroll
            for (int nf = 0; nf < 8; nf++) {
                float c0 = acc[mf][nf][rr * 2];
                float c1 = acc[mf][nf][rr * 2 + 1];
                s += c0 + c1; s2 += c0 * c0 + c1 * c1;
            }
            s  += __shfl_xor_sync(0xffffffffu, s, 1);
            s  += __shfl_xor_sync(0xffffffffu, s, 2);
            s2 += __shfl_xor_sync(0xffffffffu, s2, 1);
            s2 += __shfl_xor_sync(0xffffffffu, s2, 2);
            if ((lane & 3) == 0) {
                atomicAdd(&red[rloc * 2], s);
                atomicAdd(&red[rloc * 2 + 1], s2);
            }
        }
    }
    __syncthreads();

#pragma unroll
    for (int mf = 0; mf < 4; mf++) {
#pragma unroll
        for (int rr = 0; rr < 2; rr++) {
            int rloc = wm + mf * 16 + (lane >> 2) + rr * 8;
            int rg = row0 + rloc;
            float mean = red[rloc * 2] * (1.0f / 256.0f);
            float var  = red[rloc * 2 + 1] * (1.0f / 256.0f) - mean * mean;
            float inv  = rsqrtf(var + 1e-5f);
#pragma unroll
            for (int nf = 0; nf < 8; nf++) {
                int cloc = wn + nf * 8 + 2 * (lane & 3);
                float2 xv = *reinterpret_cast<const float2*>(
                    &x[(size_t)rg * 256 + cloc]);
                float c0 = acc[mf][nf][rr * 2];
                float c1 = acc[mf][nf][rr * 2 + 1];
                float o0 = xv.x + (c0 - mean) * inv * gam[cloc]     + bet[cloc];
                float o1 = xv.y + (c1 - mean) * inv * gam[cloc + 1] + bet[cloc + 1];
                *reinterpret_cast<float2*>(
                    &g_qkv[(size_t)rg * 768 + seg * 256 + cloc]) =
                    make_float2(o0, o1);
            }
        }
    }
}

// ---------------- proj GEMM (split-bf16 HMMA 3-pass, 128x256 tile, 3-stage) ----------------
#define PSTAGE_SZ 49152
#define SMEM_PROJ (3 * PSTAGE_SZ)

__global__ __launch_bounds__(256, 1)
void proj_gemm(const float* __restrict__ bo, float* __restrict__ outp) {
    extern __shared__ __align__(16) char smem[];
    const uint32_t sb = smem_u32(smem);

    int tid = threadIdx.x, lane = tid & 31, wid = tid >> 5;
    int row0 = blockIdx.x * 128;
    int wm = (wid >> 2) * 64;
    int wn = (wid & 3) * 64;

    float acc[4][8][4];
#pragma unroll
    for (int i = 0; i < 4; i++)
#pragma unroll
        for (int j = 0; j < 8; j++)
#pragma unroll
            for (int q = 0; q < 4; q++) acc[i][j][q] = 0.f;

    auto issue = [&](int s, int kt) {
        uint32_t stg = sb + s * PSTAGE_SZ;
        int k0 = kt * 32;
#pragma unroll
        for (int it = 0; it < 2; it++) {
            int f = it * 256 + tid;
            int r = f >> 2, kq = f & 3;
            size_t src = (size_t)(row0 + r) * 256 + k0 + kq * 8;
            uint32_t o = swz((uint32_t)r, (uint32_t)kq);
            cp16(stg + o, g_ahi + src, 16);
            cp16(stg + 8192 + o, g_alo + src, 16);
        }
#pragma unroll
        for (int it = 0; it < 4; it++) {
            int f = it * 256 + tid;
            int r = f >> 2, kq = f & 3;
            size_t src = (size_t)r * 256 + k0 + kq * 8;
            uint32_t o = swz((uint32_t)r, (uint32_t)kq);
            cp16(stg + 16384 + o, g_wohi + src, 16);
            cp16(stg + 32768 + o, g_wolo + src, 16);
        }
        cp_commit();
    };

    auto compute = [&](int s) {
        uint32_t base = sb + s * PSTAGE_SZ;
#pragma unroll
        for (int ks = 0; ks < 2; ks++) {
            uint32_t fAh[4][4], fAl[4][4];
#pragma unroll
            for (int mf = 0; mf < 4; mf++) {
                uint32_t r = wm + mf * 16 + (lane & 15);
                uint32_t kq = ks * 2 + (lane >> 4);
                uint32_t ad = base + swz(r, kq);
                ldsm4(fAh[mf][0], fAh[mf][1], fAh[mf][2], fAh[mf][3], ad);
                ldsm4(fAl[mf][0], fAl[mf][1], fAl[mf][2], fAl[mf][3], ad + 8192);
            }
#pragma unroll
            for (int np = 0; np < 4; np++) {
                uint32_t r = wn + np * 16 + (lane & 7) + ((lane >> 4) << 3);
                uint32_t kq = ks * 2 + ((lane >> 3) & 1);
                uint32_t ad = base + 16384 + swz(r, kq);
                uint32_t bh0, bh1, bh2, bh3, bl0, bl1, bl2, bl3;
                ldsm4(bh0, bh1, bh2, bh3, ad);
                ldsm4(bl0, bl1, bl2, bl3, ad + 16384);
#pragma unroll
                for (int mf = 0; mf < 4; mf++) {
                    float* d0 = acc[mf][2 * np];
                    float* d1 = acc[mf][2 * np + 1];
                    mma_bf16(d0, fAh[mf], bh0, bh1);
                    mma_bf16(d0, fAh[mf], bl0, bl1);
                    mma_bf16(d0, fAl[mf], bh0, bh1);
                    mma_bf16(d1, fAh[mf], bh2, bh3);
                    mma_bf16(d1, fAh[mf], bl2, bl3);
                    mma_bf16(d1, fAl[mf], bh2, bh3);
                }
            }
        }
    };

    const int KT = 8;
    issue(0, 0);
    issue(1, 1);
#pragma unroll 1
    for (int kt = 0; kt < KT; kt++) {
        if (kt == KT - 1) cp_wait<0>(); else cp_wait<1>();
        __syncthreads();
        if (kt + 2 < KT) issue((kt + 2) % 3, kt + 2);
        compute(kt % 3);
    }

#pragma unroll
    for (int mf = 0; mf < 4; mf++) {
        int row = row0 + wm + mf * 16 + (lane >> 2);
#pragma unroll
        for (int nf = 0; nf < 8; nf++) {
            int col = wn + nf * 8 + 2 * (lane & 3);
            float* d = acc[mf][nf];
            float b0 = bo[col], b1 = bo[col + 1];
            *reinterpret_cast<float2*>(&outp[(size_t)row * 256 + col]) =
                make_float2(d[0] + b0, d[1] + b1);
            *reinterpret_cast<float2*>(&outp[(size_t)(row + 8) * 256 + col]) =
                make_float2(d[2] + b0, d[3] + b1);
        }
    }
}

// ---------------- attention (warp per (b, head)), register-centric ----------------
__global__ __launch_bounds__(128)
void attn_kernel(const float* __restrict__ rel,
                 const float* __restrict__ gbias,
                 const float* __restrict__ alphap) {
    __shared__ float q_s[4][20][36];
    __shared__ float k_s[4][20][36];
    __shared__ float p_s[4][20][20];
    int lane = threadIdx.x & 31;
    int wid  = threadIdx.x >> 5;
    int h = blockIdx.y * 4 + wid;
    int b = blockIdx.x;
    float alpha = alphap[0];

    // stage q,k into smem (vectorized); v straight into registers (lane = dim)
    for (int idx = lane; idx < 160; idx += 32) {
        int n = idx >> 3, d4 = (idx & 7) << 2;
        size_t base = (size_t)(b * 20 + n) * 768 + h * 32 + d4;
        *reinterpret_cast<float4*>(&q_s[wid][n][d4]) =
            *reinterpret_cast<const float4*>(&g_qkv[base]);
        *reinterpret_cast<float4*>(&k_s[wid][n][d4]) =
            *reinterpret_cast<const float4*>(&g_qkv[base + 256]);
    }
    float vreg[20];
#pragma unroll
    for (int m2 = 0; m2 < 20; m2++)
        vreg[m2] = g_qkv[(size_t)(b * 20 + m2) * 768 + 512 + h * 32 + lane];
    __syncwarp();

    // scores + softmax in registers; lane = query row n (20 active)
    if (lane < 20) {
        int n = lane;
        float4 q4[8];
#pragma unroll
        for (int j = 0; j < 8; j++)
            q4[j] = *reinterpret_cast<const float4*>(&q_s[wid][n][4 * j]);
        float sc[20];
        const float* gb = &gbias[(h * 20 + n) * 20];
        float mx = -1e30f;
#pragma unroll
        for (int m2 = 0; m2 < 20; m2++) {
            float a = 0.f;
#pragma unroll
            for (int j = 0; j < 8; j++) {
                float4 k4 = *reinterpret_cast<const float4*>(&k_s[wid][m2][4 * j]);
                a += q4[j].x * k4.x + q4[j].y * k4.y +
                     q4[j].z * k4.z + q4[j].w * k4.w;
            }
            a = a * 0.17677669529663689f + __ldg(&rel[(n - m2 + 19) * 8 + h])
                + __ldg(&gb[m2]) * alpha;
            sc[m2] = a;
            mx = fmaxf(mx, a);
        }
        float ssum = 0.f;
#pragma unroll
        for (int m2 = 0; m2 < 20; m2++) {
            float e = __expf(sc[m2] - mx);
            sc[m2] = e; ssum += e;
        }
        float inv = 1.f / ssum;
#pragma unroll
        for (int j = 0; j < 5; j++) {
            float4 p4 = make_float4(sc[4 * j] * inv, sc[4 * j + 1] * inv,
                                    sc[4 * j + 2] * inv, sc[4 * j + 3] * inv);
            *reinterpret_cast<float4*>(&p_s[wid][n][4 * j]) = p4;
        }
    }
    __syncwarp();

    // AV: lane = dim d; p broadcast from smem, v in registers
#pragma unroll 1
    for (int n = 0; n < 20; n++) {
        float a = 0.f;
#pragma unroll
        for (int j = 0; j < 5; j++) {
            float4 p4 = *reinterpret_cast<const float4*>(&p_s[wid][n][4 * j]);
            a += p4.x * vreg[4 * j] + p4.y * vreg[4 * j + 1] +
                 p4.z * vreg[4 * j + 2] + p4.w * vreg[4 * j + 3];
        }
        size_t idx = (size_t)(b * 20 + n) * 256 + h * 32 + lane;
        __nv_bfloat16 hh = __float2bfloat16(a);
        g_ahi[idx] = hh;
        g_alo[idx] = __float2bfloat16(a - __bfloat162float(hh));
    }
}

// ---------------- launch ----------------
extern "C" void kernel_launch(void* const* d_in, const int* in_sizes, int n_in,
                              void* d_out, int out_size) {
    const float* x     = (const float*)d_in[0];
    const float* wq    = (const float*)d_in[1];
    const float* wk    = (const float*)d_in[2];
    const float* wv    = (const float*)d_in[3];
    const float* gq    = (const float*)d_in[4];
    const float* bq    = (const float*)d_in[5];
    const float* gk    = (const float*)d_in[6];
    const float* bk    = (const float*)d_in[7];
    const float* gv    = (const float*)d_in[8];
    const float* bv    = (const float*)d_in[9];
    const float* rel   = (const float*)d_in[10];
    const float* gbias = (const float*)d_in[11];
    const float* alpha = (const float*)d_in[12];
    const float* wo    = (const float*)d_in[13];
    const float* bo    = (const float*)d_in[14];
    float* out = (float*)d_out;

    int B = in_sizes[0] / (N_NODES * D_MODEL);
    int M = B * N_NODES;

    cudaFuncSetAttribute(conv_ln_kernel,
                         cudaFuncAttributeMaxDynamicSharedMemorySize, SMEM_CONV);
    cudaFuncSetAttribute(proj_gemm,
                         cudaFuncAttributeMaxDynamicSharedMemorySize, SMEM_PROJ);

    prep_w<<<(768 * 768 + 255) / 256, 256>>>(wq, wk, wv, wo);
    prep_x<<<(M * 64 + 255) / 256, 256>>>(x, M * 64);

    conv_ln_kernel<<<dim3(3, M / 128), 256, SMEM_CONV>>>(
        x, gq, bq, gk, bk, gv, bv);

    attn_kernel<<<dim3(B, 2), 128>>>(rel, gbias, alpha);

    proj_gemm<<<M / 128, 256, SMEM_PROJ>>>(bo, out);
}

// round 7
// speedup vs baseline: 4.1450x; 1.4082x over previous
#include <cuda_runtime.h>
#include <cuda_bf16.h>
#include <cuda_fp16.h>
#include <cstdint>

#define D_MODEL 256
#define N_NODES 20
#define N_HEADS 8
#define BMAX    8192
#define MMAX    (BMAX * N_NODES)   // 163840 rows

// ---------------- scratch (device globals: allocation-free) ----------------
__device__ __half g_xh[(size_t)MMAX * 256];     // x as fp16
__device__ __half g_wh[768 * 768];              // conv weights fp16 [o][j=t*256+i]
__device__ __half g_woh[256 * 256];             // wo fp16 [o][i]
__device__ float g_qkv [(size_t)MMAX * 768];    // q|k|v after LN+residual
__device__ __half g_ah[(size_t)MMAX * 256];     // attn out fp16

// ---------------- warp-MMA helpers (baseline PTX: sm_80+) ----------------
__device__ __forceinline__ uint32_t smem_u32(const void* p) {
    uint32_t a;
    asm("{ .reg .u64 t; cvta.to.shared.u64 t, %1; cvt.u32.u64 %0, t; }"
        : "=r"(a) : "l"(p));
    return a;
}
__device__ __forceinline__ void ldsm4(uint32_t& r0, uint32_t& r1,
                                      uint32_t& r2, uint32_t& r3, uint32_t addr) {
    asm volatile("ldmatrix.sync.aligned.m8n8.x4.shared.b16 {%0,%1,%2,%3}, [%4];"
                 : "=r"(r0), "=r"(r1), "=r"(r2), "=r"(r3) : "r"(addr));
}
__device__ __forceinline__ void mma_f16(float* d,
                                        const uint32_t* a,
                                        uint32_t b0, uint32_t b1) {
    asm volatile(
        "mma.sync.aligned.m16n8k16.row.col.f32.f16.f16.f32 "
        "{%0,%1,%2,%3}, {%4,%5,%6,%7}, {%8,%9}, {%0,%1,%2,%3};"
        : "+f"(d[0]), "+f"(d[1]), "+f"(d[2]), "+f"(d[3])
        : "r"(a[0]), "r"(a[1]), "r"(a[2]), "r"(a[3]), "r"(b0), "r"(b1));
}
__device__ __forceinline__ uint32_t swz(uint32_t r, uint32_t kq) {
    return r * 64 + ((kq ^ ((r >> 1) & 3)) * 16);
}
__device__ __forceinline__ void cp16(uint32_t dst, const void* src, int srcsz) {
    asm volatile("cp.async.cg.shared.global [%0], [%1], 16, %2;"
                 :: "r"(dst), "l"(__cvta_generic_to_global(src)), "r"(srcsz)
                 : "memory");
}
__device__ __forceinline__ void cp_commit() {
    asm volatile("cp.async.commit_group;" ::: "memory");
}
template<int N>
__device__ __forceinline__ void cp_wait() {
    asm volatile("cp.async.wait_group %0;" :: "n"(N) : "memory");
}

// ---------------- prep kernels ----------------
__global__ void prep_w(const float* __restrict__ wq, const float* __restrict__ wk,
                       const float* __restrict__ wv, const float* __restrict__ wo) {
    int idx = blockIdx.x * blockDim.x + threadIdx.x;
    if (idx < 768 * 768) {
        int o = idx / 768, j = idx % 768;
        int t = j >> 8, i = j & 255;
        const float* w = (o < 256) ? wq : (o < 512) ? wk : wv;
        int oc = o & 255;
        g_wh[idx] = __float2half(w[(oc * 256 + i) * 3 + t]);
    }
    if (idx < 256 * 256) {
        g_woh[idx] = __float2half(wo[idx]);
    }
}
__global__ void prep_x(const float* __restrict__ x, int total4) {
    int i = blockIdx.x * blockDim.x + threadIdx.x;
    if (i < total4) {
        float4 v = reinterpret_cast<const float4*>(x)[i];
        __half2 h0, h1;
        h0.x = __float2half(v.x); h0.y = __float2half(v.y);
        h1.x = __float2half(v.z); h1.y = __float2half(v.w);
        reinterpret_cast<__half2*>(g_xh)[i * 2]     = h0;
        reinterpret_cast<__half2*>(g_xh)[i * 2 + 1] = h1;
    }
}

// ---------------- fused conv GEMM + LayerNorm + residual ----------------
// Per block: 128 rows x 256 cols (one q/k/v segment, seg = blockIdx.x).
// Single-pass fp16 HMMA. cp.async 3-stage pipeline.
// Stage: A 8K | B 16K = 24K
#define STAGE_SZ 24576
#define SMEM_CONV (3 * STAGE_SZ + 1024 + 2048)

__global__ __launch_bounds__(256, 1)
void conv_ln_kernel(const float* __restrict__ x,
                    const float* __restrict__ gq, const float* __restrict__ bq,
                    const float* __restrict__ gk, const float* __restrict__ bk,
                    const float* __restrict__ gv, const float* __restrict__ bv) {
    extern __shared__ __align__(16) char smem[];
    const uint32_t sb = smem_u32(smem);
    float* red = reinterpret_cast<float*>(smem + 3 * STAGE_SZ);        // [128][2]
    float* gam = reinterpret_cast<float*>(smem + 3 * STAGE_SZ + 1024); // [256]
    float* bet = reinterpret_cast<float*>(smem + 3 * STAGE_SZ + 2048); // [256]

    int tid = threadIdx.x, lane = tid & 31, wid = tid >> 5;
    int seg = blockIdx.x;              // 0=q 1=k 2=v
    int row0 = blockIdx.y * 128;
    int wm = (wid >> 2) * 64;
    int wn = (wid & 3) * 64;

    {
        const float* gsel = (seg == 0) ? gq : (seg == 1) ? gk : gv;
        const float* bsel = (seg == 0) ? bq : (seg == 1) ? bk : bv;
        gam[tid] = gsel[tid];
        bet[tid] = bsel[tid];
        red[tid] = 0.f;
    }

    float acc[4][8][4];
#pragma unroll
    for (int i = 0; i < 4; i++)
#pragma unroll
        for (int j = 0; j < 8; j++)
#pragma unroll
            for (int q = 0; q < 4; q++) acc[i][j][q] = 0.f;

    auto issue = [&](int s, int kt) {
        uint32_t stg = sb + s * STAGE_SZ;
        int k0 = kt * 32;
        int t = kt >> 3;
        int dbase = (kt & 7) * 32;
        // A: 128 rows x 32 fp16 = 8KB
#pragma unroll
        for (int it = 0; it < 2; it++) {
            int f = it * 256 + tid;
            int r = f >> 2, kq = f & 3;
            int m = row0 + r;
            int n = m % N_NODES;
            int ns = n + t - 1;
            int ok = ((unsigned)ns < (unsigned)N_NODES);
            size_t src = (size_t)(ok ? (m + t - 1) : m) * 256 + dbase + kq * 8;
            int sz = ok ? 16 : 0;
            cp16(stg + swz((uint32_t)r, (uint32_t)kq), g_xh + src, sz);
        }
        // B: 256 rows x 32 fp16 = 16KB
#pragma unroll
        for (int it = 0; it < 4; it++) {
            int f = it * 256 + tid;
            int r = f >> 2, kq = f & 3;
            size_t src = (size_t)(seg * 256 + r) * 768 + k0 + kq * 8;
            cp16(stg + 8192 + swz((uint32_t)r, (uint32_t)kq), g_wh + src, 16);
        }
        cp_commit();
    };

    auto compute = [&](int s) {
        uint32_t base = sb + s * STAGE_SZ;
#pragma unroll
        for (int ks = 0; ks < 2; ks++) {
            uint32_t fA[4][4];
#pragma unroll
            for (int mf = 0; mf < 4; mf++) {
                uint32_t r = wm + mf * 16 + (lane & 15);
                uint32_t kq = ks * 2 + (lane >> 4);
                uint32_t ad = base + swz(r, kq);
                ldsm4(fA[mf][0], fA[mf][1], fA[mf][2], fA[mf][3], ad);
            }
#pragma unroll
            for (int np = 0; np < 4; np++) {
                uint32_t r = wn + np * 16 + (lane & 7) + ((lane >> 4) << 3);
                uint32_t kq = ks * 2 + ((lane >> 3) & 1);
                uint32_t ad = base + 8192 + swz(r, kq);
                uint32_t b0, b1, b2, b3;
                ldsm4(b0, b1, b2, b3, ad);
#pragma unroll
                for (int mf = 0; mf < 4; mf++) {
                    mma_f16(acc[mf][2 * np],     fA[mf], b0, b1);
                    mma_f16(acc[mf][2 * np + 1], fA[mf], b2, b3);
                }
            }
        }
    };

    const int KT = 24;
    issue(0, 0);
    issue(1, 1);
#pragma unroll 1
    for (int kt = 0; kt < KT; kt++) {
        if (kt == KT - 1) cp_wait<0>(); else cp_wait<1>();
        __syncthreads();
        if (kt + 2 < KT) issue((kt + 2) % 3, kt + 2);
        compute(kt % 3);
    }

    // ---- LN + residual epilogue ----
#pragma unroll
    for (int mf = 0; mf < 4; mf++) {
#pragma unroll
        for (int rr = 0; rr < 2; rr++) {
            int rloc = wm + mf * 16 + (lane >> 2) + rr * 8;
            float s = 0.f, s2 = 0.f;
#pragma unroll
            for (int nf = 0; nf < 8; nf++) {
                float c0 = acc[mf][nf][rr * 2];
                float c1 = acc[mf][nf][rr * 2 + 1];
                s += c0 + c1; s2 += c0 * c0 + c1 * c1;
            }
            s  += __shfl_xor_sync(0xffffffffu, s, 1);
            s  += __shfl_xor_sync(0xffffffffu, s, 2);
            s2 += __shfl_xor_sync(0xffffffffu, s2, 1);
            s2 += __shfl_xor_sync(0xffffffffu, s2, 2);
            if ((lane & 3) == 0) {
                atomicAdd(&red[rloc * 2], s);
                atomicAdd(&red[rloc * 2 + 1], s2);
            }
        }
    }
    __syncthreads();

#pragma unroll
    for (int mf = 0; mf < 4; mf++) {
#pragma unroll
        for (int rr = 0; rr < 2; rr++) {
            int rloc = wm + mf * 16 + (lane >> 2) + rr * 8;
            int rg = row0 + rloc;
            float mean = red[rloc * 2] * (1.0f / 256.0f);
            float var  = red[rloc * 2 + 1] * (1.0f / 256.0f) - mean * mean;
            float inv  = rsqrtf(var + 1e-5f);
#pragma unroll
            for (int nf = 0; nf < 8; nf++) {
                int cloc = wn + nf * 8 + 2 * (lane & 3);
                float2 xv = *reinterpret_cast<const float2*>(
                    &x[(size_t)rg * 256 + cloc]);
                float c0 = acc[mf][nf][rr * 2];
                float c1 = acc[mf][nf][rr * 2 + 1];
                float o0 = xv.x + (c0 - mean) * inv * gam[cloc]     + bet[cloc];
                float o1 = xv.y + (c1 - mean) * inv * gam[cloc + 1] + bet[cloc + 1];
                *reinterpret_cast<float2*>(
                    &g_qkv[(size_t)rg * 768 + seg * 256 + cloc]) =
                    make_float2(o0, o1);
            }
        }
    }
}

// ---------------- proj GEMM (single-pass fp16, 128x256 tile, 3-stage) ----------------
#define SMEM_PROJ (3 * STAGE_SZ)

__global__ __launch_bounds__(256, 1)
void proj_gemm(const float* __restrict__ bo, float* __restrict__ outp) {
    extern __shared__ __align__(16) char smem[];
    const uint32_t sb = smem_u32(smem);

    int tid = threadIdx.x, lane = tid & 31, wid = tid >> 5;
    int row0 = blockIdx.x * 128;
    int wm = (wid >> 2) * 64;
    int wn = (wid & 3) * 64;

    float acc[4][8][4];
#pragma unroll
    for (int i = 0; i < 4; i++)
#pragma unroll
        for (int j = 0; j < 8; j++)
#pragma unroll
            for (int q = 0; q < 4; q++) acc[i][j][q] = 0.f;

    auto issue = [&](int s, int kt) {
        uint32_t stg = sb + s * STAGE_SZ;
        int k0 = kt * 32;
#pragma unroll
        for (int it = 0; it < 2; it++) {
            int f = it * 256 + tid;
            int r = f >> 2, kq = f & 3;
            size_t src = (size_t)(row0 + r) * 256 + k0 + kq * 8;
            cp16(stg + swz((uint32_t)r, (uint32_t)kq), g_ah + src, 16);
        }
#pragma unroll
        for (int it = 0; it < 4; it++) {
            int f = it * 256 + tid;
            int r = f >> 2, kq = f & 3;
            size_t src = (size_t)r * 256 + k0 + kq * 8;
            cp16(stg + 8192 + swz((uint32_t)r, (uint32_t)kq), g_woh + src, 16);
        }
        cp_commit();
    };

    auto compute = [&](int s) {
        uint32_t base = sb + s * STAGE_SZ;
#pragma unroll
        for (int ks = 0; ks < 2; ks++) {
            uint32_t fA[4][4];
#pragma unroll
            for (int mf = 0; mf < 4; mf++) {
                uint32_t r = wm + mf * 16 + (lane & 15);
                uint32_t kq = ks * 2 + (lane >> 4);
                uint32_t ad = base + swz(r, kq);
                ldsm4(fA[mf][0], fA[mf][1], fA[mf][2], fA[mf][3], ad);
            }
#pragma unroll
            for (int np = 0; np < 4; np++) {
                uint32_t r = wn + np * 16 + (lane & 7) + ((lane >> 4) << 3);
                uint32_t kq = ks * 2 + ((lane >> 3) & 1);
                uint32_t ad = base + 8192 + swz(r, kq);
                uint32_t b0, b1, b2, b3;
                ldsm4(b0, b1, b2, b3, ad);
#pragma unroll
                for (int mf = 0; mf < 4; mf++) {
                    mma_f16(acc[mf][2 * np],     fA[mf], b0, b1);
                    mma_f16(acc[mf][2 * np + 1], fA[mf], b2, b3);
                }
            }
        }
    };

    const int KT = 8;
    issue(0, 0);
    issue(1, 1);
#pragma unroll 1
    for (int kt = 0; kt < KT; kt++) {
        if (kt == KT - 1) cp_wait<0>(); else cp_wait<1>();
        __syncthreads();
        if (kt + 2 < KT) issue((kt + 2) % 3, kt + 2);
        compute(kt % 3);
    }

#pragma unroll
    for (int mf = 0; mf < 4; mf++) {
        int row = row0 + wm + mf * 16 + (lane >> 2);
#pragma unroll
        for (int nf = 0; nf < 8; nf++) {
            int col = wn + nf * 8 + 2 * (lane & 3);
            float* d = acc[mf][nf];
            float b0 = bo[col], b1 = bo[col + 1];
            *reinterpret_cast<float2*>(&outp[(size_t)row * 256 + col]) =
                make_float2(d[0] + b0, d[1] + b1);
            *reinterpret_cast<float2*>(&outp[(size_t)(row + 8) * 256 + col]) =
                make_float2(d[2] + b0, d[3] + b1);
        }
    }
}

// ---------------- attention (warp per (b, head)), register-centric ----------------
__global__ __launch_bounds__(128)
void attn_kernel(const float* __restrict__ rel,
                 const float* __restrict__ gbias,
                 const float* __restrict__ alphap) {
    __shared__ float q_s[4][20][36];
    __shared__ float k_s[4][20][36];
    __shared__ float p_s[4][20][20];
    int lane = threadIdx.x & 31;
    int wid  = threadIdx.x >> 5;
    int h = blockIdx.y * 4 + wid;
    int b = blockIdx.x;
    float alpha = alphap[0];

    // stage q,k into smem (vectorized); v straight into registers (lane = dim)
    for (int idx = lane; idx < 160; idx += 32) {
        int n = idx >> 3, d4 = (idx & 7) << 2;
        size_t base = (size_t)(b * 20 + n) * 768 + h * 32 + d4;
        *reinterpret_cast<float4*>(&q_s[wid][n][d4]) =
            *reinterpret_cast<const float4*>(&g_qkv[base]);
        *reinterpret_cast<float4*>(&k_s[wid][n][d4]) =
            *reinterpret_cast<const float4*>(&g_qkv[base + 256]);
    }
    float vreg[20];
#pragma unroll
    for (int m2 = 0; m2 < 20; m2++)
        vreg[m2] = g_qkv[(size_t)(b * 20 + m2) * 768 + 512 + h * 32 + lane];
    __syncwarp();

    // scores + softmax in registers; lane = query row n (20 active)
    if (lane < 20) {
        int n = lane;
        float4 q4[8];
#pragma unroll
        for (int j = 0; j < 8; j++)
            q4[j] = *reinterpret_cast<const float4*>(&q_s[wid][n][4 * j]);
        float sc[20];
        const float* gb = &gbias[(h * 20 + n) * 20];
        float mx = -1e30f;
#pragma unroll
        for (int m2 = 0; m2 < 20; m2++) {
            float a = 0.f;
#pragma unroll
            for (int j = 0; j < 8; j++) {
                float4 k4 = *reinterpret_cast<const float4*>(&k_s[wid][m2][4 * j]);
                a += q4[j].x * k4.x + q4[j].y * k4.y +
                     q4[j].z * k4.z + q4[j].w * k4.w;
            }
            a = a * 0.17677669529663689f + __ldg(&rel[(n - m2 + 19) * 8 + h])
                + __ldg(&gb[m2]) * alpha;
            sc[m2] = a;
            mx = fmaxf(mx, a);
        }
        float ssum = 0.f;
#pragma unroll
        for (int m2 = 0; m2 < 20; m2++) {
            float e = __expf(sc[m2] - mx);
            sc[m2] = e; ssum += e;
        }
        float inv = 1.f / ssum;
#pragma unroll
        for (int j = 0; j < 5; j++) {
            float4 p4 = make_float4(sc[4 * j] * inv, sc[4 * j + 1] * inv,
                                    sc[4 * j + 2] * inv, sc[4 * j + 3] * inv);
            *reinterpret_cast<float4*>(&p_s[wid][n][4 * j]) = p4;
        }
    }
    __syncwarp();

    // AV: lane = dim d; p broadcast from smem, v in registers
#pragma unroll 1
    for (int n = 0; n < 20; n++) {
        float a = 0.f;
#pragma unroll
        for (int j = 0; j < 5; j++) {
            float4 p4 = *reinterpret_cast<const float4*>(&p_s[wid][n][4 * j]);
            a += p4.x * vreg[4 * j] + p4.y * vreg[4 * j + 1] +
                 p4.z * vreg[4 * j + 2] + p4.w * vreg[4 * j + 3];
        }
        g_ah[(size_t)(b * 20 + n) * 256 + h * 32 + lane] = __float2half(a);
    }
}

// ---------------- launch ----------------
extern "C" void kernel_launch(void* const* d_in, const int* in_sizes, int n_in,
                              void* d_out, int out_size) {
    const float* x     = (const float*)d_in[0];
    const float* wq    = (const float*)d_in[1];
    const float* wk    = (const float*)d_in[2];
    const float* wv    = (const float*)d_in[3];
    const float* gq    = (const float*)d_in[4];
    const float* bq    = (const float*)d_in[5];
    const float* gk    = (const float*)d_in[6];
    const float* bk    = (const float*)d_in[7];
    const float* gv    = (const float*)d_in[8];
    const float* bv    = (const float*)d_in[9];
    const float* rel   = (const float*)d_in[10];
    const float* gbias = (const float*)d_in[11];
    const float* alpha = (const float*)d_in[12];
    const float* wo    = (const float*)d_in[13];
    const float* bo    = (const float*)d_in[14];
    float* out = (float*)d_out;

    int B = in_sizes[0] / (N_NODES * D_MODEL);
    int M = B * N_NODES;

    cudaFuncSetAttribute(conv_ln_kernel,
                         cudaFuncAttributeMaxDynamicSharedMemorySize, SMEM_CONV);
    cudaFuncSetAttribute(proj_gemm,
                         cudaFuncAttributeMaxDynamicSharedMemorySize, SMEM_PROJ);

    prep_w<<<(768 * 768 + 255) / 256, 256>>>(wq, wk, wv, wo);
    prep_x<<<(M * 64 + 255) / 256, 256>>>(x, M * 64);

    conv_ln_kernel<<<dim3(3, M / 128), 256, SMEM_CONV>>>(
        x, gq, bq, gk, bk, gv, bv);

    attn_kernel<<<dim3(B, 2), 128>>>(rel, gbias, alpha);

    proj_gemm<<<M / 128, 256, SMEM_PROJ>>>(bo, out);
}

// round 8
// speedup vs baseline: 4.1819x; 1.0089x over previous
#include <cuda_runtime.h>
#include <cuda_bf16.h>
#include <cuda_fp16.h>
#include <cstdint>

#define D_MODEL 256
#define N_NODES 20
#define N_HEADS 8
#define BMAX    8192
#define MMAX    (BMAX * N_NODES)   // 163840 rows

// ---------------- scratch (device globals: allocation-free) ----------------
__device__ __half g_xh[(size_t)MMAX * 256];     // x as fp16
__device__ __half g_wh[768 * 768];              // conv weights fp16 [o][j=t*256+i]
__device__ __half g_woh[256 * 256];             // wo fp16 [o][i]
__device__ __half g_qkvh[(size_t)MMAX * 768];   // q|k|v after LN+residual (fp16)
__device__ __half g_ah[(size_t)MMAX * 256];     // attn out fp16

// ---------------- warp-MMA helpers (baseline PTX: sm_80+) ----------------
__device__ __forceinline__ uint32_t smem_u32(const void* p) {
    uint32_t a;
    asm("{ .reg .u64 t; cvta.to.shared.u64 t, %1; cvt.u32.u64 %0, t; }"
        : "=r"(a) : "l"(p));
    return a;
}
__device__ __forceinline__ void ldsm4(uint32_t& r0, uint32_t& r1,
                                      uint32_t& r2, uint32_t& r3, uint32_t addr) {
    asm volatile("ldmatrix.sync.aligned.m8n8.x4.shared.b16 {%0,%1,%2,%3}, [%4];"
                 : "=r"(r0), "=r"(r1), "=r"(r2), "=r"(r3) : "r"(addr));
}
__device__ __forceinline__ void mma_f16(float* d,
                                        const uint32_t* a,
                                        uint32_t b0, uint32_t b1) {
    asm volatile(
        "mma.sync.aligned.m16n8k16.row.col.f32.f16.f16.f32 "
        "{%0,%1,%2,%3}, {%4,%5,%6,%7}, {%8,%9}, {%0,%1,%2,%3};"
        : "+f"(d[0]), "+f"(d[1]), "+f"(d[2]), "+f"(d[3])
        : "r"(a[0]), "r"(a[1]), "r"(a[2]), "r"(a[3]), "r"(b0), "r"(b1));
}
__device__ __forceinline__ uint32_t swz(uint32_t r, uint32_t kq) {
    return r * 64 + ((kq ^ ((r >> 1) & 3)) * 16);
}
__device__ __forceinline__ void cp16(uint32_t dst, const void* src, int srcsz) {
    asm volatile("cp.async.cg.shared.global [%0], [%1], 16, %2;"
                 :: "r"(dst), "l"(__cvta_generic_to_global(src)), "r"(srcsz)
                 : "memory");
}
__device__ __forceinline__ void cp_commit() {
    asm volatile("cp.async.commit_group;" ::: "memory");
}
template<int N>
__device__ __forceinline__ void cp_wait() {
    asm volatile("cp.async.wait_group %0;" :: "n"(N) : "memory");
}

// ---------------- prep kernels ----------------
__global__ void prep_w(const float* __restrict__ wq, const float* __restrict__ wk,
                       const float* __restrict__ wv, const float* __restrict__ wo) {
    int idx = blockIdx.x * blockDim.x + threadIdx.x;
    if (idx < 768 * 768) {
        int o = idx / 768, j = idx % 768;
        int t = j >> 8, i = j & 255;
        const float* w = (o < 256) ? wq : (o < 512) ? wk : wv;
        int oc = o & 255;
        g_wh[idx] = __float2half(w[(oc * 256 + i) * 3 + t]);
    }
    if (idx < 256 * 256) {
        g_woh[idx] = __float2half(wo[idx]);
    }
}
__global__ void prep_x(const float* __restrict__ x, int total4) {
    int i = blockIdx.x * blockDim.x + threadIdx.x;
    if (i < total4) {
        float4 v = reinterpret_cast<const float4*>(x)[i];
        __half2 h0, h1;
        h0.x = __float2half(v.x); h0.y = __float2half(v.y);
        h1.x = __float2half(v.z); h1.y = __float2half(v.w);
        reinterpret_cast<__half2*>(g_xh)[i * 2]     = h0;
        reinterpret_cast<__half2*>(g_xh)[i * 2 + 1] = h1;
    }
}

// ---------------- fused conv GEMM + LayerNorm + residual ----------------
// Per block: 128 rows x 256 cols (one q/k/v segment, seg = blockIdx.x).
// Single-pass fp16 HMMA. cp.async 3-stage pipeline. fp16 output.
#define STAGE_SZ 24576
#define SMEM_CONV (3 * STAGE_SZ + 1024 + 2048)

__global__ __launch_bounds__(256, 1)
void conv_ln_kernel(const float* __restrict__ x,
                    const float* __restrict__ gq, const float* __restrict__ bq,
                    const float* __restrict__ gk, const float* __restrict__ bk,
                    const float* __restrict__ gv, const float* __restrict__ bv) {
    extern __shared__ __align__(16) char smem[];
    const uint32_t sb = smem_u32(smem);
    float* red = reinterpret_cast<float*>(smem + 3 * STAGE_SZ);        // [128][2]
    float* gam = reinterpret_cast<float*>(smem + 3 * STAGE_SZ + 1024); // [256]
    float* bet = reinterpret_cast<float*>(smem + 3 * STAGE_SZ + 2048); // [256]

    int tid = threadIdx.x, lane = tid & 31, wid = tid >> 5;
    int seg = blockIdx.x;              // 0=q 1=k 2=v
    int row0 = blockIdx.y * 128;
    int wm = (wid >> 2) * 64;
    int wn = (wid & 3) * 64;

    {
        const float* gsel = (seg == 0) ? gq : (seg == 1) ? gk : gv;
        const float* bsel = (seg == 0) ? bq : (seg == 1) ? bk : bv;
        gam[tid] = gsel[tid];
        bet[tid] = bsel[tid];
        red[tid] = 0.f;
    }

    float acc[4][8][4];
#pragma unroll
    for (int i = 0; i < 4; i++)
#pragma unroll
        for (int j = 0; j < 8; j++)
#pragma unroll
            for (int q = 0; q < 4; q++) acc[i][j][q] = 0.f;

    auto issue = [&](int s, int kt) {
        uint32_t stg = sb + s * STAGE_SZ;
        int k0 = kt * 32;
        int t = kt >> 3;
        int dbase = (kt & 7) * 32;
#pragma unroll
        for (int it = 0; it < 2; it++) {
            int f = it * 256 + tid;
            int r = f >> 2, kq = f & 3;
            int m = row0 + r;
            int n = m % N_NODES;
            int ns = n + t - 1;
            int ok = ((unsigned)ns < (unsigned)N_NODES);
            size_t src = (size_t)(ok ? (m + t - 1) : m) * 256 + dbase + kq * 8;
            int sz = ok ? 16 : 0;
            cp16(stg + swz((uint32_t)r, (uint32_t)kq), g_xh + src, sz);
        }
#pragma unroll
        for (int it = 0; it < 4; it++) {
            int f = it * 256 + tid;
            int r = f >> 2, kq = f & 3;
            size_t src = (size_t)(seg * 256 + r) * 768 + k0 + kq * 8;
            cp16(stg + 8192 + swz((uint32_t)r, (uint32_t)kq), g_wh + src, 16);
        }
        cp_commit();
    };

    auto compute = [&](int s) {
        uint32_t base = sb + s * STAGE_SZ;
#pragma unroll
        for (int ks = 0; ks < 2; ks++) {
            uint32_t fA[4][4];
#pragma unroll
            for (int mf = 0; mf < 4; mf++) {
                uint32_t r = wm + mf * 16 + (lane & 15);
                uint32_t kq = ks * 2 + (lane >> 4);
                uint32_t ad = base + swz(r, kq);
                ldsm4(fA[mf][0], fA[mf][1], fA[mf][2], fA[mf][3], ad);
            }
#pragma unroll
            for (int np = 0; np < 4; np++) {
                uint32_t r = wn + np * 16 + (lane & 7) + ((lane >> 4) << 3);
                uint32_t kq = ks * 2 + ((lane >> 3) & 1);
                uint32_t ad = base + 8192 + swz(r, kq);
                uint32_t b0, b1, b2, b3;
                ldsm4(b0, b1, b2, b3, ad);
#pragma unroll
                for (int mf = 0; mf < 4; mf++) {
                    mma_f16(acc[mf][2 * np],     fA[mf], b0, b1);
                    mma_f16(acc[mf][2 * np + 1], fA[mf], b2, b3);
                }
            }
        }
    };

    const int KT = 24;
    issue(0, 0);
    issue(1, 1);
#pragma unroll 1
    for (int kt = 0; kt < KT; kt++) {
        if (kt == KT - 1) cp_wait<0>(); else cp_wait<1>();
        __syncthreads();
        if (kt + 2 < KT) issue((kt + 2) % 3, kt + 2);
        compute(kt % 3);
    }

    // ---- LN + residual epilogue (fp16 output) ----
#pragma unroll
    for (int mf = 0; mf < 4; mf++) {
#pragma unroll
        for (int rr = 0; rr < 2; rr++) {
            int rloc = wm + mf * 16 + (lane >> 2) + rr * 8;
            float s = 0.f, s2 = 0.f;
#pragma unroll
            for (int nf = 0; nf < 8; nf++) {
                float c0 = acc[mf][nf][rr * 2];
                float c1 = acc[mf][nf][rr * 2 + 1];
                s += c0 + c1; s2 += c0 * c0 + c1 * c1;
            }
            s  += __shfl_xor_sync(0xffffffffu, s, 1);
            s  += __shfl_xor_sync(0xffffffffu, s, 2);
            s2 += __shfl_xor_sync(0xffffffffu, s2, 1);
            s2 += __shfl_xor_sync(0xffffffffu, s2, 2);
            if ((lane & 3) == 0) {
                atomicAdd(&red[rloc * 2], s);
                atomicAdd(&red[rloc * 2 + 1], s2);
            }
        }
    }
    __syncthreads();

#pragma unroll
    for (int mf = 0; mf < 4; mf++) {
#pragma unroll
        for (int rr = 0; rr < 2; rr++) {
            int rloc = wm + mf * 16 + (lane >> 2) + rr * 8;
            int rg = row0 + rloc;
            float mean = red[rloc * 2] * (1.0f / 256.0f);
            float var  = red[rloc * 2 + 1] * (1.0f / 256.0f) - mean * mean;
            float inv  = rsqrtf(var + 1e-5f);
#pragma unroll
            for (int nf = 0; nf < 8; nf++) {
                int cloc = wn + nf * 8 + 2 * (lane & 3);
                float2 xv = *reinterpret_cast<const float2*>(
                    &x[(size_t)rg * 256 + cloc]);
                float c0 = acc[mf][nf][rr * 2];
                float c1 = acc[mf][nf][rr * 2 + 1];
                float o0 = xv.x + (c0 - mean) * inv * gam[cloc]     + bet[cloc];
                float o1 = xv.y + (c1 - mean) * inv * gam[cloc + 1] + bet[cloc + 1];
                *reinterpret_cast<__half2*>(
                    &g_qkvh[(size_t)rg * 768 + seg * 256 + cloc]) =
                    __floats2half2_rn(o0, o1);
            }
        }
    }
}

// ---------------- proj GEMM (single-pass fp16, 128x256 tile, 3-stage) ----------------
#define SMEM_PROJ (3 * STAGE_SZ)

__global__ __launch_bounds__(256, 1)
void proj_gemm(const float* __restrict__ bo, float* __restrict__ outp) {
    extern __shared__ __align__(16) char smem[];
    const uint32_t sb = smem_u32(smem);

    int tid = threadIdx.x, lane = tid & 31, wid = tid >> 5;
    int row0 = blockIdx.x * 128;
    int wm = (wid >> 2) * 64;
    int wn = (wid & 3) * 64;

    float acc[4][8][4];
#pragma unroll
    for (int i = 0; i < 4; i++)
#pragma unroll
        for (int j = 0; j < 8; j++)
#pragma unroll
            for (int q = 0; q < 4; q++) acc[i][j][q] = 0.f;

    auto issue = [&](int s, int kt) {
        uint32_t stg = sb + s * STAGE_SZ;
        int k0 = kt * 32;
#pragma unroll
        for (int it = 0; it < 2; it++) {
            int f = it * 256 + tid;
            int r = f >> 2, kq = f & 3;
            size_t src = (size_t)(row0 + r) * 256 + k0 + kq * 8;
            cp16(stg + swz((uint32_t)r, (uint32_t)kq), g_ah + src, 16);
        }
#pragma unroll
        for (int it = 0; it < 4; it++) {
            int f = it * 256 + tid;
            int r = f >> 2, kq = f & 3;
            size_t src = (size_t)r * 256 + k0 + kq * 8;
            cp16(stg + 8192 + swz((uint32_t)r, (uint32_t)kq), g_woh + src, 16);
        }
        cp_commit();
    };

    auto compute = [&](int s) {
        uint32_t base = sb + s * STAGE_SZ;
#pragma unroll
        for (int ks = 0; ks < 2; ks++) {
            uint32_t fA[4][4];
#pragma unroll
            for (int mf = 0; mf < 4; mf++) {
                uint32_t r = wm + mf * 16 + (lane & 15);
                uint32_t kq = ks * 2 + (lane >> 4);
                uint32_t ad = base + swz(r, kq);
                ldsm4(fA[mf][0], fA[mf][1], fA[mf][2], fA[mf][3], ad);
            }
#pragma unroll
            for (int np = 0; np < 4; np++) {
                uint32_t r = wn + np * 16 + (lane & 7) + ((lane >> 4) << 3);
                uint32_t kq = ks * 2 + ((lane >> 3) & 1);
                uint32_t ad = base + 8192 + swz(r, kq);
                uint32_t b0, b1, b2, b3;
                ldsm4(b0, b1, b2, b3, ad);
#pragma unroll
                for (int mf = 0; mf < 4; mf++) {
                    mma_f16(acc[mf][2 * np],     fA[mf], b0, b1);
                    mma_f16(acc[mf][2 * np + 1], fA[mf], b2, b3);
                }
            }
        }
    };

    const int KT = 8;
    issue(0, 0);
    issue(1, 1);
#pragma unroll 1
    for (int kt = 0; kt < KT; kt++) {
        if (kt == KT - 1) cp_wait<0>(); else cp_wait<1>();
        __syncthreads();
        if (kt + 2 < KT) issue((kt + 2) % 3, kt + 2);
        compute(kt % 3);
    }

#pragma unroll
    for (int mf = 0; mf < 4; mf++) {
        int row = row0 + wm + mf * 16 + (lane >> 2);
#pragma unroll
        for (int nf = 0; nf < 8; nf++) {
            int col = wn + nf * 8 + 2 * (lane & 3);
            float* d = acc[mf][nf];
            float b0 = bo[col], b1 = bo[col + 1];
            *reinterpret_cast<float2*>(&outp[(size_t)row * 256 + col]) =
                make_float2(d[0] + b0, d[1] + b1);
            *reinterpret_cast<float2*>(&outp[(size_t)(row + 8) * 256 + col]) =
                make_float2(d[2] + b0, d[3] + b1);
        }
    }
}

// ---------------- attention (warp per (b, head)), fp16 qkv ----------------
__global__ __launch_bounds__(128)
void attn_kernel(const float* __restrict__ rel,
                 const float* __restrict__ gbias,
                 const float* __restrict__ alphap) {
    __shared__ __half2 k_s[4][20][20];   // 16 used + 4 pad (80B rows, 16B-aligned)
    __shared__ float p_s[4][20][20];
    int lane = threadIdx.x & 31;
    int wid  = threadIdx.x >> 5;
    int h = blockIdx.y * 4 + wid;
    int b = blockIdx.x;
    float alpha = alphap[0];

    // stage k rows (broadcast-consumed later); v straight into regs (lane = dim)
    for (int idx = lane; idx < 80; idx += 32) {
        int n = idx >> 2, c = idx & 3;
        *reinterpret_cast<uint4*>(&k_s[wid][n][c * 4]) =
            *reinterpret_cast<const uint4*>(
                &g_qkvh[(size_t)(b * 20 + n) * 768 + 256 + h * 32 + c * 8]);
    }
    float vreg[20];
#pragma unroll
    for (int m2 = 0; m2 < 20; m2++)
        vreg[m2] = __half2float(
            g_qkvh[(size_t)(b * 20 + m2) * 768 + 512 + h * 32 + lane]);
    __syncwarp();

    // scores + softmax in registers; lane = query row n (20 active)
    if (lane < 20) {
        int n = lane;
        __align__(16) __half2 q2[16];
#pragma unroll
        for (int c = 0; c < 4; c++)
            *reinterpret_cast<uint4*>(&q2[c * 4]) =
                *reinterpret_cast<const uint4*>(
                    &g_qkvh[(size_t)(b * 20 + n) * 768 + h * 32 + c * 8]);
        float sc[20];
        const float* gb = &gbias[(h * 20 + n) * 20];
        float mx = -1e30f;
#pragma unroll
        for (int m2 = 0; m2 < 20; m2++) {
            float a = 0.f;
#pragma unroll
            for (int j = 0; j < 16; j++) {
                float2 kf = __half22float2(k_s[wid][m2][j]);
                float2 qf = __half22float2(q2[j]);
                a += qf.x * kf.x + qf.y * kf.y;
            }
            a = a * 0.17677669529663689f + __ldg(&rel[(n - m2 + 19) * 8 + h])
                + __ldg(&gb[m2]) * alpha;
            sc[m2] = a;
            mx = fmaxf(mx, a);
        }
        float ssum = 0.f;
#pragma unroll
        for (int m2 = 0; m2 < 20; m2++) {
            float e = __expf(sc[m2] - mx);
            sc[m2] = e; ssum += e;
        }
        float inv = 1.f / ssum;
#pragma unroll
        for (int j = 0; j < 5; j++) {
            float4 p4 = make_float4(sc[4 * j] * inv, sc[4 * j + 1] * inv,
                                    sc[4 * j + 2] * inv, sc[4 * j + 3] * inv);
            *reinterpret_cast<float4*>(&p_s[wid][n][4 * j]) = p4;
        }
    }
    __syncwarp();

    // AV: lane = dim d; p broadcast from smem, v in registers
#pragma unroll 1
    for (int n = 0; n < 20; n++) {
        float a = 0.f;
#pragma unroll
        for (int j = 0; j < 5; j++) {
            float4 p4 = *reinterpret_cast<const float4*>(&p_s[wid][n][4 * j]);
            a += p4.x * vreg[4 * j] + p4.y * vreg[4 * j + 1] +
                 p4.z * vreg[4 * j + 2] + p4.w * vreg[4 * j + 3];
        }
        g_ah[(size_t)(b * 20 + n) * 256 + h * 32 + lane] = __float2half(a);
    }
}

// ---------------- launch ----------------
extern "C" void kernel_launch(void* const* d_in, const int* in_sizes, int n_in,
                              void* d_out, int out_size) {
    const float* x     = (const float*)d_in[0];
    const float* wq    = (const float*)d_in[1];
    const float* wk    = (const float*)d_in[2];
    const float* wv    = (const float*)d_in[3];
    const float* gq    = (const float*)d_in[4];
    const float* bq    = (const float*)d_in[5];
    const float* gk    = (const float*)d_in[6];
    const float* bk    = (const float*)d_in[7];
    const float* gv    = (const float*)d_in[8];
    const float* bv    = (const float*)d_in[9];
    const float* rel   = (const float*)d_in[10];
    const float* gbias = (const float*)d_in[11];
    const float* alpha = (const float*)d_in[12];
    const float* wo    = (const float*)d_in[13];
    const float* bo    = (const float*)d_in[14];
    float* out = (float*)d_out;

    int B = in_sizes[0] / (N_NODES * D_MODEL);
    int M = B * N_NODES;

    cudaFuncSetAttribute(conv_ln_kernel,
                         cudaFuncAttributeMaxDynamicSharedMemorySize, SMEM_CONV);
    cudaFuncSetAttribute(proj_gemm,
                         cudaFuncAttributeMaxDynamicSharedMemorySize, SMEM_PROJ);

    prep_w<<<(768 * 768 + 255) / 256, 256>>>(wq, wk, wv, wo);
    prep_x<<<(M * 64 + 255) / 256, 256>>>(x, M * 64);

    conv_ln_kernel<<<dim3(3, M / 128), 256, SMEM_CONV>>>(
        x, gq, bq, gk, bk, gv, bv);

    attn_kernel<<<dim3(B, 2), 128>>>(rel, gbias, alpha);

    proj_gemm<<<M / 128, 256, SMEM_PROJ>>>(bo, out);
}

// round 9
// speedup vs baseline: 4.8552x; 1.1610x over previous
#include <cuda_runtime.h>
#include <cuda_bf16.h>
#include <cuda_fp16.h>
#include <cstdint>

#define D_MODEL 256
#define N_NODES 20
#define N_HEADS 8
#define BMAX    8192
#define MMAX    (BMAX * N_NODES)   // 163840 rows

// ---------------- scratch (device globals: allocation-free) ----------------
__device__ __half g_xh[(size_t)MMAX * 256];     // x as fp16
__device__ __half g_wh[768 * 768];              // conv weights fp16 [o][j=t*256+i]
__device__ __half g_woh[256 * 256];             // wo fp16 [o][i]
__device__ __half g_qkvh[(size_t)MMAX * 768];   // q|k|v after LN+residual (fp16)
__device__ __half g_ah[(size_t)MMAX * 256];     // attn out fp16

// ---------------- warp-MMA helpers (baseline PTX: sm_80+) ----------------
__device__ __forceinline__ uint32_t smem_u32(const void* p) {
    uint32_t a;
    asm("{ .reg .u64 t; cvta.to.shared.u64 t, %1; cvt.u32.u64 %0, t; }"
        : "=r"(a) : "l"(p));
    return a;
}
__device__ __forceinline__ void ldsm4(uint32_t& r0, uint32_t& r1,
                                      uint32_t& r2, uint32_t& r3, uint32_t addr) {
    asm volatile("ldmatrix.sync.aligned.m8n8.x4.shared.b16 {%0,%1,%2,%3}, [%4];"
                 : "=r"(r0), "=r"(r1), "=r"(r2), "=r"(r3) : "r"(addr));
}
__device__ __forceinline__ void ldsm4t(uint32_t& r0, uint32_t& r1,
                                       uint32_t& r2, uint32_t& r3, uint32_t addr) {
    asm volatile("ldmatrix.sync.aligned.m8n8.x4.trans.shared.b16 {%0,%1,%2,%3}, [%4];"
                 : "=r"(r0), "=r"(r1), "=r"(r2), "=r"(r3) : "r"(addr));
}
__device__ __forceinline__ void mma_f16(float* d,
                                        const uint32_t* a,
                                        uint32_t b0, uint32_t b1) {
    asm volatile(
        "mma.sync.aligned.m16n8k16.row.col.f32.f16.f16.f32 "
        "{%0,%1,%2,%3}, {%4,%5,%6,%7}, {%8,%9}, {%0,%1,%2,%3};"
        : "+f"(d[0]), "+f"(d[1]), "+f"(d[2]), "+f"(d[3])
        : "r"(a[0]), "r"(a[1]), "r"(a[2]), "r"(a[3]), "r"(b0), "r"(b1));
}
__device__ __forceinline__ uint32_t pack_h2(float x, float y) {
    __half2 h = __floats2half2_rn(x, y);
    return *reinterpret_cast<uint32_t*>(&h);
}
// 64B-row swizzle (proj) and 128B-row swizzle (conv BK=64)
__device__ __forceinline__ uint32_t swz(uint32_t r, uint32_t kq) {
    return r * 64 + ((kq ^ ((r >> 1) & 3)) * 16);
}
__device__ __forceinline__ uint32_t swz128(uint32_t r, uint32_t kq) {
    return r * 128 + ((kq ^ (r & 7)) * 16);
}
__device__ __forceinline__ void cp16(uint32_t dst, const void* src, int srcsz) {
    asm volatile("cp.async.cg.shared.global [%0], [%1], 16, %2;"
                 :: "r"(dst), "l"(__cvta_generic_to_global(src)), "r"(srcsz)
                 : "memory");
}
__device__ __forceinline__ void cp_commit() {
    asm volatile("cp.async.commit_group;" ::: "memory");
}
template<int N>
__device__ __forceinline__ void cp_wait() {
    asm volatile("cp.async.wait_group %0;" :: "n"(N) : "memory");
}

// ---------------- prep kernels ----------------
__global__ void prep_w(const float* __restrict__ wq, const float* __restrict__ wk,
                       const float* __restrict__ wv, const float* __restrict__ wo) {
    int idx = blockIdx.x * blockDim.x + threadIdx.x;
    if (idx < 768 * 768) {
        int o = idx / 768, j = idx % 768;
        int t = j >> 8, i = j & 255;
        const float* w = (o < 256) ? wq : (o < 512) ? wk : wv;
        int oc = o & 255;
        g_wh[idx] = __float2half(w[(oc * 256 + i) * 3 + t]);
    }
    if (idx < 256 * 256) {
        g_woh[idx] = __float2half(wo[idx]);
    }
}
__global__ void prep_x(const float* __restrict__ x, int total4) {
    int i = blockIdx.x * blockDim.x + threadIdx.x;
    if (i < total4) {
        float4 v = reinterpret_cast<const float4*>(x)[i];
        __half2 h0, h1;
        h0.x = __float2half(v.x); h0.y = __float2half(v.y);
        h1.x = __float2half(v.z); h1.y = __float2half(v.w);
        reinterpret_cast<__half2*>(g_xh)[i * 2]     = h0;
        reinterpret_cast<__half2*>(g_xh)[i * 2 + 1] = h1;
    }
}

// ---------------- fused conv GEMM + LayerNorm + residual ----------------
// Per block: 128 rows x 256 cols (one q/k/v segment). BK=64, 3-stage cp.async.
// Stage: A 16K | B 32K = 48K
#define STAGE_SZ 49152
#define SMEM_CONV (3 * STAGE_SZ + 1024 + 2048)

__global__ __launch_bounds__(256, 1)
void conv_ln_kernel(const float* __restrict__ x,
                    const float* __restrict__ gq, const float* __restrict__ bq,
                    const float* __restrict__ gk, const float* __restrict__ bk,
                    const float* __restrict__ gv, const float* __restrict__ bv) {
    extern __shared__ __align__(16) char smem[];
    const uint32_t sb = smem_u32(smem);
    float* red = reinterpret_cast<float*>(smem + 3 * STAGE_SZ);        // [128][2]
    float* gam = reinterpret_cast<float*>(smem + 3 * STAGE_SZ + 1024); // [256]
    float* bet = reinterpret_cast<float*>(smem + 3 * STAGE_SZ + 2048); // [256]

    int tid = threadIdx.x, lane = tid & 31, wid = tid >> 5;
    int seg = blockIdx.x;              // 0=q 1=k 2=v
    int row0 = blockIdx.y * 128;
    int wm = (wid >> 2) * 64;
    int wn = (wid & 3) * 64;

    {
        const float* gsel = (seg == 0) ? gq : (seg == 1) ? gk : gv;
        const float* bsel = (seg == 0) ? bq : (seg == 1) ? bk : bv;
        gam[tid] = gsel[tid];
        bet[tid] = bsel[tid];
        red[tid] = 0.f;
    }

    float acc[4][8][4];
#pragma unroll
    for (int i = 0; i < 4; i++)
#pragma unroll
        for (int j = 0; j < 8; j++)
#pragma unroll
            for (int q = 0; q < 4; q++) acc[i][j][q] = 0.f;

    auto issue = [&](int s, int kt) {
        uint32_t stg = sb + s * STAGE_SZ;
        int k0 = kt * 64;
        int t = kt >> 2;                 // tap (4 chunks of 64 per tap)
        int dbase = (kt & 3) * 64;
        // A: 128 rows x 64 fp16 = 16KB
#pragma unroll
        for (int it = 0; it < 4; it++) {
            int f = it * 256 + tid;
            int r = f >> 3, kq = f & 7;
            int m = row0 + r;
            int n = m % N_NODES;
            int ns = n + t - 1;
            int ok = ((unsigned)ns < (unsigned)N_NODES);
            size_t src = (size_t)(ok ? (m + t - 1) : m) * 256 + dbase + kq * 8;
            int sz = ok ? 16 : 0;
            cp16(stg + swz128((uint32_t)r, (uint32_t)kq), g_xh + src, sz);
        }
        // B: 256 rows x 64 fp16 = 32KB
#pragma unroll
        for (int it = 0; it < 8; it++) {
            int f = it * 256 + tid;
            int r = f >> 3, kq = f & 7;
            size_t src = (size_t)(seg * 256 + r) * 768 + k0 + kq * 8;
            cp16(stg + 16384 + swz128((uint32_t)r, (uint32_t)kq), g_wh + src, 16);
        }
        cp_commit();
    };

    auto compute = [&](int s) {
        uint32_t base = sb + s * STAGE_SZ;
#pragma unroll
        for (int ks = 0; ks < 4; ks++) {
            uint32_t fA[4][4];
#pragma unroll
            for (int mf = 0; mf < 4; mf++) {
                uint32_t r = wm + mf * 16 + (lane & 15);
                uint32_t kq = ks * 2 + (lane >> 4);
                uint32_t ad = base + swz128(r, kq);
                ldsm4(fA[mf][0], fA[mf][1], fA[mf][2], fA[mf][3], ad);
            }
#pragma unroll
            for (int np = 0; np < 4; np++) {
                uint32_t r = wn + np * 16 + (lane & 7) + ((lane >> 4) << 3);
                uint32_t kq = ks * 2 + ((lane >> 3) & 1);
                uint32_t ad = base + 16384 + swz128(r, kq);
                uint32_t b0, b1, b2, b3;
                ldsm4(b0, b1, b2, b3, ad);
#pragma unroll
                for (int mf = 0; mf < 4; mf++) {
                    mma_f16(acc[mf][2 * np],     fA[mf], b0, b1);
                    mma_f16(acc[mf][2 * np + 1], fA[mf], b2, b3);
                }
            }
        }
    };

    const int KT = 12;
    issue(0, 0);
    issue(1, 1);
#pragma unroll 1
    for (int kt = 0; kt < KT; kt++) {
        if (kt == KT - 1) cp_wait<0>(); else cp_wait<1>();
        __syncthreads();
        if (kt + 2 < KT) issue((kt + 2) % 3, kt + 2);
        compute(kt % 3);
    }

    // ---- LN + residual epilogue (fp16 output) ----
#pragma unroll
    for (int mf = 0; mf < 4; mf++) {
#pragma unroll
        for (int rr = 0; rr < 2; rr++) {
            int rloc = wm + mf * 16 + (lane >> 2) + rr * 8;
            float s = 0.f, s2 = 0.f;
#pragma unroll
            for (int nf = 0; nf < 8; nf++) {
                float c0 = acc[mf][nf][rr * 2];
                float c1 = acc[mf][nf][rr * 2 + 1];
                s += c0 + c1; s2 += c0 * c0 + c1 * c1;
            }
            s  += __shfl_xor_sync(0xffffffffu, s, 1);
            s  += __shfl_xor_sync(0xffffffffu, s, 2);
            s2 += __shfl_xor_sync(0xffffffffu, s2, 1);
            s2 += __shfl_xor_sync(0xffffffffu, s2, 2);
            if ((lane & 3) == 0) {
                atomicAdd(&red[rloc * 2], s);
                atomicAdd(&red[rloc * 2 + 1], s2);
            }
        }
    }
    __syncthreads();

#pragma unroll
    for (int mf = 0; mf < 4; mf++) {
#pragma unroll
        for (int rr = 0; rr < 2; rr++) {
            int rloc = wm + mf * 16 + (lane >> 2) + rr * 8;
            int rg = row0 + rloc;
            float mean = red[rloc * 2] * (1.0f / 256.0f);
            float var  = red[rloc * 2 + 1] * (1.0f / 256.0f) - mean * mean;
            float inv  = rsqrtf(var + 1e-5f);
#pragma unroll
            for (int nf = 0; nf < 8; nf++) {
                int cloc = wn + nf * 8 + 2 * (lane & 3);
                float2 xv = *reinterpret_cast<const float2*>(
                    &x[(size_t)rg * 256 + cloc]);
                float c0 = acc[mf][nf][rr * 2];
                float c1 = acc[mf][nf][rr * 2 + 1];
                float o0 = xv.x + (c0 - mean) * inv * gam[cloc]     + bet[cloc];
                float o1 = xv.y + (c1 - mean) * inv * gam[cloc + 1] + bet[cloc + 1];
                *reinterpret_cast<__half2*>(
                    &g_qkvh[(size_t)rg * 768 + seg * 256 + cloc]) =
                    __floats2half2_rn(o0, o1);
            }
        }
    }
}

// ---------------- proj GEMM (single-pass fp16, 128x256 tile, 3-stage) ----------------
#define PSTAGE_SZ 24576
#define SMEM_PROJ (3 * PSTAGE_SZ)

__global__ __launch_bounds__(256, 1)
void proj_gemm(const float* __restrict__ bo, float* __restrict__ outp) {
    extern __shared__ __align__(16) char smem[];
    const uint32_t sb = smem_u32(smem);

    int tid = threadIdx.x, lane = tid & 31, wid = tid >> 5;
    int row0 = blockIdx.x * 128;
    int wm = (wid >> 2) * 64;
    int wn = (wid & 3) * 64;

    float acc[4][8][4];
#pragma unroll
    for (int i = 0; i < 4; i++)
#pragma unroll
        for (int j = 0; j < 8; j++)
#pragma unroll
            for (int q = 0; q < 4; q++) acc[i][j][q] = 0.f;

    auto issue = [&](int s, int kt) {
        uint32_t stg = sb + s * PSTAGE_SZ;
        int k0 = kt * 32;
#pragma unroll
        for (int it = 0; it < 2; it++) {
            int f = it * 256 + tid;
            int r = f >> 2, kq = f & 3;
            size_t src = (size_t)(row0 + r) * 256 + k0 + kq * 8;
            cp16(stg + swz((uint32_t)r, (uint32_t)kq), g_ah + src, 16);
        }
#pragma unroll
        for (int it = 0; it < 4; it++) {
            int f = it * 256 + tid;
            int r = f >> 2, kq = f & 3;
            size_t src = (size_t)r * 256 + k0 + kq * 8;
            cp16(stg + 8192 + swz((uint32_t)r, (uint32_t)kq), g_woh + src, 16);
        }
        cp_commit();
    };

    auto compute = [&](int s) {
        uint32_t base = sb + s * PSTAGE_SZ;
#pragma unroll
        for (int ks = 0; ks < 2; ks++) {
            uint32_t fA[4][4];
#pragma unroll
            for (int mf = 0; mf < 4; mf++) {
                uint32_t r = wm + mf * 16 + (lane & 15);
                uint32_t kq = ks * 2 + (lane >> 4);
                uint32_t ad = base + swz(r, kq);
                ldsm4(fA[mf][0], fA[mf][1], fA[mf][2], fA[mf][3], ad);
            }
#pragma unroll
            for (int np = 0; np < 4; np++) {
                uint32_t r = wn + np * 16 + (lane & 7) + ((lane >> 4) << 3);
                uint32_t kq = ks * 2 + ((lane >> 3) & 1);
                uint32_t ad = base + 8192 + swz(r, kq);
                uint32_t b0, b1, b2, b3;
                ldsm4(b0, b1, b2, b3, ad);
#pragma unroll
                for (int mf = 0; mf < 4; mf++) {
                    mma_f16(acc[mf][2 * np],     fA[mf], b0, b1);
                    mma_f16(acc[mf][2 * np + 1], fA[mf], b2, b3);
                }
            }
        }
    };

    const int KT = 8;
    issue(0, 0);
    issue(1, 1);
#pragma unroll 1
    for (int kt = 0; kt < KT; kt++) {
        if (kt == KT - 1) cp_wait<0>(); else cp_wait<1>();
        __syncthreads();
        if (kt + 2 < KT) issue((kt + 2) % 3, kt + 2);
        compute(kt % 3);
    }

#pragma unroll
    for (int mf = 0; mf < 4; mf++) {
        int row = row0 + wm + mf * 16 + (lane >> 2);
#pragma unroll
        for (int nf = 0; nf < 8; nf++) {
            int col = wn + nf * 8 + 2 * (lane & 3);
            float* d = acc[mf][nf];
            float b0 = bo[col], b1 = bo[col + 1];
            *reinterpret_cast<float2*>(&outp[(size_t)row * 256 + col]) =
                make_float2(d[0] + b0, d[1] + b1);
            *reinterpret_cast<float2*>(&outp[(size_t)(row + 8) * 256 + col]) =
                make_float2(d[2] + b0, d[3] + b1);
        }
    }
}

// ---------------- attention: HMMA per (b, head), warp-local ----------------
// q,k,v padded to [32,32] fp16 in smem (stride 40 halves -> ldsm conflict-free).
// QK and AV on tensor cores; softmax in C-fragments via quad shuffles.
__global__ __launch_bounds__(128)
void attn_kernel(const float* __restrict__ rel,
                 const float* __restrict__ gbias,
                 const float* __restrict__ alphap) {
    __shared__ __half q_s[4][32][40];
    __shared__ __half k_s[4][32][40];
    __shared__ __half v_s[4][32][40];
    int lane = threadIdx.x & 31;
    int wid  = threadIdx.x >> 5;
    int h = blockIdx.y * 4 + wid;
    int b = blockIdx.x;
    float alpha = alphap[0];

    // stage q,k,v rows (zero-pad rows >= 20)
    {
        int r = lane;
        if (r < 20) {
            const __half* basep = &g_qkvh[(size_t)(b * 20 + r) * 768 + h * 32];
#pragma unroll
            for (int c = 0; c < 4; c++) {
                *reinterpret_cast<uint4*>(&q_s[wid][r][c * 8]) =
                    *reinterpret_cast<const uint4*>(basep + c * 8);
                *reinterpret_cast<uint4*>(&k_s[wid][r][c * 8]) =
                    *reinterpret_cast<const uint4*>(basep + 256 + c * 8);
                *reinterpret_cast<uint4*>(&v_s[wid][r][c * 8]) =
                    *reinterpret_cast<const uint4*>(basep + 512 + c * 8);
            }
        } else {
            uint4 z = make_uint4(0, 0, 0, 0);
#pragma unroll
            for (int c = 0; c < 4; c++) {
                *reinterpret_cast<uint4*>(&q_s[wid][r][c * 8]) = z;
                *reinterpret_cast<uint4*>(&k_s[wid][r][c * 8]) = z;
                *reinterpret_cast<uint4*>(&v_s[wid][r][c * 8]) = z;
            }
        }
    }
    __syncwarp();

    const uint32_t sq = smem_u32(&q_s[wid][0][0]);
    const uint32_t sk = smem_u32(&k_s[wid][0][0]);
    const uint32_t sv = smem_u32(&v_s[wid][0][0]);
    int g = lane >> 2, t = lane & 3;

    // ---- QK^T: scores[32][32] in C fragments c[mt][nt][4] ----
    float c[2][4][4];
#pragma unroll
    for (int i = 0; i < 2; i++)
#pragma unroll
        for (int j = 0; j < 4; j++)
#pragma unroll
            for (int q = 0; q < 4; q++) c[i][j][q] = 0.f;

#pragma unroll
    for (int ks = 0; ks < 2; ks++) {
        uint32_t a[2][4];
#pragma unroll
        for (int mt = 0; mt < 2; mt++) {
            uint32_t ad = sq + (mt * 16 + (lane & 15)) * 80 +
                          (ks * 16 + (lane >> 4) * 8) * 2;
            ldsm4(a[mt][0], a[mt][1], a[mt][2], a[mt][3], ad);
        }
        uint32_t bf[2][4];
#pragma unroll
        for (int np = 0; np < 2; np++) {
            uint32_t ad = sk + (np * 16 + (lane & 7) + ((lane >> 4) << 3)) * 80 +
                          (ks * 2 + ((lane >> 3) & 1)) * 16;
            ldsm4(bf[np][0], bf[np][1], bf[np][2], bf[np][3], ad);
        }
#pragma unroll
        for (int mt = 0; mt < 2; mt++)
#pragma unroll
            for (int nt = 0; nt < 4; nt++)
                mma_f16(c[mt][nt], a[mt],
                        bf[nt >> 1][(nt & 1) * 2], bf[nt >> 1][(nt & 1) * 2 + 1]);
    }

    // ---- biases + masking (in fragments) ----
#pragma unroll
    for (int mt = 0; mt < 2; mt++)
#pragma unroll
        for (int nt = 0; nt < 4; nt++)
#pragma unroll
            for (int q = 0; q < 4; q++) {
                int row = mt * 16 + g + (q >> 1) * 8;
                int col = nt * 8 + 2 * t + (q & 1);
                if (row < 20 && col < 20) {
                    c[mt][nt][q] = c[mt][nt][q] * 0.17677669529663689f +
                        __ldg(&rel[(row - col + 19) * 8 + h]) +
                        __ldg(&gbias[(h * 20 + row) * 20 + col]) * alpha;
                } else {
                    c[mt][nt][q] = -1e30f;
                }
            }

    // ---- softmax over cols (quad shuffles; rows g and g+8 per mt) ----
#pragma unroll
    for (int mt = 0; mt < 2; mt++) {
        float m0 = -1e30f, m1 = -1e30f;
#pragma unroll
        for (int nt = 0; nt < 4; nt++) {
            m0 = fmaxf(m0, fmaxf(c[mt][nt][0], c[mt][nt][1]));
            m1 = fmaxf(m1, fmaxf(c[mt][nt][2], c[mt][nt][3]));
        }
        m0 = fmaxf(m0, __shfl_xor_sync(0xffffffffu, m0, 1));
        m0 = fmaxf(m0, __shfl_xor_sync(0xffffffffu, m0, 2));
        m1 = fmaxf(m1, __shfl_xor_sync(0xffffffffu, m1, 1));
        m1 = fmaxf(m1, __shfl_xor_sync(0xffffffffu, m1, 2));
        float s0 = 0.f, s1 = 0.f;
#pragma unroll
        for (int nt = 0; nt < 4; nt++) {
            c[mt][nt][0] = __expf(c[mt][nt][0] - m0);
            c[mt][nt][1] = __expf(c[mt][nt][1] - m0);
            c[mt][nt][2] = __expf(c[mt][nt][2] - m1);
            c[mt][nt][3] = __expf(c[mt][nt][3] - m1);
            s0 += c[mt][nt][0] + c[mt][nt][1];
            s1 += c[mt][nt][2] + c[mt][nt][3];
        }
        s0 += __shfl_xor_sync(0xffffffffu, s0, 1);
        s0 += __shfl_xor_sync(0xffffffffu, s0, 2);
        s1 += __shfl_xor_sync(0xffffffffu, s1, 1);
        s1 += __shfl_xor_sync(0xffffffffu, s1, 2);
        float i0 = 1.f / s0, i1 = 1.f / s1;
#pragma unroll
        for (int nt = 0; nt < 4; nt++) {
            c[mt][nt][0] *= i0; c[mt][nt][1] *= i0;
            c[mt][nt][2] *= i1; c[mt][nt][3] *= i1;
        }
    }

    // ---- AV: out[32][32] = P @ V, P from fragments, V via ldmatrix.trans ----
    float o[2][4][4];
#pragma unroll
    for (int i = 0; i < 2; i++)
#pragma unroll
        for (int j = 0; j < 4; j++)
#pragma unroll
            for (int q = 0; q < 4; q++) o[i][j][q] = 0.f;

#pragma unroll
    for (int ks = 0; ks < 2; ks++) {
        uint32_t pa[2][4];
#pragma unroll
        for (int mt = 0; mt < 2; mt++) {
            pa[mt][0] = pack_h2(c[mt][2 * ks][0],     c[mt][2 * ks][1]);
            pa[mt][1] = pack_h2(c[mt][2 * ks][2],     c[mt][2 * ks][3]);
            pa[mt][2] = pack_h2(c[mt][2 * ks + 1][0], c[mt][2 * ks + 1][1]);
            pa[mt][3] = pack_h2(c[mt][2 * ks + 1][2], c[mt][2 * ks + 1][3]);
        }
        uint32_t bv[2][4];
#pragma unroll
        for (int dp = 0; dp < 2; dp++) {
            uint32_t ad = sv + (ks * 16 + (lane & 15)) * 80 +
                          (dp * 16 + ((lane >> 4) << 3)) * 2;
            ldsm4t(bv[dp][0], bv[dp][1], bv[dp][2], bv[dp][3], ad);
        }
#pragma unroll
        for (int mt = 0; mt < 2; mt++)
#pragma unroll
            for (int nt = 0; nt < 4; nt++)
                mma_f16(o[mt][nt], pa[mt],
                        bv[nt >> 1][(nt & 1) * 2], bv[nt >> 1][(nt & 1) * 2 + 1]);
    }

    // ---- store rows < 20 as fp16 ----
#pragma unroll
    for (int mt = 0; mt < 2; mt++)
#pragma unroll
        for (int q2 = 0; q2 < 2; q2++) {
            int row = mt * 16 + g + q2 * 8;
            if (row < 20) {
                __half* dst = &g_ah[(size_t)(b * 20 + row) * 256 + h * 32];
#pragma unroll
                for (int nt = 0; nt < 4; nt++) {
                    int col = nt * 8 + 2 * t;
                    *reinterpret_cast<__half2*>(dst + col) =
                        __floats2half2_rn(o[mt][nt][q2 * 2], o[mt][nt][q2 * 2 + 1]);
                }
            }
        }
}

// ---------------- launch ----------------
extern "C" void kernel_launch(void* const* d_in, const int* in_sizes, int n_in,
                              void* d_out, int out_size) {
    const float* x     = (const float*)d_in[0];
    const float* wq    = (const float*)d_in[1];
    const float* wk    = (const float*)d_in[2];
    const float* wv    = (const float*)d_in[3];
    const float* gq    = (const float*)d_in[4];
    const float* bq    = (const float*)d_in[5];
    const float* gk    = (const float*)d_in[6];
    const float* bk    = (const float*)d_in[7];
    const float* gv    = (const float*)d_in[8];
    const float* bv    = (const float*)d_in[9];
    const float* rel   = (const float*)d_in[10];
    const float* gbias = (const float*)d_in[11];
    const float* alpha = (const float*)d_in[12];
    const float* wo    = (const float*)d_in[13];
    const float* bo    = (const float*)d_in[14];
    float* out = (float*)d_out;

    int B = in_sizes[0] / (N_NODES * D_MODEL);
    int M = B * N_NODES;

    cudaFuncSetAttribute(conv_ln_kernel,
                         cudaFuncAttributeMaxDynamicSharedMemorySize, SMEM_CONV);
    cudaFuncSetAttribute(proj_gemm,
                         cudaFuncAttributeMaxDynamicSharedMemorySize, SMEM_PROJ);

    prep_w<<<(768 * 768 + 255) / 256, 256>>>(wq, wk, wv, wo);
    prep_x<<<(M * 64 + 255) / 256, 256>>>(x, M * 64);

    conv_ln_kernel<<<dim3(3, M / 128), 256, SMEM_CONV>>>(
        x, gq, bq, gk, bk, gv, bv);

    attn_kernel<<<dim3(B, 2), 128>>>(rel, gbias, alpha);

    proj_gemm<<<M / 128, 256, SMEM_PROJ>>>(bo, out);
}

// round 10
// speedup vs baseline: 4.9308x; 1.0156x over previous
#include <cuda_runtime.h>
#include <cuda_bf16.h>
#include <cuda_fp16.h>
#include <cstdint>

#define D_MODEL 256
#define N_NODES 20
#define N_HEADS 8
#define BMAX    8192
#define MMAX    (BMAX * N_NODES)   // 163840 rows

// ---------------- scratch (device globals: allocation-free) ----------------
__device__ __half g_xh[(size_t)MMAX * 256];     // x as fp16
__device__ __half g_wh[768 * 768];              // conv weights fp16 [o][j=t*256+i]
__device__ __half g_woh[256 * 256];             // wo fp16 [o][i]
__device__ __half g_qkvh[(size_t)MMAX * 768];   // q|k|v after LN+residual (fp16)
__device__ __half g_ah[(size_t)MMAX * 256];     // attn out fp16
__device__ float  g_bias[N_HEADS * 20 * 20];    // rel + alpha*gbias combined

// ---------------- warp-MMA helpers (baseline PTX: sm_80+) ----------------
__device__ __forceinline__ uint32_t smem_u32(const void* p) {
    uint32_t a;
    asm("{ .reg .u64 t; cvta.to.shared.u64 t, %1; cvt.u32.u64 %0, t; }"
        : "=r"(a) : "l"(p));
    return a;
}
__device__ __forceinline__ void ldsm4(uint32_t& r0, uint32_t& r1,
                                      uint32_t& r2, uint32_t& r3, uint32_t addr) {
    asm volatile("ldmatrix.sync.aligned.m8n8.x4.shared.b16 {%0,%1,%2,%3}, [%4];"
                 : "=r"(r0), "=r"(r1), "=r"(r2), "=r"(r3) : "r"(addr));
}
__device__ __forceinline__ void ldsm4t(uint32_t& r0, uint32_t& r1,
                                       uint32_t& r2, uint32_t& r3, uint32_t addr) {
    asm volatile("ldmatrix.sync.aligned.m8n8.x4.trans.shared.b16 {%0,%1,%2,%3}, [%4];"
                 : "=r"(r0), "=r"(r1), "=r"(r2), "=r"(r3) : "r"(addr));
}
__device__ __forceinline__ void mma_f16(float* d,
                                        const uint32_t* a,
                                        uint32_t b0, uint32_t b1) {
    asm volatile(
        "mma.sync.aligned.m16n8k16.row.col.f32.f16.f16.f32 "
        "{%0,%1,%2,%3}, {%4,%5,%6,%7}, {%8,%9}, {%0,%1,%2,%3};"
        : "+f"(d[0]), "+f"(d[1]), "+f"(d[2]), "+f"(d[3])
        : "r"(a[0]), "r"(a[1]), "r"(a[2]), "r"(a[3]), "r"(b0), "r"(b1));
}
__device__ __forceinline__ uint32_t pack_h2(float x, float y) {
    __half2 h = __floats2half2_rn(x, y);
    return *reinterpret_cast<uint32_t*>(&h);
}
__device__ __forceinline__ uint32_t swz(uint32_t r, uint32_t kq) {
    return r * 64 + ((kq ^ ((r >> 1) & 3)) * 16);
}
__device__ __forceinline__ uint32_t swz128(uint32_t r, uint32_t kq) {
    return r * 128 + ((kq ^ (r & 7)) * 16);
}
__device__ __forceinline__ void cp16(uint32_t dst, const void* src, int srcsz) {
    asm volatile("cp.async.cg.shared.global [%0], [%1], 16, %2;"
                 :: "r"(dst), "l"(__cvta_generic_to_global(src)), "r"(srcsz)
                 : "memory");
}
__device__ __forceinline__ void cp_commit() {
    asm volatile("cp.async.commit_group;" ::: "memory");
}
template<int N>
__device__ __forceinline__ void cp_wait() {
    asm volatile("cp.async.wait_group %0;" :: "n"(N) : "memory");
}

// ---------------- prep kernels ----------------
__global__ void prep_w(const float* __restrict__ wq, const float* __restrict__ wk,
                       const float* __restrict__ wv, const float* __restrict__ wo) {
    int idx = blockIdx.x * blockDim.x + threadIdx.x;
    if (idx < 768 * 768) {
        int o = idx / 768, j = idx % 768;
        int t = j >> 8, i = j & 255;
        const float* w = (o < 256) ? wq : (o < 512) ? wk : wv;
        int oc = o & 255;
        g_wh[idx] = __float2half(w[(oc * 256 + i) * 3 + t]);
    }
    if (idx < 256 * 256) {
        g_woh[idx] = __float2half(wo[idx]);
    }
}
__global__ void prep_x(const float* __restrict__ x, int total4) {
    int i = blockIdx.x * blockDim.x + threadIdx.x;
    if (i < total4) {
        float4 v = reinterpret_cast<const float4*>(x)[i];
        __half2 h0, h1;
        h0.x = __float2half(v.x); h0.y = __float2half(v.y);
        h1.x = __float2half(v.z); h1.y = __float2half(v.w);
        reinterpret_cast<__half2*>(g_xh)[i * 2]     = h0;
        reinterpret_cast<__half2*>(g_xh)[i * 2 + 1] = h1;
    }
}
__global__ void prep_bias(const float* __restrict__ rel,
                          const float* __restrict__ gbias,
                          const float* __restrict__ alphap) {
    int idx = blockIdx.x * blockDim.x + threadIdx.x;
    if (idx < N_HEADS * 400) {
        int h = idx / 400, rc = idx % 400;
        int r = rc / 20, c = rc % 20;
        g_bias[idx] = rel[(r - c + 19) * 8 + h] + alphap[0] * gbias[idx];
    }
}

// ---------------- fused conv GEMM + LayerNorm + residual ----------------
// Per block: 128 rows x 256 cols (one q/k/v segment). BK=64, 3-stage cp.async.
// 512 threads (16 warps, warp tile 32x64) for latency hiding.
#define STAGE_SZ 49152
#define SMEM_CONV (3 * STAGE_SZ + 1024 + 2048)

__global__ __launch_bounds__(512, 1)
void conv_ln_kernel(const float* __restrict__ x,
                    const float* __restrict__ gq, const float* __restrict__ bq,
                    const float* __restrict__ gk, const float* __restrict__ bk,
                    const float* __restrict__ gv, const float* __restrict__ bv) {
    extern __shared__ __align__(16) char smem[];
    const uint32_t sb = smem_u32(smem);
    float* red = reinterpret_cast<float*>(smem + 3 * STAGE_SZ);        // [128][2]
    float* gam = reinterpret_cast<float*>(smem + 3 * STAGE_SZ + 1024); // [256]
    float* bet = reinterpret_cast<float*>(smem + 3 * STAGE_SZ + 2048); // [256]

    int tid = threadIdx.x, lane = tid & 31, wid = tid >> 5;
    int seg = blockIdx.x;              // 0=q 1=k 2=v
    int row0 = blockIdx.y * 128;
    int wm = (wid >> 2) * 32;          // 4 warp-rows of 32
    int wn = (wid & 3) * 64;           // 4 warp-cols of 64

    if (tid < 256) {
        const float* gsel = (seg == 0) ? gq : (seg == 1) ? gk : gv;
        const float* bsel = (seg == 0) ? bq : (seg == 1) ? bk : bv;
        gam[tid] = gsel[tid];
        bet[tid] = bsel[tid];
        red[tid] = 0.f;
    }

    float acc[2][8][4];
#pragma unroll
    for (int i = 0; i < 2; i++)
#pragma unroll
        for (int j = 0; j < 8; j++)
#pragma unroll
            for (int q = 0; q < 4; q++) acc[i][j][q] = 0.f;

    auto issue = [&](int s, int kt) {
        uint32_t stg = sb + s * STAGE_SZ;
        int k0 = kt * 64;
        int t = kt >> 2;                 // tap (4 chunks of 64 per tap)
        int dbase = (kt & 3) * 64;
        // A: 128 rows x 64 fp16 = 16KB -> 1024 cp16 / 512 thr = 2 each
#pragma unroll
        for (int it = 0; it < 2; it++) {
            int f = it * 512 + tid;
            int r = f >> 3, kq = f & 7;
            int m = row0 + r;
            int n = m % N_NODES;
            int ns = n + t - 1;
            int ok = ((unsigned)ns < (unsigned)N_NODES);
            size_t src = (size_t)(ok ? (m + t - 1) : m) * 256 + dbase + kq * 8;
            int sz = ok ? 16 : 0;
            cp16(stg + swz128((uint32_t)r, (uint32_t)kq), g_xh + src, sz);
        }
        // B: 256 rows x 64 fp16 = 32KB -> 2048 cp16 / 512 thr = 4 each
#pragma unroll
        for (int it = 0; it < 4; it++) {
            int f = it * 512 + tid;
            int r = f >> 3, kq = f & 7;
            size_t src = (size_t)(seg * 256 + r) * 768 + k0 + kq * 8;
            cp16(stg + 16384 + swz128((uint32_t)r, (uint32_t)kq), g_wh + src, 16);
        }
        cp_commit();
    };

    auto compute = [&](int s) {
        uint32_t base = sb + s * STAGE_SZ;
#pragma unroll
        for (int ks = 0; ks < 4; ks++) {
            uint32_t fA[2][4];
#pragma unroll
            for (int mf = 0; mf < 2; mf++) {
                uint32_t r = wm + mf * 16 + (lane & 15);
                uint32_t kq = ks * 2 + (lane >> 4);
                uint32_t ad = base + swz128(r, kq);
                ldsm4(fA[mf][0], fA[mf][1], fA[mf][2], fA[mf][3], ad);
            }
#pragma unroll
            for (int np = 0; np < 4; np++) {
                uint32_t r = wn + np * 16 + (lane & 7) + ((lane >> 4) << 3);
                uint32_t kq = ks * 2 + ((lane >> 3) & 1);
                uint32_t ad = base + 16384 + swz128(r, kq);
                uint32_t b0, b1, b2, b3;
                ldsm4(b0, b1, b2, b3, ad);
#pragma unroll
                for (int mf = 0; mf < 2; mf++) {
                    mma_f16(acc[mf][2 * np],     fA[mf], b0, b1);
                    mma_f16(acc[mf][2 * np + 1], fA[mf], b2, b3);
                }
            }
        }
    };

    const int KT = 12;
    issue(0, 0);
    issue(1, 1);
#pragma unroll 1
    for (int kt = 0; kt < KT; kt++) {
        if (kt == KT - 1) cp_wait<0>(); else cp_wait<1>();
        __syncthreads();
        if (kt + 2 < KT) issue((kt + 2) % 3, kt + 2);
        compute(kt % 3);
    }

    // ---- LN + residual epilogue (fp16 output) ----
#pragma unroll
    for (int mf = 0; mf < 2; mf++) {
#pragma unroll
        for (int rr = 0; rr < 2; rr++) {
            int rloc = wm + mf * 16 + (lane >> 2) + rr * 8;
            float s = 0.f, s2 = 0.f;
#pragma unroll
            for (int nf = 0; nf < 8; nf++) {
                float c0 = acc[mf][nf][rr * 2];
                float c1 = acc[mf][nf][rr * 2 + 1];
                s += c0 + c1; s2 += c0 * c0 + c1 * c1;
            }
            s  += __shfl_xor_sync(0xffffffffu, s, 1);
            s  += __shfl_xor_sync(0xffffffffu, s, 2);
            s2 += __shfl_xor_sync(0xffffffffu, s2, 1);
            s2 += __shfl_xor_sync(0xffffffffu, s2, 2);
            if ((lane & 3) == 0) {
                atomicAdd(&red[rloc * 2], s);
                atomicAdd(&red[rloc * 2 + 1], s2);
            }
        }
    }
    __syncthreads();

#pragma unroll
    for (int mf = 0; mf < 2; mf++) {
#pragma unroll
        for (int rr = 0; rr < 2; rr++) {
            int rloc = wm + mf * 16 + (lane >> 2) + rr * 8;
            int rg = row0 + rloc;
            float mean = red[rloc * 2] * (1.0f / 256.0f);
            float var  = red[rloc * 2 + 1] * (1.0f / 256.0f) - mean * mean;
            float inv  = rsqrtf(var + 1e-5f);
#pragma unroll
            for (int nf = 0; nf < 8; nf++) {
                int cloc = wn + nf * 8 + 2 * (lane & 3);
                float2 xv = *reinterpret_cast<const float2*>(
                    &x[(size_t)rg * 256 + cloc]);
                float c0 = acc[mf][nf][rr * 2];
                float c1 = acc[mf][nf][rr * 2 + 1];
                float o0 = xv.x + (c0 - mean) * inv * gam[cloc]     + bet[cloc];
                float o1 = xv.y + (c1 - mean) * inv * gam[cloc + 1] + bet[cloc + 1];
                *reinterpret_cast<__half2*>(
                    &g_qkvh[(size_t)rg * 768 + seg * 256 + cloc]) =
                    __floats2half2_rn(o0, o1);
            }
        }
    }
}

// ---------------- proj GEMM (single-pass fp16, 128x256 tile, 3-stage) ----------------
#define PSTAGE_SZ 24576
#define SMEM_PROJ (3 * PSTAGE_SZ)

__global__ __launch_bounds__(256, 1)
void proj_gemm(const float* __restrict__ bo, float* __restrict__ outp) {
    extern __shared__ __align__(16) char smem[];
    const uint32_t sb = smem_u32(smem);

    int tid = threadIdx.x, lane = tid & 31, wid = tid >> 5;
    int row0 = blockIdx.x * 128;
    int wm = (wid >> 2) * 64;
    int wn = (wid & 3) * 64;

    float acc[4][8][4];
#pragma unroll
    for (int i = 0; i < 4; i++)
#pragma unroll
        for (int j = 0; j < 8; j++)
#pragma unroll
            for (int q = 0; q < 4; q++) acc[i][j][q] = 0.f;

    auto issue = [&](int s, int kt) {
        uint32_t stg = sb + s * PSTAGE_SZ;
        int k0 = kt * 32;
#pragma unroll
        for (int it = 0; it < 2; it++) {
            int f = it * 256 + tid;
            int r = f >> 2, kq = f & 3;
            size_t src = (size_t)(row0 + r) * 256 + k0 + kq * 8;
            cp16(stg + swz((uint32_t)r, (uint32_t)kq), g_ah + src, 16);
        }
#pragma unroll
        for (int it = 0; it < 4; it++) {
            int f = it * 256 + tid;
            int r = f >> 2, kq = f & 3;
            size_t src = (size_t)r * 256 + k0 + kq * 8;
            cp16(stg + 8192 + swz((uint32_t)r, (uint32_t)kq), g_woh + src, 16);
        }
        cp_commit();
    };

    auto compute = [&](int s) {
        uint32_t base = sb + s * PSTAGE_SZ;
#pragma unroll
        for (int ks = 0; ks < 2; ks++) {
            uint32_t fA[4][4];
#pragma unroll
            for (int mf = 0; mf < 4; mf++) {
                uint32_t r = wm + mf * 16 + (lane & 15);
                uint32_t kq = ks * 2 + (lane >> 4);
                uint32_t ad = base + swz(r, kq);
                ldsm4(fA[mf][0], fA[mf][1], fA[mf][2], fA[mf][3], ad);
            }
#pragma unroll
            for (int np = 0; np < 4; np++) {
                uint32_t r = wn + np * 16 + (lane & 7) + ((lane >> 4) << 3);
                uint32_t kq = ks * 2 + ((lane >> 3) & 1);
                uint32_t ad = base + 8192 + swz(r, kq);
                uint32_t b0, b1, b2, b3;
                ldsm4(b0, b1, b2, b3, ad);
#pragma unroll
                for (int mf = 0; mf < 4; mf++) {
                    mma_f16(acc[mf][2 * np],     fA[mf], b0, b1);
                    mma_f16(acc[mf][2 * np + 1], fA[mf], b2, b3);
                }
            }
        }
    };

    const int KT = 8;
    issue(0, 0);
    issue(1, 1);
#pragma unroll 1
    for (int kt = 0; kt < KT; kt++) {
        if (kt == KT - 1) cp_wait<0>(); else cp_wait<1>();
        __syncthreads();
        if (kt + 2 < KT) issue((kt + 2) % 3, kt + 2);
        compute(kt % 3);
    }

#pragma unroll
    for (int mf = 0; mf < 4; mf++) {
        int row = row0 + wm + mf * 16 + (lane >> 2);
#pragma unroll
        for (int nf = 0; nf < 8; nf++) {
            int col = wn + nf * 8 + 2 * (lane & 3);
            float* d = acc[mf][nf];
            float b0 = bo[col], b1 = bo[col + 1];
            *reinterpret_cast<float2*>(&outp[(size_t)row * 256 + col]) =
                make_float2(d[0] + b0, d[1] + b1);
            *reinterpret_cast<float2*>(&outp[(size_t)(row + 8) * 256 + col]) =
                make_float2(d[2] + b0, d[3] + b1);
        }
    }
}

// ---------------- attention: HMMA per (b, head), smem bias table ----------------
__global__ __launch_bounds__(128)
void attn_kernel() {
    __shared__ __half q_s[4][32][40];
    __shared__ __half k_s[4][32][40];
    __shared__ __half v_s[4][32][40];
    __shared__ float bias_s[4][400];
    int lane = threadIdx.x & 31;
    int wid  = threadIdx.x >> 5;
    int h = blockIdx.y * 4 + wid;
    int b = blockIdx.x;
    int tid = threadIdx.x;

    // stage combined bias for this block's 4 heads (coalesced float4)
    {
        const float* src = &g_bias[blockIdx.y * 4 * 400];
        float* dst = &bias_s[0][0];
        for (int i = tid; i < 400; i += 128)
            *reinterpret_cast<float4*>(dst + i * 4) =
                *reinterpret_cast<const float4*>(src + i * 4);
    }

    // stage q,k,v rows (zero-pad rows >= 20)
    {
        int r = lane;
        if (r < 20) {
            const __half* basep = &g_qkvh[(size_t)(b * 20 + r) * 768 + h * 32];
#pragma unroll
            for (int c = 0; c < 4; c++) {
                *reinterpret_cast<uint4*>(&q_s[wid][r][c * 8]) =
                    *reinterpret_cast<const uint4*>(basep + c * 8);
                *reinterpret_cast<uint4*>(&k_s[wid][r][c * 8]) =
                    *reinterpret_cast<const uint4*>(basep + 256 + c * 8);
                *reinterpret_cast<uint4*>(&v_s[wid][r][c * 8]) =
                    *reinterpret_cast<const uint4*>(basep + 512 + c * 8);
            }
        } else {
            uint4 z = make_uint4(0, 0, 0, 0);
#pragma unroll
            for (int c = 0; c < 4; c++) {
                *reinterpret_cast<uint4*>(&q_s[wid][r][c * 8]) = z;
                *reinterpret_cast<uint4*>(&k_s[wid][r][c * 8]) = z;
                *reinterpret_cast<uint4*>(&v_s[wid][r][c * 8]) = z;
            }
        }
    }
    __syncthreads();

    const uint32_t sq = smem_u32(&q_s[wid][0][0]);
    const uint32_t sk = smem_u32(&k_s[wid][0][0]);
    const uint32_t sv = smem_u32(&v_s[wid][0][0]);
    int g = lane >> 2, t = lane & 3;

    // ---- QK^T ----
    float c[2][4][4];
#pragma unroll
    for (int i = 0; i < 2; i++)
#pragma unroll
        for (int j = 0; j < 4; j++)
#pragma unroll
            for (int q = 0; q < 4; q++) c[i][j][q] = 0.f;

#pragma unroll
    for (int ks = 0; ks < 2; ks++) {
        uint32_t a[2][4];
#pragma unroll
        for (int mt = 0; mt < 2; mt++) {
            uint32_t ad = sq + (mt * 16 + (lane & 15)) * 80 +
                          (ks * 16 + (lane >> 4) * 8) * 2;
            ldsm4(a[mt][0], a[mt][1], a[mt][2], a[mt][3], ad);
        }
        uint32_t bf[2][4];
#pragma unroll
        for (int np = 0; np < 2; np++) {
            uint32_t ad = sk + (np * 16 + (lane & 7) + ((lane >> 4) << 3)) * 80 +
                          (ks * 2 + ((lane >> 3) & 1)) * 16;
            ldsm4(bf[np][0], bf[np][1], bf[np][2], bf[np][3], ad);
        }
#pragma unroll
        for (int mt = 0; mt < 2; mt++)
#pragma unroll
            for (int nt = 0; nt < 4; nt++)
                mma_f16(c[mt][nt], a[mt],
                        bf[nt >> 1][(nt & 1) * 2], bf[nt >> 1][(nt & 1) * 2 + 1]);
    }

    // ---- bias + mask (smem table) ----
#pragma unroll
    for (int mt = 0; mt < 2; mt++)
#pragma unroll
        for (int nt = 0; nt < 4; nt++)
#pragma unroll
            for (int q = 0; q < 4; q++) {
                int row = mt * 16 + g + (q >> 1) * 8;
                int col = nt * 8 + 2 * t + (q & 1);
                if (row < 20 && col < 20) {
                    c[mt][nt][q] = c[mt][nt][q] * 0.17677669529663689f +
                                   bias_s[wid][row * 20 + col];
                } else {
                    c[mt][nt][q] = -1e30f;
                }
            }

    // ---- softmax (quad shuffles) ----
#pragma unroll
    for (int mt = 0; mt < 2; mt++) {
        float m0 = -1e30f, m1 = -1e30f;
#pragma unroll
        for (int nt = 0; nt < 4; nt++) {
            m0 = fmaxf(m0, fmaxf(c[mt][nt][0], c[mt][nt][1]));
            m1 = fmaxf(m1, fmaxf(c[mt][nt][2], c[mt][nt][3]));
        }
        m0 = fmaxf(m0, __shfl_xor_sync(0xffffffffu, m0, 1));
        m0 = fmaxf(m0, __shfl_xor_sync(0xffffffffu, m0, 2));
        m1 = fmaxf(m1, __shfl_xor_sync(0xffffffffu, m1, 1));
        m1 = fmaxf(m1, __shfl_xor_sync(0xffffffffu, m1, 2));
        float s0 = 0.f, s1 = 0.f;
#pragma unroll
        for (int nt = 0; nt < 4; nt++) {
            c[mt][nt][0] = __expf(c[mt][nt][0] - m0);
            c[mt][nt][1] = __expf(c[mt][nt][1] - m0);
            c[mt][nt][2] = __expf(c[mt][nt][2] - m1);
            c[mt][nt][3] = __expf(c[mt][nt][3] - m1);
            s0 += c[mt][nt][0] + c[mt][nt][1];
            s1 += c[mt][nt][2] + c[mt][nt][3];
        }
        s0 += __shfl_xor_sync(0xffffffffu, s0, 1);
        s0 += __shfl_xor_sync(0xffffffffu, s0, 2);
        s1 += __shfl_xor_sync(0xffffffffu, s1, 1);
        s1 += __shfl_xor_sync(0xffffffffu, s1, 2);
        float i0 = 1.f / s0, i1 = 1.f / s1;
#pragma unroll
        for (int nt = 0; nt < 4; nt++) {
            c[mt][nt][0] *= i0; c[mt][nt][1] *= i0;
            c[mt][nt][2] *= i1; c[mt][nt][3] *= i1;
        }
    }

    // ---- AV ----
    float o[2][4][4];
#pragma unroll
    for (int i = 0; i < 2; i++)
#pragma unroll
        for (int j = 0; j < 4; j++)
#pragma unroll
            for (int q = 0; q < 4; q++) o[i][j][q] = 0.f;

#pragma unroll
    for (int ks = 0; ks < 2; ks++) {
        uint32_t pa[2][4];
#pragma unroll
        for (int mt = 0; mt < 2; mt++) {
            pa[mt][0] = pack_h2(c[mt][2 * ks][0],     c[mt][2 * ks][1]);
            pa[mt][1] = pack_h2(c[mt][2 * ks][2],     c[mt][2 * ks][3]);
            pa[mt][2] = pack_h2(c[mt][2 * ks + 1][0], c[mt][2 * ks + 1][1]);
            pa[mt][3] = pack_h2(c[mt][2 * ks + 1][2], c[mt][2 * ks + 1][3]);
        }
        uint32_t bv[2][4];
#pragma unroll
        for (int dp = 0; dp < 2; dp++) {
            uint32_t ad = sv + (ks * 16 + (lane & 15)) * 80 +
                          (dp * 16 + ((lane >> 4) << 3)) * 2;
            ldsm4t(bv[dp][0], bv[dp][1], bv[dp][2], bv[dp][3], ad);
        }
#pragma unroll
        for (int mt = 0; mt < 2; mt++)
#pragma unroll
            for (int nt = 0; nt < 4; nt++)
                mma_f16(o[mt][nt], pa[mt],
                        bv[nt >> 1][(nt & 1) * 2], bv[nt >> 1][(nt & 1) * 2 + 1]);
    }

    // ---- store rows < 20 ----
#pragma unroll
    for (int mt = 0; mt < 2; mt++)
#pragma unroll
        for (int q2 = 0; q2 < 2; q2++) {
            int row = mt * 16 + g + q2 * 8;
            if (row < 20) {
                __half* dst = &g_ah[(size_t)(b * 20 + row) * 256 + h * 32];
#pragma unroll
                for (int nt = 0; nt < 4; nt++) {
                    int col = nt * 8 + 2 * t;
                    *reinterpret_cast<__half2*>(dst + col) =
                        __floats2half2_rn(o[mt][nt][q2 * 2], o[mt][nt][q2 * 2 + 1]);
                }
            }
        }
}

// ---------------- launch ----------------
extern "C" void kernel_launch(void* const* d_in, const int* in_sizes, int n_in,
                              void* d_out, int out_size) {
    const float* x     = (const float*)d_in[0];
    const float* wq    = (const float*)d_in[1];
    const float* wk    = (const float*)d_in[2];
    const float* wv    = (const float*)d_in[3];
    const float* gq    = (const float*)d_in[4];
    const float* bq    = (const float*)d_in[5];
    const float* gk    = (const float*)d_in[6];
    const float* bk    = (const float*)d_in[7];
    const float* gv    = (const float*)d_in[8];
    const float* bv    = (const float*)d_in[9];
    const float* rel   = (const float*)d_in[10];
    const float* gbias = (const float*)d_in[11];
    const float* alpha = (const float*)d_in[12];
    const float* wo    = (const float*)d_in[13];
    const float* bo    = (const float*)d_in[14];
    float* out = (float*)d_out;

    int B = in_sizes[0] / (N_NODES * D_MODEL);
    int M = B * N_NODES;

    cudaFuncSetAttribute(conv_ln_kernel,
                         cudaFuncAttributeMaxDynamicSharedMemorySize, SMEM_CONV);
    cudaFuncSetAttribute(proj_gemm,
                         cudaFuncAttributeMaxDynamicSharedMemorySize, SMEM_PROJ);

    prep_w<<<(768 * 768 + 255) / 256, 256>>>(wq, wk, wv, wo);
    prep_x<<<(M * 64 + 255) / 256, 256>>>(x, M * 64);
    prep_bias<<<(N_HEADS * 400 + 255) / 256, 256>>>(rel, gbias, alpha);

    conv_ln_kernel<<<dim3(3, M / 128), 512, SMEM_CONV>>>(
        x, gq, bq, gk, bk, gv, bv);

    attn_kernel<<<dim3(B, 2), 128>>>();

    proj_gemm<<<M / 128, 256, SMEM_PROJ>>>(bo, out);
}

// round 11
// speedup vs baseline: 5.3541x; 1.0859x over previous
#include <cuda_runtime.h>
#include <cuda_bf16.h>
#include <cuda_fp16.h>
#include <cstdint>

#define D_MODEL 256
#define N_NODES 20
#define N_HEADS 8
#define BMAX    8192
#define MMAX    (BMAX * N_NODES)   // 163840 rows

// ---------------- scratch (device globals: allocation-free) ----------------
__device__ __half g_xh[(size_t)MMAX * 256];     // x as fp16
__device__ __half g_wh[768 * 768];              // conv weights fp16 [o][j=t*256+i]
__device__ __half g_woh[256 * 256];             // wo fp16 [o][i]
__device__ __half g_qkvh[(size_t)MMAX * 768];   // q|k|v after LN+residual (fp16)
__device__ __half g_ah[(size_t)MMAX * 256];     // attn out fp16
__device__ float  g_bias[N_HEADS * 20 * 20];    // rel + alpha*gbias combined

// ---------------- warp-MMA helpers (baseline PTX: sm_80+) ----------------
__device__ __forceinline__ uint32_t smem_u32(const void* p) {
    uint32_t a;
    asm("{ .reg .u64 t; cvta.to.shared.u64 t, %1; cvt.u32.u64 %0, t; }"
        : "=r"(a) : "l"(p));
    return a;
}
__device__ __forceinline__ void ldsm4(uint32_t& r0, uint32_t& r1,
                                      uint32_t& r2, uint32_t& r3, uint32_t addr) {
    asm volatile("ldmatrix.sync.aligned.m8n8.x4.shared.b16 {%0,%1,%2,%3}, [%4];"
                 : "=r"(r0), "=r"(r1), "=r"(r2), "=r"(r3) : "r"(addr));
}
__device__ __forceinline__ void ldsm4t(uint32_t& r0, uint32_t& r1,
                                       uint32_t& r2, uint32_t& r3, uint32_t addr) {
    asm volatile("ldmatrix.sync.aligned.m8n8.x4.trans.shared.b16 {%0,%1,%2,%3}, [%4];"
                 : "=r"(r0), "=r"(r1), "=r"(r2), "=r"(r3) : "r"(addr));
}
__device__ __forceinline__ void mma_f16(float* d,
                                        const uint32_t* a,
                                        uint32_t b0, uint32_t b1) {
    asm volatile(
        "mma.sync.aligned.m16n8k16.row.col.f32.f16.f16.f32 "
        "{%0,%1,%2,%3}, {%4,%5,%6,%7}, {%8,%9}, {%0,%1,%2,%3};"
        : "+f"(d[0]), "+f"(d[1]), "+f"(d[2]), "+f"(d[3])
        : "r"(a[0]), "r"(a[1]), "r"(a[2]), "r"(a[3]), "r"(b0), "r"(b1));
}
__device__ __forceinline__ uint32_t pack_h2(float x, float y) {
    __half2 h = __floats2half2_rn(x, y);
    return *reinterpret_cast<uint32_t*>(&h);
}
__device__ __forceinline__ uint32_t swz128(uint32_t r, uint32_t kq) {
    return r * 128 + ((kq ^ (r & 7)) * 16);
}
__device__ __forceinline__ void cp16(uint32_t dst, const void* src, int srcsz) {
    asm volatile("cp.async.cg.shared.global [%0], [%1], 16, %2;"
                 :: "r"(dst), "l"(__cvta_generic_to_global(src)), "r"(srcsz)
                 : "memory");
}
__device__ __forceinline__ void cp_commit() {
    asm volatile("cp.async.commit_group;" ::: "memory");
}
template<int N>
__device__ __forceinline__ void cp_wait() {
    asm volatile("cp.async.wait_group %0;" :: "n"(N) : "memory");
}

// ---------------- prep kernels ----------------
__global__ void prep_w(const float* __restrict__ wq, const float* __restrict__ wk,
                       const float* __restrict__ wv, const float* __restrict__ wo) {
    int idx = blockIdx.x * blockDim.x + threadIdx.x;
    if (idx < 768 * 768) {
        int o = idx / 768, j = idx % 768;
        int t = j >> 8, i = j & 255;
        const float* w = (o < 256) ? wq : (o < 512) ? wk : wv;
        int oc = o & 255;
        g_wh[idx] = __float2half(w[(oc * 256 + i) * 3 + t]);
    }
    if (idx < 256 * 256) {
        g_woh[idx] = __float2half(wo[idx]);
    }
}
__global__ void prep_x(const float* __restrict__ x, int total4) {
    int i = blockIdx.x * blockDim.x + threadIdx.x;
    if (i < total4) {
        float4 v = reinterpret_cast<const float4*>(x)[i];
        __half2 h0, h1;
        h0.x = __float2half(v.x); h0.y = __float2half(v.y);
        h1.x = __float2half(v.z); h1.y = __float2half(v.w);
        reinterpret_cast<__half2*>(g_xh)[i * 2]     = h0;
        reinterpret_cast<__half2*>(g_xh)[i * 2 + 1] = h1;
    }
}
__global__ void prep_bias(const float* __restrict__ rel,
                          const float* __restrict__ gbias,
                          const float* __restrict__ alphap) {
    int idx = blockIdx.x * blockDim.x + threadIdx.x;
    if (idx < N_HEADS * 400) {
        int h = idx / 400, rc = idx % 400;
        int r = rc / 20, c = rc % 20;
        g_bias[idx] = rel[(r - c + 19) * 8 + h] + alphap[0] * gbias[idx];
    }
}

// ---------------- fused conv GEMM + LayerNorm + residual ----------------
// Per block: 64 rows x 256 cols (one q/k/v segment). BK=64, 2-stage cp.async.
// 256 threads, 8 warps (2x4), warp tile 32x64 -> 2 CTAs per SM.
#define CSTAGE 40960                       // A 8K | B 32K
#define SMEM_CONV (2 * CSTAGE + 1024 + 2048)

__global__ __launch_bounds__(256, 2)
void conv_ln_kernel(const float* __restrict__ x,
                    const float* __restrict__ gq, const float* __restrict__ bq,
                    const float* __restrict__ gk, const float* __restrict__ bk,
                    const float* __restrict__ gv, const float* __restrict__ bv) {
    extern __shared__ __align__(16) char smem[];
    const uint32_t sb = smem_u32(smem);
    float* red = reinterpret_cast<float*>(smem + 2 * CSTAGE);          // [64][2]
    float* gam = reinterpret_cast<float*>(smem + 2 * CSTAGE + 1024);   // [256]
    float* bet = reinterpret_cast<float*>(smem + 2 * CSTAGE + 2048);   // [256]

    int tid = threadIdx.x, lane = tid & 31, wid = tid >> 5;
    int seg = blockIdx.x;              // 0=q 1=k 2=v
    int row0 = blockIdx.y * 64;
    int wm = (wid >> 2) * 32;          // 2 warp-rows of 32
    int wn = (wid & 3) * 64;           // 4 warp-cols of 64

    {
        const float* gsel = (seg == 0) ? gq : (seg == 1) ? gk : gv;
        const float* bsel = (seg == 0) ? bq : (seg == 1) ? bk : bv;
        gam[tid] = gsel[tid];
        bet[tid] = bsel[tid];
        if (tid < 128) red[tid] = 0.f;
    }

    float acc[2][8][4];
#pragma unroll
    for (int i = 0; i < 2; i++)
#pragma unroll
        for (int j = 0; j < 8; j++)
#pragma unroll
            for (int q = 0; q < 4; q++) acc[i][j][q] = 0.f;

    auto issue = [&](int s, int kt) {
        uint32_t stg = sb + s * CSTAGE;
        int k0 = kt * 64;
        int t = kt >> 2;                 // tap (4 chunks of 64 per tap)
        int dbase = (kt & 3) * 64;
        // A: 64 rows x 64 fp16 = 8KB -> 512 cp16 / 256 thr = 2 each
#pragma unroll
        for (int it = 0; it < 2; it++) {
            int f = it * 256 + tid;
            int r = f >> 3, kq = f & 7;
            int m = row0 + r;
            int n = m % N_NODES;
            int ns = n + t - 1;
            int ok = ((unsigned)ns < (unsigned)N_NODES);
            size_t src = (size_t)(ok ? (m + t - 1) : m) * 256 + dbase + kq * 8;
            int sz = ok ? 16 : 0;
            cp16(stg + swz128((uint32_t)r, (uint32_t)kq), g_xh + src, sz);
        }
        // B: 256 rows x 64 fp16 = 32KB -> 2048 cp16 / 256 thr = 8 each
#pragma unroll
        for (int it = 0; it < 8; it++) {
            int f = it * 256 + tid;
            int r = f >> 3, kq = f & 7;
            size_t src = (size_t)(seg * 256 + r) * 768 + k0 + kq * 8;
            cp16(stg + 8192 + swz128((uint32_t)r, (uint32_t)kq), g_wh + src, 16);
        }
        cp_commit();
    };

    auto compute = [&](int s) {
        uint32_t base = sb + s * CSTAGE;
#pragma unroll
        for (int ks = 0; ks < 4; ks++) {
            uint32_t fA[2][4];
#pragma unroll
            for (int mf = 0; mf < 2; mf++) {
                uint32_t r = wm + mf * 16 + (lane & 15);
                uint32_t kq = ks * 2 + (lane >> 4);
                uint32_t ad = base + swz128(r, kq);
                ldsm4(fA[mf][0], fA[mf][1], fA[mf][2], fA[mf][3], ad);
            }
#pragma unroll
            for (int np = 0; np < 4; np++) {
                uint32_t r = wn + np * 16 + (lane & 7) + ((lane >> 4) << 3);
                uint32_t kq = ks * 2 + ((lane >> 3) & 1);
                uint32_t ad = base + 8192 + swz128(r, kq);
                uint32_t b0, b1, b2, b3;
                ldsm4(b0, b1, b2, b3, ad);
#pragma unroll
                for (int mf = 0; mf < 2; mf++) {
                    mma_f16(acc[mf][2 * np],     fA[mf], b0, b1);
                    mma_f16(acc[mf][2 * np + 1], fA[mf], b2, b3);
                }
            }
        }
    };

    const int KT = 12;
    issue(0, 0);
    issue(1, 1);
#pragma unroll 1
    for (int kt = 0; kt < KT; kt++) {
        if (kt == KT - 1) cp_wait<0>(); else cp_wait<1>();
        __syncthreads();
        compute(kt & 1);
        __syncthreads();
        if (kt + 2 < KT) issue(kt & 1, kt + 2);
    }

    // ---- LN + residual epilogue (fp16 output) ----
#pragma unroll
    for (int mf = 0; mf < 2; mf++) {
#pragma unroll
        for (int rr = 0; rr < 2; rr++) {
            int rloc = wm + mf * 16 + (lane >> 2) + rr * 8;
            float s = 0.f, s2 = 0.f;
#pragma unroll
            for (int nf = 0; nf < 8; nf++) {
                float c0 = acc[mf][nf][rr * 2];
                float c1 = acc[mf][nf][rr * 2 + 1];
                s += c0 + c1; s2 += c0 * c0 + c1 * c1;
            }
            s  += __shfl_xor_sync(0xffffffffu, s, 1);
            s  += __shfl_xor_sync(0xffffffffu, s, 2);
            s2 += __shfl_xor_sync(0xffffffffu, s2, 1);
            s2 += __shfl_xor_sync(0xffffffffu, s2, 2);
            if ((lane & 3) == 0) {
                atomicAdd(&red[rloc * 2], s);
                atomicAdd(&red[rloc * 2 + 1], s2);
            }
        }
    }
    __syncthreads();

#pragma unroll
    for (int mf = 0; mf < 2; mf++) {
#pragma unroll
        for (int rr = 0; rr < 2; rr++) {
            int rloc = wm + mf * 16 + (lane >> 2) + rr * 8;
            int rg = row0 + rloc;
            float mean = red[rloc * 2] * (1.0f / 256.0f);
            float var  = red[rloc * 2 + 1] * (1.0f / 256.0f) - mean * mean;
            float inv  = rsqrtf(var + 1e-5f);
#pragma unroll
            for (int nf = 0; nf < 8; nf++) {
                int cloc = wn + nf * 8 + 2 * (lane & 3);
                float2 xv = *reinterpret_cast<const float2*>(
                    &x[(size_t)rg * 256 + cloc]);
                float c0 = acc[mf][nf][rr * 2];
                float c1 = acc[mf][nf][rr * 2 + 1];
                float o0 = xv.x + (c0 - mean) * inv * gam[cloc]     + bet[cloc];
                float o1 = xv.y + (c1 - mean) * inv * gam[cloc + 1] + bet[cloc + 1];
                *reinterpret_cast<__half2*>(
                    &g_qkvh[(size_t)rg * 768 + seg * 256 + cloc]) =
                    __floats2half2_rn(o0, o1);
            }
        }
    }
}

// ---------------- proj GEMM (single-pass fp16, 64x256 tile, 2 CTAs/SM) ----------------
#define SMEM_PROJ (2 * CSTAGE)

__global__ __launch_bounds__(256, 2)
void proj_gemm(const float* __restrict__ bo, float* __restrict__ outp) {
    extern __shared__ __align__(16) char smem[];
    const uint32_t sb = smem_u32(smem);

    int tid = threadIdx.x, lane = tid & 31, wid = tid >> 5;
    int row0 = blockIdx.x * 64;
    int wm = (wid >> 2) * 32;
    int wn = (wid & 3) * 64;

    float acc[2][8][4];
#pragma unroll
    for (int i = 0; i < 2; i++)
#pragma unroll
        for (int j = 0; j < 8; j++)
#pragma unroll
            for (int q = 0; q < 4; q++) acc[i][j][q] = 0.f;

    auto issue = [&](int s, int kt) {
        uint32_t stg = sb + s * CSTAGE;
        int k0 = kt * 64;
        // A: 64 rows x 64 fp16 = 8KB
#pragma unroll
        for (int it = 0; it < 2; it++) {
            int f = it * 256 + tid;
            int r = f >> 3, kq = f & 7;
            size_t src = (size_t)(row0 + r) * 256 + k0 + kq * 8;
            cp16(stg + swz128((uint32_t)r, (uint32_t)kq), g_ah + src, 16);
        }
        // B: 256 rows x 64 fp16 = 32KB
#pragma unroll
        for (int it = 0; it < 8; it++) {
            int f = it * 256 + tid;
            int r = f >> 3, kq = f & 7;
            size_t src = (size_t)r * 256 + k0 + kq * 8;
            cp16(stg + 8192 + swz128((uint32_t)r, (uint32_t)kq), g_woh + src, 16);
        }
        cp_commit();
    };

    auto compute = [&](int s) {
        uint32_t base = sb + s * CSTAGE;
#pragma unroll
        for (int ks = 0; ks < 4; ks++) {
            uint32_t fA[2][4];
#pragma unroll
            for (int mf = 0; mf < 2; mf++) {
                uint32_t r = wm + mf * 16 + (lane & 15);
                uint32_t kq = ks * 2 + (lane >> 4);
                uint32_t ad = base + swz128(r, kq);
                ldsm4(fA[mf][0], fA[mf][1], fA[mf][2], fA[mf][3], ad);
            }
#pragma unroll
            for (int np = 0; np < 4; np++) {
                uint32_t r = wn + np * 16 + (lane & 7) + ((lane >> 4) << 3);
                uint32_t kq = ks * 2 + ((lane >> 3) & 1);
                uint32_t ad = base + 8192 + swz128(r, kq);
                uint32_t b0, b1, b2, b3;
                ldsm4(b0, b1, b2, b3, ad);
#pragma unroll
                for (int mf = 0; mf < 2; mf++) {
                    mma_f16(acc[mf][2 * np],     fA[mf], b0, b1);
                    mma_f16(acc[mf][2 * np + 1], fA[mf], b2, b3);
                }
            }
        }
    };

    const int KT = 4;
    issue(0, 0);
    issue(1, 1);
#pragma unroll 1
    for (int kt = 0; kt < KT; kt++) {
        if (kt == KT - 1) cp_wait<0>(); else cp_wait<1>();
        __syncthreads();
        compute(kt & 1);
        __syncthreads();
        if (kt + 2 < KT) issue(kt & 1, kt + 2);
    }

#pragma unroll
    for (int mf = 0; mf < 2; mf++) {
        int row = row0 + wm + mf * 16 + (lane >> 2);
#pragma unroll
        for (int nf = 0; nf < 8; nf++) {
            int col = wn + nf * 8 + 2 * (lane & 3);
            float* d = acc[mf][nf];
            float b0 = bo[col], b1 = bo[col + 1];
            *reinterpret_cast<float2*>(&outp[(size_t)row * 256 + col]) =
                make_float2(d[0] + b0, d[1] + b1);
            *reinterpret_cast<float2*>(&outp[(size_t)(row + 8) * 256 + col]) =
                make_float2(d[2] + b0, d[3] + b1);
        }
    }
}

// ---------------- attention: HMMA per (b, head), smem bias table ----------------
__global__ __launch_bounds__(128)
void attn_kernel() {
    __shared__ __half q_s[4][32][40];
    __shared__ __half k_s[4][32][40];
    __shared__ __half v_s[4][32][40];
    __shared__ float bias_s[4][400];
    int lane = threadIdx.x & 31;
    int wid  = threadIdx.x >> 5;
    int h = blockIdx.y * 4 + wid;
    int b = blockIdx.x;
    int tid = threadIdx.x;

    // stage combined bias for this block's 4 heads (coalesced float4)
    {
        const float* src = &g_bias[blockIdx.y * 4 * 400];
        float* dst = &bias_s[0][0];
        for (int i = tid; i < 400; i += 128)
            *reinterpret_cast<float4*>(dst + i * 4) =
                *reinterpret_cast<const float4*>(src + i * 4);
    }

    // stage q,k,v rows (zero-pad rows >= 20)
    {
        int r = lane;
        if (r < 20) {
            const __half* basep = &g_qkvh[(size_t)(b * 20 + r) * 768 + h * 32];
#pragma unroll
            for (int c = 0; c < 4; c++) {
                *reinterpret_cast<uint4*>(&q_s[wid][r][c * 8]) =
                    *reinterpret_cast<const uint4*>(basep + c * 8);
                *reinterpret_cast<uint4*>(&k_s[wid][r][c * 8]) =
                    *reinterpret_cast<const uint4*>(basep + 256 + c * 8);
                *reinterpret_cast<uint4*>(&v_s[wid][r][c * 8]) =
                    *reinterpret_cast<const uint4*>(basep + 512 + c * 8);
            }
        } else {
            uint4 z = make_uint4(0, 0, 0, 0);
#pragma unroll
            for (int c = 0; c < 4; c++) {
                *reinterpret_cast<uint4*>(&q_s[wid][r][c * 8]) = z;
                *reinterpret_cast<uint4*>(&k_s[wid][r][c * 8]) = z;
                *reinterpret_cast<uint4*>(&v_s[wid][r][c * 8]) = z;
            }
        }
    }
    __syncthreads();

    const uint32_t sq = smem_u32(&q_s[wid][0][0]);
    const uint32_t sk = smem_u32(&k_s[wid][0][0]);
    const uint32_t sv = smem_u32(&v_s[wid][0][0]);
    int g = lane >> 2, t = lane & 3;

    // ---- QK^T ----
    float c[2][4][4];
#pragma unroll
    for (int i = 0; i < 2; i++)
#pragma unroll
        for (int j = 0; j < 4; j++)
#pragma unroll
            for (int q = 0; q < 4; q++) c[i][j][q] = 0.f;

#pragma unroll
    for (int ks = 0; ks < 2; ks++) {
        uint32_t a[2][4];
#pragma unroll
        for (int mt = 0; mt < 2; mt++) {
            uint32_t ad = sq + (mt * 16 + (lane & 15)) * 80 +
                          (ks * 16 + (lane >> 4) * 8) * 2;
            ldsm4(a[mt][0], a[mt][1], a[mt][2], a[mt][3], ad);
        }
        uint32_t bf[2][4];
#pragma unroll
        for (int np = 0; np < 2; np++) {
            uint32_t ad = sk + (np * 16 + (lane & 7) + ((lane >> 4) << 3)) * 80 +
                          (ks * 2 + ((lane >> 3) & 1)) * 16;
            ldsm4(bf[np][0], bf[np][1], bf[np][2], bf[np][3], ad);
        }
#pragma unroll
        for (int mt = 0; mt < 2; mt++)
#pragma unroll
            for (int nt = 0; nt < 4; nt++)
                mma_f16(c[mt][nt], a[mt],
                        bf[nt >> 1][(nt & 1) * 2], bf[nt >> 1][(nt & 1) * 2 + 1]);
    }

    // ---- bias + mask (smem table) ----
#pragma unroll
    for (int mt = 0; mt < 2; mt++)
#pragma unroll
        for (int nt = 0; nt < 4; nt++)
#pragma unroll
            for (int q = 0; q < 4; q++) {
                int row = mt * 16 + g + (q >> 1) * 8;
                int col = nt * 8 + 2 * t + (q & 1);
                if (row < 20 && col < 20) {
                    c[mt][nt][q] = c[mt][nt][q] * 0.17677669529663689f +
                                   bias_s[wid][row * 20 + col];
                } else {
                    c[mt][nt][q] = -1e30f;
                }
            }

    // ---- softmax (quad shuffles) ----
#pragma unroll
    for (int mt = 0; mt < 2; mt++) {
        float m0 = -1e30f, m1 = -1e30f;
#pragma unroll
        for (int nt = 0; nt < 4; nt++) {
            m0 = fmaxf(m0, fmaxf(c[mt][nt][0], c[mt][nt][1]));
            m1 = fmaxf(m1, fmaxf(c[mt][nt][2], c[mt][nt][3]));
        }
        m0 = fmaxf(m0, __shfl_xor_sync(0xffffffffu, m0, 1));
        m0 = fmaxf(m0, __shfl_xor_sync(0xffffffffu, m0, 2));
        m1 = fmaxf(m1, __shfl_xor_sync(0xffffffffu, m1, 1));
        m1 = fmaxf(m1, __shfl_xor_sync(0xffffffffu, m1, 2));
        float s0 = 0.f, s1 = 0.f;
#pragma unroll
        for (int nt = 0; nt < 4; nt++) {
            c[mt][nt][0] = __expf(c[mt][nt][0] - m0);
            c[mt][nt][1] = __expf(c[mt][nt][1] - m0);
            c[mt][nt][2] = __expf(c[mt][nt][2] - m1);
            c[mt][nt][3] = __expf(c[mt][nt][3] - m1);
            s0 += c[mt][nt][0] + c[mt][nt][1];
            s1 += c[mt][nt][2] + c[mt][nt][3];
        }
        s0 += __shfl_xor_sync(0xffffffffu, s0, 1);
        s0 += __shfl_xor_sync(0xffffffffu, s0, 2);
        s1 += __shfl_xor_sync(0xffffffffu, s1, 1);
        s1 += __shfl_xor_sync(0xffffffffu, s1, 2);
        float i0 = 1.f / s0, i1 = 1.f / s1;
#pragma unroll
        for (int nt = 0; nt < 4; nt++) {
            c[mt][nt][0] *= i0; c[mt][nt][1] *= i0;
            c[mt][nt][2] *= i1; c[mt][nt][3] *= i1;
        }
    }

    // ---- AV ----
    float o[2][4][4];
#pragma unroll
    for (int i = 0; i < 2; i++)
#pragma unroll
        for (int j = 0; j < 4; j++)
#pragma unroll
            for (int q = 0; q < 4; q++) o[i][j][q] = 0.f;

#pragma unroll
    for (int ks = 0; ks < 2; ks++) {
        uint32_t pa[2][4];
#pragma unroll
        for (int mt = 0; mt < 2; mt++) {
            pa[mt][0] = pack_h2(c[mt][2 * ks][0],     c[mt][2 * ks][1]);
            pa[mt][1] = pack_h2(c[mt][2 * ks][2],     c[mt][2 * ks][3]);
            pa[mt][2] = pack_h2(c[mt][2 * ks + 1][0], c[mt][2 * ks + 1][1]);
            pa[mt][3] = pack_h2(c[mt][2 * ks + 1][2], c[mt][2 * ks + 1][3]);
        }
        uint32_t bv[2][4];
#pragma unroll
        for (int dp = 0; dp < 2; dp++) {
            uint32_t ad = sv + (ks * 16 + (lane & 15)) * 80 +
                          (dp * 16 + ((lane >> 4) << 3)) * 2;
            ldsm4t(bv[dp][0], bv[dp][1], bv[dp][2], bv[dp][3], ad);
        }
#pragma unroll
        for (int mt = 0; mt < 2; mt++)
#pragma unroll
            for (int nt = 0; nt < 4; nt++)
                mma_f16(o[mt][nt], pa[mt],
                        bv[nt >> 1][(nt & 1) * 2], bv[nt >> 1][(nt & 1) * 2 + 1]);
    }

    // ---- store rows < 20 ----
#pragma unroll
    for (int mt = 0; mt < 2; mt++)
#pragma unroll
        for (int q2 = 0; q2 < 2; q2++) {
            int row = mt * 16 + g + q2 * 8;
            if (row < 20) {
                __half* dst = &g_ah[(size_t)(b * 20 + row) * 256 + h * 32];
#pragma unroll
                for (int nt = 0; nt < 4; nt++) {
                    int col = nt * 8 + 2 * t;
                    *reinterpret_cast<__half2*>(dst + col) =
                        __floats2half2_rn(o[mt][nt][q2 * 2], o[mt][nt][q2 * 2 + 1]);
                }
            }
        }
}

// ---------------- launch ----------------
extern "C" void kernel_launch(void* const* d_in, const int* in_sizes, int n_in,
                              void* d_out, int out_size) {
    const float* x     = (const float*)d_in[0];
    const float* wq    = (const float*)d_in[1];
    const float* wk    = (const float*)d_in[2];
    const float* wv    = (const float*)d_in[3];
    const float* gq    = (const float*)d_in[4];
    const float* bq    = (const float*)d_in[5];
    const float* gk    = (const float*)d_in[6];
    const float* bk    = (const float*)d_in[7];
    const float* gv    = (const float*)d_in[8];
    const float* bv    = (const float*)d_in[9];
    const float* rel   = (const float*)d_in[10];
    const float* gbias = (const float*)d_in[11];
    const float* alpha = (const float*)d_in[12];
    const float* wo    = (const float*)d_in[13];
    const float* bo    = (const float*)d_in[14];
    float* out = (float*)d_out;

    int B = in_sizes[0] / (N_NODES * D_MODEL);
    int M = B * N_NODES;

    cudaFuncSetAttribute(conv_ln_kernel,
                         cudaFuncAttributeMaxDynamicSharedMemorySize, SMEM_CONV);
    cudaFuncSetAttribute(proj_gemm,
                         cudaFuncAttributeMaxDynamicSharedMemorySize, SMEM_PROJ);

    prep_w<<<(768 * 768 + 255) / 256, 256>>>(wq, wk, wv, wo);
    prep_x<<<(M * 64 + 255) / 256, 256>>>(x, M * 64);
    prep_bias<<<(N_HEADS * 400 + 255) / 256, 256>>>(rel, gbias, alpha);

    conv_ln_kernel<<<dim3(3, M / 64), 256, SMEM_CONV>>>(
        x, gq, bq, gk, bk, gv, bv);

    attn_kernel<<<dim3(B, 2), 128>>>();

    proj_gemm<<<M / 64, 256, SMEM_PROJ>>>(bo, out);
}